// round 1
// baseline (speedup 1.0000x reference)
#include <cuda_runtime.h>
#include <math.h>

// ---------------- Problem constants ----------------
static constexpr int BB = 2;
static constexpr int TT = 1024;
static constexpr int EE = 1024;
static constexpr int HH = 16;
static constexpr int DD = 64;
static constexpr int LL = 12;
static constexpr int VV = 50257;
static constexpr int MM = BB * TT;                 // 2048 rows
static constexpr long long NBTV = (long long)MM * VV;

// ---------------- Scratch (device globals; no runtime allocation) ----------------
__device__ float g_h   [(size_t)MM * EE];          // residual stream
__device__ float g_x   [(size_t)MM * EE];          // layernorm output
__device__ float g_qkv [(size_t)MM * 3 * EE];      // qkv projections
__device__ float g_sc  [(size_t)BB * HH * TT * TT];// attention scores/probs (128MB)
__device__ float g_attn[(size_t)MM * EE];          // attention output
__device__ float g_mlp [(size_t)MM * 4 * EE];      // mlp hidden
__device__ float g_nll [MM];                       // per-token nll
__device__ float g_logits[(size_t)MM * VV];        // fallback logits buffer

// ---------------- Embedding: h = wte[idx] + wpe[pos] ----------------
__global__ void embed_k(const int* __restrict__ idx, const float* __restrict__ wte,
                        const float* __restrict__ wpe, float* __restrict__ h) {
    int bt = blockIdx.x;
    int t  = bt % TT;
    int tok = idx[bt];
    int i = threadIdx.x * 4;
    float4 a = *(const float4*)(wte + (size_t)tok * EE + i);
    float4 p = *(const float4*)(wpe + (size_t)t   * EE + i);
    a.x += p.x; a.y += p.y; a.z += p.z; a.w += p.w;
    *(float4*)(h + (size_t)bt * EE + i) = a;
}

// ---------------- LayerNorm: one block per row, E=1024, 256 threads x 4 ----------------
__global__ void layernorm_k(const float* __restrict__ xin, const float* __restrict__ g,
                            const float* __restrict__ bb, float* __restrict__ y) {
    __shared__ float rs[8], rq[8];
    int row = blockIdx.x, tid = threadIdx.x;
    const float* xr = xin + (size_t)row * EE;
    float4 v = *(const float4*)(xr + tid * 4);
    float s = v.x + v.y + v.z + v.w;
    float q = v.x * v.x + v.y * v.y + v.z * v.z + v.w * v.w;
#pragma unroll
    for (int o = 16; o; o >>= 1) {
        s += __shfl_xor_sync(0xffffffffu, s, o);
        q += __shfl_xor_sync(0xffffffffu, q, o);
    }
    if ((tid & 31) == 0) { rs[tid >> 5] = s; rq[tid >> 5] = q; }
    __syncthreads();
    if (tid == 0) {
        float S = 0.f, Q = 0.f;
#pragma unroll
        for (int i = 0; i < 8; i++) { S += rs[i]; Q += rq[i]; }
        rs[0] = S; rq[0] = Q;
    }
    __syncthreads();
    float mean = rs[0] * (1.f / EE);
    float var  = rq[0] * (1.f / EE) - mean * mean;
    float rstd = rsqrtf(var + 1e-5f);
    float4 gg = *(const float4*)(g  + tid * 4);
    float4 be = *(const float4*)(bb + tid * 4);
    float4 o;
    o.x = (v.x - mean) * rstd * gg.x + be.x;
    o.y = (v.y - mean) * rstd * gg.y + be.y;
    o.z = (v.z - mean) * rstd * gg.z + be.z;
    o.w = (v.w - mean) * rstd * gg.w + be.w;
    *(float4*)(y + (size_t)row * EE + tid * 4) = o;
}

// ---------------- Generic SGEMM: C = act(A@B + bias) [+ Res] ----------------
// A: [M,K] row-major.  B: [K,N] row-major (TRANSB=false) or [N,K] row-major (TRANSB=true).
// Tile 64x64x16, 256 threads, 4x4 per thread. M % 64 == 0, K % 16 == 0 assumed.
template<bool TRANSB, int ACT, bool RES>
__global__ void sgemm_k(const float* __restrict__ A, const float* __restrict__ Bm,
                        const float* __restrict__ bias, const float* __restrict__ Res,
                        float* __restrict__ C, int M, int N, int K) {
    __shared__ float As[16][64];
    __shared__ float Bs[16][64];
    int row0 = blockIdx.x * 64;
    int col0 = blockIdx.y * 64;
    int tid = threadIdx.x;
    int tx = tid & 15, ty = tid >> 4;
    float acc[4][4] = {};
    int ar = tid >> 2;            // 0..63
    int ak = (tid & 3) << 2;      // 0,4,8,12
    for (int k0 = 0; k0 < K; k0 += 16) {
        float4 av = *(const float4*)(A + (size_t)(row0 + ar) * K + k0 + ak);
        As[ak][ar] = av.x; As[ak + 1][ar] = av.y; As[ak + 2][ar] = av.z; As[ak + 3][ar] = av.w;
        if (!TRANSB) {
            int br = tid >> 4;            // 0..15 (k)
            int bc = (tid & 15) << 2;     // 0..60 (n)
            int gc = col0 + bc;
            const float* bp = Bm + (size_t)(k0 + br) * N + gc;
            float4 bv;
            if (gc + 3 < N) bv = *(const float4*)bp;
            else {
                bv.x = (gc + 0 < N) ? bp[0] : 0.f;
                bv.y = (gc + 1 < N) ? bp[1] : 0.f;
                bv.z = (gc + 2 < N) ? bp[2] : 0.f;
                bv.w = (gc + 3 < N) ? bp[3] : 0.f;
            }
            Bs[br][bc] = bv.x; Bs[br][bc + 1] = bv.y; Bs[br][bc + 2] = bv.z; Bs[br][bc + 3] = bv.w;
        } else {
            int bn = tid >> 2;            // 0..63 (n)
            int bk = (tid & 3) << 2;      // 0,4,8,12 (k)
            int gc = col0 + bn;
            float4 bv = make_float4(0.f, 0.f, 0.f, 0.f);
            if (gc < N) bv = *(const float4*)(Bm + (size_t)gc * K + k0 + bk);
            Bs[bk][bn] = bv.x; Bs[bk + 1][bn] = bv.y; Bs[bk + 2][bn] = bv.z; Bs[bk + 3][bn] = bv.w;
        }
        __syncthreads();
#pragma unroll
        for (int k = 0; k < 16; k++) {
            float4 a = *(const float4*)&As[k][ty << 2];
            float4 b = *(const float4*)&Bs[k][tx << 2];
            acc[0][0] += a.x * b.x; acc[0][1] += a.x * b.y; acc[0][2] += a.x * b.z; acc[0][3] += a.x * b.w;
            acc[1][0] += a.y * b.x; acc[1][1] += a.y * b.y; acc[1][2] += a.y * b.z; acc[1][3] += a.y * b.w;
            acc[2][0] += a.z * b.x; acc[2][1] += a.z * b.y; acc[2][2] += a.z * b.z; acc[2][3] += a.z * b.w;
            acc[3][0] += a.w * b.x; acc[3][1] += a.w * b.y; acc[3][2] += a.w * b.z; acc[3][3] += a.w * b.w;
        }
        __syncthreads();
    }
#pragma unroll
    for (int i = 0; i < 4; i++) {
        int r = row0 + (ty << 2) + i;
#pragma unroll
        for (int j = 0; j < 4; j++) {
            int c = col0 + (tx << 2) + j;
            if (c < N) {
                float v = acc[i][j] + bias[c];
                if (ACT == 1) v = 0.5f * v * (1.f + erff(v * 0.70710678118654752f));
                if (RES) v += Res[(size_t)r * N + c];
                C[(size_t)r * N + c] = v;
            }
        }
    }
}

// ---------------- Attention scores: S = scale * Q @ K^T, causal masked ----------------
// grid (T/64 [k-tile], T/64 [q-tile], B*H). Skips fully-masked tiles.
__global__ void attn_scores_k(const float* __restrict__ qkv, float* __restrict__ sc) {
    int k0 = blockIdx.x * 64;
    int q0 = blockIdx.y * 64;
    if (k0 > q0 + 63) return;   // entire tile masked & never read
    int bh = blockIdx.z;
    int b = bh / HH, h = bh % HH;
    __shared__ float Qs[16][64];
    __shared__ float Ks[16][64];
    const float* base = qkv + (size_t)b * TT * 3 * EE;
    int tid = threadIdx.x;
    int tx = tid & 15, ty = tid >> 4;
    int lr = tid >> 2;
    int ld = (tid & 3) << 2;
    float acc[4][4] = {};
    for (int d0 = 0; d0 < DD; d0 += 16) {
        float4 qv = *(const float4*)(base + (size_t)(q0 + lr) * 3 * EE + h * DD + d0 + ld);
        Qs[ld][lr] = qv.x; Qs[ld + 1][lr] = qv.y; Qs[ld + 2][lr] = qv.z; Qs[ld + 3][lr] = qv.w;
        float4 kv = *(const float4*)(base + (size_t)(k0 + lr) * 3 * EE + EE + h * DD + d0 + ld);
        Ks[ld][lr] = kv.x; Ks[ld + 1][lr] = kv.y; Ks[ld + 2][lr] = kv.z; Ks[ld + 3][lr] = kv.w;
        __syncthreads();
#pragma unroll
        for (int k = 0; k < 16; k++) {
            float4 a = *(const float4*)&Qs[k][ty << 2];
            float4 c = *(const float4*)&Ks[k][tx << 2];
            acc[0][0] += a.x * c.x; acc[0][1] += a.x * c.y; acc[0][2] += a.x * c.z; acc[0][3] += a.x * c.w;
            acc[1][0] += a.y * c.x; acc[1][1] += a.y * c.y; acc[1][2] += a.y * c.z; acc[1][3] += a.y * c.w;
            acc[2][0] += a.z * c.x; acc[2][1] += a.z * c.y; acc[2][2] += a.z * c.z; acc[2][3] += a.z * c.w;
            acc[3][0] += a.w * c.x; acc[3][1] += a.w * c.y; acc[3][2] += a.w * c.z; acc[3][3] += a.w * c.w;
        }
        __syncthreads();
    }
    const float scale = 0.125f;  // D^-0.5, D=64
    float* srow = sc + (size_t)bh * TT * TT;
#pragma unroll
    for (int i = 0; i < 4; i++) {
        int q = q0 + (ty << 2) + i;
#pragma unroll
        for (int j = 0; j < 4; j++) {
            int kk = k0 + (tx << 2) + j;
            float s = acc[i][j] * scale;
            if (kk > q) s = -1e30f;
            srow[(size_t)q * TT + kk] = s;
        }
    }
}

// ---------------- Row softmax over causal-valid prefix; zeros the rest of the tile span ----------------
__global__ void softmax_k(float* __restrict__ sc) {
    int row = blockIdx.x;             // bh*T + q
    int q = row & (TT - 1);
    float* p = sc + (size_t)row * TT;
    int valid = q + 1;
    int tid = threadIdx.x;
    __shared__ float sh[256];
    float m = -1e30f;
    for (int i = tid; i < valid; i += 256) m = fmaxf(m, p[i]);
    sh[tid] = m; __syncthreads();
    for (int o = 128; o; o >>= 1) { if (tid < o) sh[tid] = fmaxf(sh[tid], sh[tid + o]); __syncthreads(); }
    m = sh[0]; __syncthreads();
    float s = 0.f;
    for (int i = tid; i < valid; i += 256) s += __expf(p[i] - m);
    sh[tid] = s; __syncthreads();
    for (int o = 128; o; o >>= 1) { if (tid < o) sh[tid] += sh[tid + o]; __syncthreads(); }
    float inv = 1.f / sh[0];
    int wl = ((q >> 6) + 1) << 6;     // write up through the last 64-wide tile attn_v will read
    for (int i = tid; i < wl; i += 256) {
        float v = 0.f;
        if (i < valid) v = __expf(p[i] - m) * inv;
        p[i] = v;
    }
}

// ---------------- attn = P @ V, exploiting causal k <= q0+63 ----------------
// grid (T/64 [q-tile], B*H)
__global__ void attn_v_k(const float* __restrict__ qkv, const float* __restrict__ sc,
                         float* __restrict__ out) {
    int q0 = blockIdx.x * 64;
    int bh = blockIdx.y;
    int b = bh / HH, h = bh % HH;
    __shared__ float Ss[16][64];
    __shared__ float Vs[16][64];
    const float* vbase = qkv + (size_t)b * TT * 3 * EE + 2 * EE + h * DD;
    const float* srow = sc + (size_t)bh * TT * TT;
    int tid = threadIdx.x;
    int tx = tid & 15, ty = tid >> 4;
    int lr = tid >> 2;            // 0..63 (q row within tile)
    int lk = (tid & 3) << 2;      // 0,4,8,12 (k within 16-chunk)
    int vr = tid >> 4;            // 0..15 (k row)
    int vc = (tid & 15) << 2;     // 0..60 (d)
    float acc[4][4] = {};
    int kmax = q0 + 64;           // causal bound for this q tile
    for (int kt = 0; kt < kmax; kt += 16) {
        float4 sv = *(const float4*)(srow + (size_t)(q0 + lr) * TT + kt + lk);
        Ss[lk][lr] = sv.x; Ss[lk + 1][lr] = sv.y; Ss[lk + 2][lr] = sv.z; Ss[lk + 3][lr] = sv.w;
        float4 vv = *(const float4*)(vbase + (size_t)(kt + vr) * 3 * EE + vc);
        Vs[vr][vc] = vv.x; Vs[vr][vc + 1] = vv.y; Vs[vr][vc + 2] = vv.z; Vs[vr][vc + 3] = vv.w;
        __syncthreads();
#pragma unroll
        for (int k = 0; k < 16; k++) {
            float4 a = *(const float4*)&Ss[k][ty << 2];
            float4 c = *(const float4*)&Vs[k][tx << 2];
            acc[0][0] += a.x * c.x; acc[0][1] += a.x * c.y; acc[0][2] += a.x * c.z; acc[0][3] += a.x * c.w;
            acc[1][0] += a.y * c.x; acc[1][1] += a.y * c.y; acc[1][2] += a.y * c.z; acc[1][3] += a.y * c.w;
            acc[2][0] += a.z * c.x; acc[2][1] += a.z * c.y; acc[2][2] += a.z * c.z; acc[2][3] += a.z * c.w;
            acc[3][0] += a.w * c.x; acc[3][1] += a.w * c.y; acc[3][2] += a.w * c.z; acc[3][3] += a.w * c.w;
        }
        __syncthreads();
    }
#pragma unroll
    for (int i = 0; i < 4; i++) {
        int q = q0 + (ty << 2) + i;
#pragma unroll
        for (int j = 0; j < 4; j++) {
            int d = (tx << 2) + j;
            out[((size_t)(b * TT + q)) * EE + h * DD + d] = acc[i][j];
        }
    }
}

// ---------------- Per-row NLL over V=50257 logits ----------------
__global__ void nll_k(const float* __restrict__ logits, const int* __restrict__ tgt,
                      float* __restrict__ nll) {
    int row = blockIdx.x;
    const float* lr = logits + (size_t)row * VV;
    int tid = threadIdx.x;
    __shared__ float sh[256];
    float m = -1e30f;
    for (int i = tid; i < VV; i += 256) m = fmaxf(m, lr[i]);
    sh[tid] = m; __syncthreads();
    for (int o = 128; o; o >>= 1) { if (tid < o) sh[tid] = fmaxf(sh[tid], sh[tid + o]); __syncthreads(); }
    m = sh[0]; __syncthreads();
    float s = 0.f;
    for (int i = tid; i < VV; i += 256) s += __expf(lr[i] - m);
    sh[tid] = s; __syncthreads();
    for (int o = 128; o; o >>= 1) { if (tid < o) sh[tid] += sh[tid + o]; __syncthreads(); }
    if (tid == 0) nll[row] = logf(sh[0]) + m - lr[tgt[row]];
}

__global__ void loss_reduce_k(const float* __restrict__ nll, float* __restrict__ dst, int count) {
    __shared__ float sh[256];
    float s = 0.f;
    for (int i = threadIdx.x; i < MM; i += 256) s += nll[i];
    sh[threadIdx.x] = s; __syncthreads();
    for (int o = 128; o; o >>= 1) { if (threadIdx.x < o) sh[threadIdx.x] += sh[threadIdx.x + o]; __syncthreads(); }
    if (threadIdx.x == 0) {
        float loss = sh[0] * (1.f / (float)MM);
        for (int i = 0; i < count; i++) dst[i] = loss;
    }
}

// ---------------- Launch ----------------
extern "C" void kernel_launch(void* const* d_in, const int* in_sizes, int n_in,
                              void* d_out, int out_size) {
    const int*   idx     = (const int*)  d_in[0];
    const int*   targets = (const int*)  d_in[1];
    const float* wte     = (const float*)d_in[2];
    const float* wpe     = (const float*)d_in[3];
    const float* ln1_g   = (const float*)d_in[4];
    const float* ln1_b   = (const float*)d_in[5];
    const float* qkv_w   = (const float*)d_in[6];
    const float* qkv_b   = (const float*)d_in[7];
    const float* o_w     = (const float*)d_in[8];
    const float* o_b     = (const float*)d_in[9];
    const float* ln2_g   = (const float*)d_in[10];
    const float* ln2_b   = (const float*)d_in[11];
    const float* up_w    = (const float*)d_in[12];
    const float* up_b    = (const float*)d_in[13];
    const float* down_w  = (const float*)d_in[14];
    const float* down_b  = (const float*)d_in[15];
    const float* lnf_g   = (const float*)d_in[16];
    const float* lnf_b   = (const float*)d_in[17];
    const float* lm_b    = (const float*)d_in[18];

    float *h, *x, *qkv, *sc, *attn, *mlp, *nll, *logits_scratch;
    cudaGetSymbolAddress((void**)&h,    g_h);
    cudaGetSymbolAddress((void**)&x,    g_x);
    cudaGetSymbolAddress((void**)&qkv,  g_qkv);
    cudaGetSymbolAddress((void**)&sc,   g_sc);
    cudaGetSymbolAddress((void**)&attn, g_attn);
    cudaGetSymbolAddress((void**)&mlp,  g_mlp);
    cudaGetSymbolAddress((void**)&nll,  g_nll);
    cudaGetSymbolAddress((void**)&logits_scratch, g_logits);

    float* logits = ((long long)out_size >= NBTV) ? (float*)d_out : logits_scratch;

    embed_k<<<MM, 256>>>(idx, wte, wpe, h);

    for (int l = 0; l < LL; l++) {
        layernorm_k<<<MM, 256>>>(h, ln1_g + (size_t)l * EE, ln1_b + (size_t)l * EE, x);
        sgemm_k<false, 0, false><<<dim3(MM / 64, 3 * EE / 64), 256>>>(
            x, qkv_w + (size_t)l * EE * 3 * EE, qkv_b + (size_t)l * 3 * EE, nullptr,
            qkv, MM, 3 * EE, EE);
        attn_scores_k<<<dim3(TT / 64, TT / 64, BB * HH), 256>>>(qkv, sc);
        softmax_k<<<BB * HH * TT, 256>>>(sc);
        attn_v_k<<<dim3(TT / 64, BB * HH), 256>>>(qkv, sc, attn);
        sgemm_k<false, 0, true><<<dim3(MM / 64, EE / 64), 256>>>(
            attn, o_w + (size_t)l * EE * EE, o_b + (size_t)l * EE, h,
            h, MM, EE, EE);
        layernorm_k<<<MM, 256>>>(h, ln2_g + (size_t)l * EE, ln2_b + (size_t)l * EE, x);
        sgemm_k<false, 1, false><<<dim3(MM / 64, 4 * EE / 64), 256>>>(
            x, up_w + (size_t)l * EE * 4 * EE, up_b + (size_t)l * 4 * EE, nullptr,
            mlp, MM, 4 * EE, EE);
        sgemm_k<false, 0, true><<<dim3(MM / 64, EE / 64), 256>>>(
            mlp, down_w + (size_t)l * 4 * EE * EE, down_b + (size_t)l * EE, h,
            h, MM, EE, 4 * EE);
    }

    layernorm_k<<<MM, 256>>>(h, lnf_g, lnf_b, x);
    sgemm_k<true, 0, false><<<dim3(MM / 64, (VV + 63) / 64), 256>>>(
        x, wte, lm_b, nullptr, logits, MM, VV, EE);

    nll_k<<<MM, 256>>>(logits, targets, nll);

    long long extra = (long long)out_size - NBTV;
    if (extra > 0) {
        loss_reduce_k<<<1, 256>>>(nll, (float*)d_out + NBTV, (int)extra);
    } else if ((long long)out_size < NBTV) {
        loss_reduce_k<<<1, 256>>>(nll, (float*)d_out, out_size);
    }
}

// round 2
// speedup vs baseline: 2.4603x; 2.4603x over previous
#include <cuda_runtime.h>
#include <math.h>
#include <stdint.h>

// ---------------- Problem constants ----------------
static constexpr int BB = 2;
static constexpr int TT = 1024;
static constexpr int EE = 1024;
static constexpr int HH = 16;
static constexpr int DD = 64;
static constexpr int LL = 12;
static constexpr int VV = 50257;
static constexpr int MM = BB * TT;                 // 2048 rows
static constexpr long long NBTV = (long long)MM * VV;

// ---------------- Scratch (device globals; no runtime allocation) ----------------
__device__ float g_h   [(size_t)MM * EE];
__device__ float g_x   [(size_t)MM * EE];
__device__ float g_qkv [(size_t)MM * 3 * EE];
__device__ float g_sc  [(size_t)BB * HH * TT * TT];
__device__ float g_attn[(size_t)MM * EE];
__device__ float g_mlp [(size_t)MM * 4 * EE];
__device__ float g_nll [MM];
__device__ float g_logits[(size_t)MM * VV];

// ---------------- Helpers ----------------
__device__ __forceinline__ float tf32r(float x) {
    uint32_t u;
    asm("cvt.rna.tf32.f32 %0, %1;" : "=r"(u) : "f"(x));
    return __uint_as_float(u);
}

__device__ __forceinline__ void mma_tf32(float c[4], const uint32_t a[4], const uint32_t b[2]) {
    asm volatile(
        "mma.sync.aligned.m16n8k8.row.col.f32.tf32.tf32.f32 "
        "{%0,%1,%2,%3}, {%4,%5,%6,%7}, {%8,%9}, {%0,%1,%2,%3};"
        : "+f"(c[0]), "+f"(c[1]), "+f"(c[2]), "+f"(c[3])
        : "r"(a[0]), "r"(a[1]), "r"(a[2]), "r"(a[3]), "r"(b[0]), "r"(b[1]));
}

// ---------------- Embedding ----------------
__global__ void embed_k(const int* __restrict__ idx, const float* __restrict__ wte,
                        const float* __restrict__ wpe, float* __restrict__ h) {
    int bt = blockIdx.x;
    int t  = bt % TT;
    int tok = idx[bt];
    int i = threadIdx.x * 4;
    float4 a = *(const float4*)(wte + (size_t)tok * EE + i);
    float4 p = *(const float4*)(wpe + (size_t)t   * EE + i);
    a.x += p.x; a.y += p.y; a.z += p.z; a.w += p.w;
    *(float4*)(h + (size_t)bt * EE + i) = a;
}

// ---------------- LayerNorm ----------------
__global__ void layernorm_k(const float* __restrict__ xin, const float* __restrict__ g,
                            const float* __restrict__ bb, float* __restrict__ y) {
    __shared__ float rs[8], rq[8];
    int row = blockIdx.x, tid = threadIdx.x;
    const float* xr = xin + (size_t)row * EE;
    float4 v = *(const float4*)(xr + tid * 4);
    float s = v.x + v.y + v.z + v.w;
    float q = v.x * v.x + v.y * v.y + v.z * v.z + v.w * v.w;
#pragma unroll
    for (int o = 16; o; o >>= 1) {
        s += __shfl_xor_sync(0xffffffffu, s, o);
        q += __shfl_xor_sync(0xffffffffu, q, o);
    }
    if ((tid & 31) == 0) { rs[tid >> 5] = s; rq[tid >> 5] = q; }
    __syncthreads();
    if (tid == 0) {
        float S = 0.f, Q = 0.f;
#pragma unroll
        for (int i = 0; i < 8; i++) { S += rs[i]; Q += rq[i]; }
        rs[0] = S; rq[0] = Q;
    }
    __syncthreads();
    float mean = rs[0] * (1.f / EE);
    float var  = rq[0] * (1.f / EE) - mean * mean;
    float rstd = rsqrtf(var + 1e-5f);
    float4 gg = *(const float4*)(g  + tid * 4);
    float4 be = *(const float4*)(bb + tid * 4);
    float4 o;
    o.x = (v.x - mean) * rstd * gg.x + be.x;
    o.y = (v.y - mean) * rstd * gg.y + be.y;
    o.z = (v.z - mean) * rstd * gg.z + be.z;
    o.w = (v.w - mean) * rstd * gg.w + be.w;
    *(float4*)(y + (size_t)row * EE + tid * 4) = o;
}

// ---------------- Tensor-core GEMM (tf32 mma.sync) ----------------
// C = act(A@B + bias) [+ Res]
// A: [M,K] row-major. B: [K,N] (TRANSB=false) or [N,K] (TRANSB=true).
// Block tile 128x128x16, 256 threads = 8 warps (2x4), warp tile 64x32.
// M % 128 == 0, K % 16 == 0 assumed; N arbitrary only when TRANSB.
template<bool TRANSB, int ACT, bool RES>
__global__ __launch_bounds__(256)
void mmagemm_k(const float* __restrict__ A, const float* __restrict__ Bm,
               const float* __restrict__ bias, const float* __restrict__ Res,
               float* __restrict__ C, int M, int N, int K) {
    constexpr int AST = 20;                      // As row stride (floats): [128][20]
    constexpr int BST = TRANSB ? 134 : 136;      // Bs row stride (floats): [16][BST]
    __shared__ float As[2][128 * AST];
    __shared__ float Bs[2][16 * BST];

    const int tid  = threadIdx.x;
    const int lane = tid & 31;
    const int wid  = tid >> 5;
    const int wm   = wid >> 2;       // 0..1
    const int wn   = wid & 3;        // 0..3
    const int g    = lane >> 2;      // 0..7
    const int t    = lane & 3;       // 0..3

    const int row0 = blockIdx.x * 128;
    const int col0 = blockIdx.y * 128;

    // ---- global load indices ----
    const int ar  = tid >> 2;             // 0..63
    const int ac4 = (tid & 3) << 2;       // 0,4,8,12
    // B non-trans: 16 x 128 tile
    const int bkr = tid >> 5;             // 0..7
    const int bc4 = (lane) << 2;          // 0..124
    // B trans: 128 (n) x 16 (k) source
    const int bnr = tid >> 2;             // 0..63
    const int bk4 = (tid & 3) << 2;

    float4 a0g, a1g, b0g, b1g;

    auto ld_global = [&](int k0) {
        a0g = *(const float4*)(A + (size_t)(row0 + ar) * K + k0 + ac4);
        a1g = *(const float4*)(A + (size_t)(row0 + ar + 64) * K + k0 + ac4);
        if (!TRANSB) {
            b0g = *(const float4*)(Bm + (size_t)(k0 + bkr) * N + col0 + bc4);
            b1g = *(const float4*)(Bm + (size_t)(k0 + bkr + 8) * N + col0 + bc4);
        } else {
            int n0 = col0 + bnr, n1 = col0 + bnr + 64;
            b0g = (n0 < N) ? *(const float4*)(Bm + (size_t)n0 * K + k0 + bk4)
                           : make_float4(0.f, 0.f, 0.f, 0.f);
            b1g = (n1 < N) ? *(const float4*)(Bm + (size_t)n1 * K + k0 + bk4)
                           : make_float4(0.f, 0.f, 0.f, 0.f);
        }
    };

    auto st_smem = [&](int buf) {
        float* ap = &As[buf][ar * AST + ac4];
        ap[0] = tf32r(a0g.x); ap[1] = tf32r(a0g.y); ap[2] = tf32r(a0g.z); ap[3] = tf32r(a0g.w);
        float* ap2 = &As[buf][(ar + 64) * AST + ac4];
        ap2[0] = tf32r(a1g.x); ap2[1] = tf32r(a1g.y); ap2[2] = tf32r(a1g.z); ap2[3] = tf32r(a1g.w);
        if (!TRANSB) {
            float* bp = &Bs[buf][bkr * BST + bc4];
            bp[0] = tf32r(b0g.x); bp[1] = tf32r(b0g.y); bp[2] = tf32r(b0g.z); bp[3] = tf32r(b0g.w);
            float* bp2 = &Bs[buf][(bkr + 8) * BST + bc4];
            bp2[0] = tf32r(b1g.x); bp2[1] = tf32r(b1g.y); bp2[2] = tf32r(b1g.z); bp2[3] = tf32r(b1g.w);
        } else {
            Bs[buf][(bk4 + 0) * BST + bnr] = tf32r(b0g.x);
            Bs[buf][(bk4 + 1) * BST + bnr] = tf32r(b0g.y);
            Bs[buf][(bk4 + 2) * BST + bnr] = tf32r(b0g.z);
            Bs[buf][(bk4 + 3) * BST + bnr] = tf32r(b0g.w);
            Bs[buf][(bk4 + 0) * BST + bnr + 64] = tf32r(b1g.x);
            Bs[buf][(bk4 + 1) * BST + bnr + 64] = tf32r(b1g.y);
            Bs[buf][(bk4 + 2) * BST + bnr + 64] = tf32r(b1g.z);
            Bs[buf][(bk4 + 3) * BST + bnr + 64] = tf32r(b1g.w);
        }
    };

    float acc[4][4][4] = {};

    const int nIters = K >> 4;
    int buf = 0;
    ld_global(0);
    st_smem(0);
    __syncthreads();

    for (int it = 0; it < nIters; ++it) {
        if (it + 1 < nIters) ld_global((it + 1) << 4);

        const float* Ab = As[buf];
        const float* Bb = Bs[buf];
#pragma unroll
        for (int ks = 0; ks < 2; ks++) {
            uint32_t afr[4][4];
            uint32_t bfr[4][2];
#pragma unroll
            for (int mt = 0; mt < 4; mt++) {
                int r = wm * 64 + mt * 16 + g;
                int kk = ks * 8 + t;
                afr[mt][0] = __float_as_uint(Ab[(r)     * AST + kk]);
                afr[mt][1] = __float_as_uint(Ab[(r + 8) * AST + kk]);
                afr[mt][2] = __float_as_uint(Ab[(r)     * AST + kk + 4]);
                afr[mt][3] = __float_as_uint(Ab[(r + 8) * AST + kk + 4]);
            }
#pragma unroll
            for (int nt = 0; nt < 4; nt++) {
                int c = wn * 32 + nt * 8 + g;
                bfr[nt][0] = __float_as_uint(Bb[(ks * 8 + t)     * BST + c]);
                bfr[nt][1] = __float_as_uint(Bb[(ks * 8 + t + 4) * BST + c]);
            }
#pragma unroll
            for (int mt = 0; mt < 4; mt++)
#pragma unroll
                for (int nt = 0; nt < 4; nt++)
                    mma_tf32(acc[mt][nt], afr[mt], bfr[nt]);
        }

        if (it + 1 < nIters) {
            st_smem(buf ^ 1);
            __syncthreads();
            buf ^= 1;
        }
    }

    // ---- epilogue ----
#pragma unroll
    for (int mt = 0; mt < 4; mt++) {
        int r0 = row0 + wm * 64 + mt * 16 + g;
#pragma unroll
        for (int nt = 0; nt < 4; nt++) {
            int c = col0 + wn * 32 + nt * 8 + t * 2;
#pragma unroll
            for (int half = 0; half < 2; half++) {
                int r = r0 + half * 8;
                float v0 = acc[mt][nt][half * 2 + 0];
                float v1 = acc[mt][nt][half * 2 + 1];
                if (!TRANSB) {
                    v0 += bias[c]; v1 += bias[c + 1];
                    if (ACT == 1) {
                        v0 = 0.5f * v0 * (1.f + erff(v0 * 0.70710678118654752f));
                        v1 = 0.5f * v1 * (1.f + erff(v1 * 0.70710678118654752f));
                    }
                    if (RES) {
                        v0 += Res[(size_t)r * N + c];
                        v1 += Res[(size_t)r * N + c + 1];
                    }
                    *(float2*)(C + (size_t)r * N + c) = make_float2(v0, v1);
                } else {
                    if (c < N)     C[(size_t)r * N + c]     = v0 + bias[c];
                    if (c + 1 < N) C[(size_t)r * N + c + 1] = v1 + bias[c + 1];
                }
            }
        }
    }
}

// ---------------- Attention scores: S = scale * Q @ K^T, causal masked ----------------
__global__ void attn_scores_k(const float* __restrict__ qkv, float* __restrict__ sc) {
    int k0 = blockIdx.x * 64;
    int q0 = blockIdx.y * 64;
    if (k0 > q0 + 63) return;
    int bh = blockIdx.z;
    int b = bh / HH, h = bh % HH;
    __shared__ float Qs[16][64];
    __shared__ float Ks[16][64];
    const float* base = qkv + (size_t)b * TT * 3 * EE;
    int tid = threadIdx.x;
    int tx = tid & 15, ty = tid >> 4;
    int lr = tid >> 2;
    int ld = (tid & 3) << 2;
    float acc[4][4] = {};
    for (int d0 = 0; d0 < DD; d0 += 16) {
        float4 qv = *(const float4*)(base + (size_t)(q0 + lr) * 3 * EE + h * DD + d0 + ld);
        Qs[ld][lr] = qv.x; Qs[ld + 1][lr] = qv.y; Qs[ld + 2][lr] = qv.z; Qs[ld + 3][lr] = qv.w;
        float4 kv = *(const float4*)(base + (size_t)(k0 + lr) * 3 * EE + EE + h * DD + d0 + ld);
        Ks[ld][lr] = kv.x; Ks[ld + 1][lr] = kv.y; Ks[ld + 2][lr] = kv.z; Ks[ld + 3][lr] = kv.w;
        __syncthreads();
#pragma unroll
        for (int k = 0; k < 16; k++) {
            float4 a = *(const float4*)&Qs[k][ty << 2];
            float4 c = *(const float4*)&Ks[k][tx << 2];
            acc[0][0] += a.x * c.x; acc[0][1] += a.x * c.y; acc[0][2] += a.x * c.z; acc[0][3] += a.x * c.w;
            acc[1][0] += a.y * c.x; acc[1][1] += a.y * c.y; acc[1][2] += a.y * c.z; acc[1][3] += a.y * c.w;
            acc[2][0] += a.z * c.x; acc[2][1] += a.z * c.y; acc[2][2] += a.z * c.z; acc[2][3] += a.z * c.w;
            acc[3][0] += a.w * c.x; acc[3][1] += a.w * c.y; acc[3][2] += a.w * c.z; acc[3][3] += a.w * c.w;
        }
        __syncthreads();
    }
    const float scale = 0.125f;
    float* srow = sc + (size_t)bh * TT * TT;
#pragma unroll
    for (int i = 0; i < 4; i++) {
        int q = q0 + (ty << 2) + i;
#pragma unroll
        for (int j = 0; j < 4; j++) {
            int kk = k0 + (tx << 2) + j;
            float s = acc[i][j] * scale;
            if (kk > q) s = -1e30f;
            srow[(size_t)q * TT + kk] = s;
        }
    }
}

// ---------------- Row softmax over causal-valid prefix ----------------
__global__ void softmax_k(float* __restrict__ sc) {
    int row = blockIdx.x;
    int q = row & (TT - 1);
    float* p = sc + (size_t)row * TT;
    int valid = q + 1;
    int tid = threadIdx.x;
    __shared__ float sh[256];
    float m = -1e30f;
    for (int i = tid; i < valid; i += 256) m = fmaxf(m, p[i]);
    sh[tid] = m; __syncthreads();
    for (int o = 128; o; o >>= 1) { if (tid < o) sh[tid] = fmaxf(sh[tid], sh[tid + o]); __syncthreads(); }
    m = sh[0]; __syncthreads();
    float s = 0.f;
    for (int i = tid; i < valid; i += 256) s += __expf(p[i] - m);
    sh[tid] = s; __syncthreads();
    for (int o = 128; o; o >>= 1) { if (tid < o) sh[tid] += sh[tid + o]; __syncthreads(); }
    float inv = 1.f / sh[0];
    int wl = ((q >> 6) + 1) << 6;
    for (int i = tid; i < wl; i += 256) {
        float v = 0.f;
        if (i < valid) v = __expf(p[i] - m) * inv;
        p[i] = v;
    }
}

// ---------------- attn = P @ V ----------------
__global__ void attn_v_k(const float* __restrict__ qkv, const float* __restrict__ sc,
                         float* __restrict__ out) {
    int q0 = blockIdx.x * 64;
    int bh = blockIdx.y;
    int b = bh / HH, h = bh % HH;
    __shared__ float Ss[16][64];
    __shared__ float Vs[16][64];
    const float* vbase = qkv + (size_t)b * TT * 3 * EE + 2 * EE + h * DD;
    const float* srow = sc + (size_t)bh * TT * TT;
    int tid = threadIdx.x;
    int tx = tid & 15, ty = tid >> 4;
    int lr = tid >> 2;
    int lk = (tid & 3) << 2;
    int vr = tid >> 4;
    int vc = (tid & 15) << 2;
    float acc[4][4] = {};
    int kmax = q0 + 64;
    for (int kt = 0; kt < kmax; kt += 16) {
        float4 sv = *(const float4*)(srow + (size_t)(q0 + lr) * TT + kt + lk);
        Ss[lk][lr] = sv.x; Ss[lk + 1][lr] = sv.y; Ss[lk + 2][lr] = sv.z; Ss[lk + 3][lr] = sv.w;
        float4 vv = *(const float4*)(vbase + (size_t)(kt + vr) * 3 * EE + vc);
        Vs[vr][vc] = vv.x; Vs[vr][vc + 1] = vv.y; Vs[vr][vc + 2] = vv.z; Vs[vr][vc + 3] = vv.w;
        __syncthreads();
#pragma unroll
        for (int k = 0; k < 16; k++) {
            float4 a = *(const float4*)&Ss[k][ty << 2];
            float4 c = *(const float4*)&Vs[k][tx << 2];
            acc[0][0] += a.x * c.x; acc[0][1] += a.x * c.y; acc[0][2] += a.x * c.z; acc[0][3] += a.x * c.w;
            acc[1][0] += a.y * c.x; acc[1][1] += a.y * c.y; acc[1][2] += a.y * c.z; acc[1][3] += a.y * c.w;
            acc[2][0] += a.z * c.x; acc[2][1] += a.z * c.y; acc[2][2] += a.z * c.z; acc[2][3] += a.z * c.w;
            acc[3][0] += a.w * c.x; acc[3][1] += a.w * c.y; acc[3][2] += a.w * c.z; acc[3][3] += a.w * c.w;
        }
        __syncthreads();
    }
#pragma unroll
    for (int i = 0; i < 4; i++) {
        int q = q0 + (ty << 2) + i;
#pragma unroll
        for (int j = 0; j < 4; j++) {
            int d = (tx << 2) + j;
            out[((size_t)(b * TT + q)) * EE + h * DD + d] = acc[i][j];
        }
    }
}

// ---------------- Per-row NLL ----------------
__global__ void nll_k(const float* __restrict__ logits, const int* __restrict__ tgt,
                      float* __restrict__ nll) {
    int row = blockIdx.x;
    const float* lr = logits + (size_t)row * VV;
    int tid = threadIdx.x;
    __shared__ float sh[256];
    float m = -1e30f;
    for (int i = tid; i < VV; i += 256) m = fmaxf(m, lr[i]);
    sh[tid] = m; __syncthreads();
    for (int o = 128; o; o >>= 1) { if (tid < o) sh[tid] = fmaxf(sh[tid], sh[tid + o]); __syncthreads(); }
    m = sh[0]; __syncthreads();
    float s = 0.f;
    for (int i = tid; i < VV; i += 256) s += __expf(lr[i] - m);
    sh[tid] = s; __syncthreads();
    for (int o = 128; o; o >>= 1) { if (tid < o) sh[tid] += sh[tid + o]; __syncthreads(); }
    if (tid == 0) nll[row] = logf(sh[0]) + m - lr[tgt[row]];
}

__global__ void loss_reduce_k(const float* __restrict__ nll, float* __restrict__ dst, int count) {
    __shared__ float sh[256];
    float s = 0.f;
    for (int i = threadIdx.x; i < MM; i += 256) s += nll[i];
    sh[threadIdx.x] = s; __syncthreads();
    for (int o = 128; o; o >>= 1) { if (threadIdx.x < o) sh[threadIdx.x] += sh[threadIdx.x + o]; __syncthreads(); }
    if (threadIdx.x == 0) {
        float loss = sh[0] * (1.f / (float)MM);
        for (int i = 0; i < count; i++) dst[i] = loss;
    }
}

// ---------------- Launch ----------------
extern "C" void kernel_launch(void* const* d_in, const int* in_sizes, int n_in,
                              void* d_out, int out_size) {
    const int*   idx     = (const int*)  d_in[0];
    const int*   targets = (const int*)  d_in[1];
    const float* wte     = (const float*)d_in[2];
    const float* wpe     = (const float*)d_in[3];
    const float* ln1_g   = (const float*)d_in[4];
    const float* ln1_b   = (const float*)d_in[5];
    const float* qkv_w   = (const float*)d_in[6];
    const float* qkv_b   = (const float*)d_in[7];
    const float* o_w     = (const float*)d_in[8];
    const float* o_b     = (const float*)d_in[9];
    const float* ln2_g   = (const float*)d_in[10];
    const float* ln2_b   = (const float*)d_in[11];
    const float* up_w    = (const float*)d_in[12];
    const float* up_b    = (const float*)d_in[13];
    const float* down_w  = (const float*)d_in[14];
    const float* down_b  = (const float*)d_in[15];
    const float* lnf_g   = (const float*)d_in[16];
    const float* lnf_b   = (const float*)d_in[17];
    const float* lm_b    = (const float*)d_in[18];

    float *h, *x, *qkv, *sc, *attn, *mlp, *nll, *logits_scratch;
    cudaGetSymbolAddress((void**)&h,    g_h);
    cudaGetSymbolAddress((void**)&x,    g_x);
    cudaGetSymbolAddress((void**)&qkv,  g_qkv);
    cudaGetSymbolAddress((void**)&sc,   g_sc);
    cudaGetSymbolAddress((void**)&attn, g_attn);
    cudaGetSymbolAddress((void**)&mlp,  g_mlp);
    cudaGetSymbolAddress((void**)&nll,  g_nll);
    cudaGetSymbolAddress((void**)&logits_scratch, g_logits);

    float* logits = ((long long)out_size >= NBTV) ? (float*)d_out : logits_scratch;

    embed_k<<<MM, 256>>>(idx, wte, wpe, h);

    for (int l = 0; l < LL; l++) {
        layernorm_k<<<MM, 256>>>(h, ln1_g + (size_t)l * EE, ln1_b + (size_t)l * EE, x);
        mmagemm_k<false, 0, false><<<dim3(MM / 128, 3 * EE / 128), 256>>>(
            x, qkv_w + (size_t)l * EE * 3 * EE, qkv_b + (size_t)l * 3 * EE, nullptr,
            qkv, MM, 3 * EE, EE);
        attn_scores_k<<<dim3(TT / 64, TT / 64, BB * HH), 256>>>(qkv, sc);
        softmax_k<<<BB * HH * TT, 256>>>(sc);
        attn_v_k<<<dim3(TT / 64, BB * HH), 256>>>(qkv, sc, attn);
        mmagemm_k<false, 0, true><<<dim3(MM / 128, EE / 128), 256>>>(
            attn, o_w + (size_t)l * EE * EE, o_b + (size_t)l * EE, h,
            h, MM, EE, EE);
        layernorm_k<<<MM, 256>>>(h, ln2_g + (size_t)l * EE, ln2_b + (size_t)l * EE, x);
        mmagemm_k<false, 1, false><<<dim3(MM / 128, 4 * EE / 128), 256>>>(
            x, up_w + (size_t)l * EE * 4 * EE, up_b + (size_t)l * 4 * EE, nullptr,
            mlp, MM, 4 * EE, EE);
        mmagemm_k<false, 0, true><<<dim3(MM / 128, EE / 128), 256>>>(
            mlp, down_w + (size_t)l * 4 * EE * EE, down_b + (size_t)l * EE, h,
            h, MM, EE, 4 * EE);
    }

    layernorm_k<<<MM, 256>>>(h, lnf_g, lnf_b, x);
    mmagemm_k<true, 0, false><<<dim3(MM / 128, (VV + 127) / 128), 256>>>(
        x, wte, lm_b, nullptr, logits, MM, VV, EE);

    nll_k<<<MM, 256>>>(logits, targets, nll);

    long long extra = (long long)out_size - NBTV;
    if (extra > 0) {
        loss_reduce_k<<<1, 256>>>(nll, (float*)d_out + NBTV, (int)extra);
    } else if ((long long)out_size < NBTV) {
        loss_reduce_k<<<1, 256>>>(nll, (float*)d_out, out_size);
    }
}

// round 3
// speedup vs baseline: 2.6819x; 1.0901x over previous
#include <cuda_runtime.h>
#include <math.h>
#include <stdint.h>

// ---------------- Problem constants ----------------
static constexpr int BB = 2;
static constexpr int TT = 1024;
static constexpr int EE = 1024;
static constexpr int HH = 16;
static constexpr int DD = 64;
static constexpr int LL = 12;
static constexpr int VV = 50257;
static constexpr int MM = BB * TT;
static constexpr long long NBTV = (long long)MM * VV;

// ---------------- Scratch ----------------
__device__ float g_h   [(size_t)MM * EE];
__device__ float g_x   [(size_t)MM * EE];
__device__ float g_qkv [(size_t)MM * 3 * EE];
__device__ float g_attn[(size_t)MM * EE];
__device__ float g_mlp [(size_t)MM * 4 * EE];
__device__ float g_nll [MM];
__device__ float g_logits[(size_t)MM * VV];

// ---------------- Helpers ----------------
__device__ __forceinline__ float tf32r(float x) {
    uint32_t u;
    asm("cvt.rna.tf32.f32 %0, %1;" : "=r"(u) : "f"(x));
    return __uint_as_float(u);
}

__device__ __forceinline__ void mma_tf32(float c[4], const uint32_t a[4], const uint32_t b[2]) {
    asm volatile(
        "mma.sync.aligned.m16n8k8.row.col.f32.tf32.tf32.f32 "
        "{%0,%1,%2,%3}, {%4,%5,%6,%7}, {%8,%9}, {%0,%1,%2,%3};"
        : "+f"(c[0]), "+f"(c[1]), "+f"(c[2]), "+f"(c[3])
        : "r"(a[0]), "r"(a[1]), "r"(a[2]), "r"(a[3]), "r"(b[0]), "r"(b[1]));
}

// ---------------- Embedding ----------------
__global__ void embed_k(const int* __restrict__ idx, const float* __restrict__ wte,
                        const float* __restrict__ wpe, float* __restrict__ h) {
    int bt = blockIdx.x;
    int t  = bt % TT;
    int tok = idx[bt];
    int i = threadIdx.x * 4;
    float4 a = *(const float4*)(wte + (size_t)tok * EE + i);
    float4 p = *(const float4*)(wpe + (size_t)t   * EE + i);
    a.x += p.x; a.y += p.y; a.z += p.z; a.w += p.w;
    *(float4*)(h + (size_t)bt * EE + i) = a;
}

// ---------------- LayerNorm ----------------
__global__ void layernorm_k(const float* __restrict__ xin, const float* __restrict__ g,
                            const float* __restrict__ bb, float* __restrict__ y) {
    __shared__ float rs[8], rq[8];
    int row = blockIdx.x, tid = threadIdx.x;
    const float* xr = xin + (size_t)row * EE;
    float4 v = *(const float4*)(xr + tid * 4);
    float s = v.x + v.y + v.z + v.w;
    float q = v.x * v.x + v.y * v.y + v.z * v.z + v.w * v.w;
#pragma unroll
    for (int o = 16; o; o >>= 1) {
        s += __shfl_xor_sync(0xffffffffu, s, o);
        q += __shfl_xor_sync(0xffffffffu, q, o);
    }
    if ((tid & 31) == 0) { rs[tid >> 5] = s; rq[tid >> 5] = q; }
    __syncthreads();
    if (tid == 0) {
        float S = 0.f, Q = 0.f;
#pragma unroll
        for (int i = 0; i < 8; i++) { S += rs[i]; Q += rq[i]; }
        rs[0] = S; rq[0] = Q;
    }
    __syncthreads();
    float mean = rs[0] * (1.f / EE);
    float var  = rq[0] * (1.f / EE) - mean * mean;
    float rstd = rsqrtf(var + 1e-5f);
    float4 gg = *(const float4*)(g  + tid * 4);
    float4 be = *(const float4*)(bb + tid * 4);
    float4 o;
    o.x = (v.x - mean) * rstd * gg.x + be.x;
    o.y = (v.y - mean) * rstd * gg.y + be.y;
    o.z = (v.z - mean) * rstd * gg.z + be.z;
    o.w = (v.w - mean) * rstd * gg.w + be.w;
    *(float4*)(y + (size_t)row * EE + tid * 4) = o;
}

// ---------------- Tensor-core GEMM (tf32 mma.sync) ----------------
template<bool TRANSB, int ACT, bool RES>
__global__ __launch_bounds__(256)
void mmagemm_k(const float* __restrict__ A, const float* __restrict__ Bm,
               const float* __restrict__ bias, const float* __restrict__ Res,
               float* __restrict__ C, int M, int N, int K) {
    constexpr int AST = 20;
    constexpr int BST = TRANSB ? 134 : 136;
    __shared__ float As[2][128 * AST];
    __shared__ float Bs[2][16 * BST];

    const int tid  = threadIdx.x;
    const int lane = tid & 31;
    const int wid  = tid >> 5;
    const int wm   = wid >> 2;
    const int wn   = wid & 3;
    const int g    = lane >> 2;
    const int t    = lane & 3;

    const int row0 = blockIdx.x * 128;
    const int col0 = blockIdx.y * 128;

    const int ar  = tid >> 2;
    const int ac4 = (tid & 3) << 2;
    const int bkr = tid >> 5;
    const int bc4 = (lane) << 2;
    const int bnr = tid >> 2;
    const int bk4 = (tid & 3) << 2;

    float4 a0g, a1g, b0g, b1g;

    auto ld_global = [&](int k0) {
        a0g = *(const float4*)(A + (size_t)(row0 + ar) * K + k0 + ac4);
        a1g = *(const float4*)(A + (size_t)(row0 + ar + 64) * K + k0 + ac4);
        if (!TRANSB) {
            b0g = *(const float4*)(Bm + (size_t)(k0 + bkr) * N + col0 + bc4);
            b1g = *(const float4*)(Bm + (size_t)(k0 + bkr + 8) * N + col0 + bc4);
        } else {
            int n0 = col0 + bnr, n1 = col0 + bnr + 64;
            b0g = (n0 < N) ? *(const float4*)(Bm + (size_t)n0 * K + k0 + bk4)
                           : make_float4(0.f, 0.f, 0.f, 0.f);
            b1g = (n1 < N) ? *(const float4*)(Bm + (size_t)n1 * K + k0 + bk4)
                           : make_float4(0.f, 0.f, 0.f, 0.f);
        }
    };

    auto st_smem = [&](int buf) {
        float* ap = &As[buf][ar * AST + ac4];
        ap[0] = tf32r(a0g.x); ap[1] = tf32r(a0g.y); ap[2] = tf32r(a0g.z); ap[3] = tf32r(a0g.w);
        float* ap2 = &As[buf][(ar + 64) * AST + ac4];
        ap2[0] = tf32r(a1g.x); ap2[1] = tf32r(a1g.y); ap2[2] = tf32r(a1g.z); ap2[3] = tf32r(a1g.w);
        if (!TRANSB) {
            float* bp = &Bs[buf][bkr * BST + bc4];
            bp[0] = tf32r(b0g.x); bp[1] = tf32r(b0g.y); bp[2] = tf32r(b0g.z); bp[3] = tf32r(b0g.w);
            float* bp2 = &Bs[buf][(bkr + 8) * BST + bc4];
            bp2[0] = tf32r(b1g.x); bp2[1] = tf32r(b1g.y); bp2[2] = tf32r(b1g.z); bp2[3] = tf32r(b1g.w);
        } else {
            Bs[buf][(bk4 + 0) * BST + bnr] = tf32r(b0g.x);
            Bs[buf][(bk4 + 1) * BST + bnr] = tf32r(b0g.y);
            Bs[buf][(bk4 + 2) * BST + bnr] = tf32r(b0g.z);
            Bs[buf][(bk4 + 3) * BST + bnr] = tf32r(b0g.w);
            Bs[buf][(bk4 + 0) * BST + bnr + 64] = tf32r(b1g.x);
            Bs[buf][(bk4 + 1) * BST + bnr + 64] = tf32r(b1g.y);
            Bs[buf][(bk4 + 2) * BST + bnr + 64] = tf32r(b1g.z);
            Bs[buf][(bk4 + 3) * BST + bnr + 64] = tf32r(b1g.w);
        }
    };

    float acc[4][4][4] = {};

    const int nIters = K >> 4;
    int buf = 0;
    ld_global(0);
    st_smem(0);
    __syncthreads();

    for (int it = 0; it < nIters; ++it) {
        if (it + 1 < nIters) ld_global((it + 1) << 4);

        const float* Ab = As[buf];
        const float* Bb = Bs[buf];
#pragma unroll
        for (int ks = 0; ks < 2; ks++) {
            uint32_t afr[4][4];
            uint32_t bfr[4][2];
#pragma unroll
            for (int mt = 0; mt < 4; mt++) {
                int r = wm * 64 + mt * 16 + g;
                int kk = ks * 8 + t;
                afr[mt][0] = __float_as_uint(Ab[(r)     * AST + kk]);
                afr[mt][1] = __float_as_uint(Ab[(r + 8) * AST + kk]);
                afr[mt][2] = __float_as_uint(Ab[(r)     * AST + kk + 4]);
                afr[mt][3] = __float_as_uint(Ab[(r + 8) * AST + kk + 4]);
            }
#pragma unroll
            for (int nt = 0; nt < 4; nt++) {
                int c = wn * 32 + nt * 8 + g;
                bfr[nt][0] = __float_as_uint(Bb[(ks * 8 + t)     * BST + c]);
                bfr[nt][1] = __float_as_uint(Bb[(ks * 8 + t + 4) * BST + c]);
            }
#pragma unroll
            for (int mt = 0; mt < 4; mt++)
#pragma unroll
                for (int nt = 0; nt < 4; nt++)
                    mma_tf32(acc[mt][nt], afr[mt], bfr[nt]);
        }

        if (it + 1 < nIters) {
            st_smem(buf ^ 1);
            __syncthreads();
            buf ^= 1;
        }
    }

#pragma unroll
    for (int mt = 0; mt < 4; mt++) {
        int r0 = row0 + wm * 64 + mt * 16 + g;
#pragma unroll
        for (int nt = 0; nt < 4; nt++) {
            int c = col0 + wn * 32 + nt * 8 + t * 2;
#pragma unroll
            for (int half = 0; half < 2; half++) {
                int r = r0 + half * 8;
                float v0 = acc[mt][nt][half * 2 + 0];
                float v1 = acc[mt][nt][half * 2 + 1];
                if (!TRANSB) {
                    v0 += bias[c]; v1 += bias[c + 1];
                    if (ACT == 1) {
                        v0 = 0.5f * v0 * (1.f + erff(v0 * 0.70710678118654752f));
                        v1 = 0.5f * v1 * (1.f + erff(v1 * 0.70710678118654752f));
                    }
                    if (RES) {
                        v0 += Res[(size_t)r * N + c];
                        v1 += Res[(size_t)r * N + c + 1];
                    }
                    *(float2*)(C + (size_t)r * N + c) = make_float2(v0, v1);
                } else {
                    if (c < N)     C[(size_t)r * N + c]     = v0 + bias[c];
                    if (c + 1 < N) C[(size_t)r * N + c + 1] = v1 + bias[c + 1];
                }
            }
        }
    }
}

// ---------------- Fused FP32 flash attention ----------------
// One block per (q-tile of 64 rows, b*h). 256 threads = 16x16 microtile grid.
// Streams K/V in 64-key chunks with online softmax. All FP32 (no tf32).
static constexpr int FA_Q  = 0;                 // Qs[d][row]  64x68
static constexpr int FA_K  = 64 * 68;           // Ks[d][key]  64x68
static constexpr int FA_V  = 2 * 64 * 68;       // Vs[key][d]  64x68
static constexpr int FA_P  = 3 * 64 * 68;       // Ps[key][row] 64x68
static constexpr int FA_R  = 4 * 64 * 68;       // red[row][17]
static constexpr int FA_M  = FA_R + 64 * 17;    // mrow[64]
static constexpr int FA_L  = FA_M + 64;         // lrow[64]
static constexpr int FA_A  = FA_L + 64;         // arow[64]
static constexpr int FA_FLOATS = FA_A + 64;
static constexpr int FA_SMEM_BYTES = FA_FLOATS * 4;  // ~74.8KB

__global__ __launch_bounds__(256)
void flash_attn_k(const float* __restrict__ qkv, float* __restrict__ out) {
    extern __shared__ float sm[];
    float* Qs   = sm + FA_Q;
    float* Ks   = sm + FA_K;
    float* Vs   = sm + FA_V;
    float* Ps   = sm + FA_P;
    float* red  = sm + FA_R;
    float* mrow = sm + FA_M;
    float* lrow = sm + FA_L;
    float* arow = sm + FA_A;

    const int tid = threadIdx.x;
    const int tx = tid & 15, ty = tid >> 4;
    const int qi = gridDim.x - 1 - blockIdx.x;     // big tiles first
    const int q0 = qi * 64;
    const int bh = blockIdx.y;
    const int b = bh / HH, h = bh % HH;

    const float* base = qkv + (size_t)b * TT * 3 * EE + h * DD;

    // load Q tile transposed: Qs[d][row]
    {
        int r = tid >> 2;               // 0..63
        int c = tid & 3;                // 0..3
        const float* qp = base + (size_t)(q0 + r) * 3 * EE;
#pragma unroll
        for (int u = 0; u < 4; u++) {
            int d = (c + 4 * u) * 4;
            float4 v = *(const float4*)(qp + d);
            Qs[(d + 0) * 68 + r] = v.x;
            Qs[(d + 1) * 68 + r] = v.y;
            Qs[(d + 2) * 68 + r] = v.z;
            Qs[(d + 3) * 68 + r] = v.w;
        }
    }
    if (tid < 64) { mrow[tid] = -1e30f; lrow[tid] = 0.f; }

    float oacc[4][4] = {};
    const int nch = qi + 1;

    for (int ch = 0; ch < nch; ch++) {
        const int kt = ch * 64;
        __syncthreads();   // protect Ks/Vs/Ps (+first iter: Q/m/l init)
        // load K chunk transposed Ks[d][key], V chunk natural Vs[key][d]
        {
            int r = tid >> 2;
            int c = tid & 3;
            const float* kp = base + (size_t)(kt + r) * 3 * EE + EE;
            const float* vp = base + (size_t)(kt + r) * 3 * EE + 2 * EE;
#pragma unroll
            for (int u = 0; u < 4; u++) {
                int d = (c + 4 * u) * 4;
                float4 kv = *(const float4*)(kp + d);
                Ks[(d + 0) * 68 + r] = kv.x;
                Ks[(d + 1) * 68 + r] = kv.y;
                Ks[(d + 2) * 68 + r] = kv.z;
                Ks[(d + 3) * 68 + r] = kv.w;
                float4 vv = *(const float4*)(vp + d);
                *(float4*)(Vs + r * 68 + d) = vv;
            }
        }
        __syncthreads();

        // S = Q @ K^T (16 values per thread)
        float sacc[4][4] = {};
#pragma unroll 8
        for (int d = 0; d < 64; d++) {
            float4 a = *(const float4*)(Qs + d * 68 + ty * 4);
            float4 c = *(const float4*)(Ks + d * 68 + tx * 4);
            sacc[0][0] += a.x * c.x; sacc[0][1] += a.x * c.y; sacc[0][2] += a.x * c.z; sacc[0][3] += a.x * c.w;
            sacc[1][0] += a.y * c.x; sacc[1][1] += a.y * c.y; sacc[1][2] += a.y * c.z; sacc[1][3] += a.y * c.w;
            sacc[2][0] += a.z * c.x; sacc[2][1] += a.z * c.y; sacc[2][2] += a.z * c.z; sacc[2][3] += a.z * c.w;
            sacc[3][0] += a.w * c.x; sacc[3][1] += a.w * c.y; sacc[3][2] += a.w * c.z; sacc[3][3] += a.w * c.w;
        }
        const bool diag = (kt == q0);
#pragma unroll
        for (int i = 0; i < 4; i++) {
            int q = q0 + ty * 4 + i;
            float lm = -1e30f;
#pragma unroll
            for (int j = 0; j < 4; j++) {
                float s = sacc[i][j] * 0.125f;
                if (diag && (kt + tx * 4 + j > q)) s = -1e30f;
                sacc[i][j] = s;
                lm = fmaxf(lm, s);
            }
            red[(ty * 4 + i) * 17 + tx] = lm;
        }
        __syncthreads();
        if (tid < 64) {
            float m16 = -1e30f;
#pragma unroll
            for (int j = 0; j < 16; j++) m16 = fmaxf(m16, red[tid * 17 + j]);
            float mold = mrow[tid];
            float mnew = fmaxf(mold, m16);
            arow[tid] = __expf(mold - mnew);
            mrow[tid] = mnew;
        }
        __syncthreads();

        // P = exp(S - m), store Ps[key][row], accumulate row sums
#pragma unroll
        for (int i = 0; i < 4; i++) {
            int r = ty * 4 + i;
            float mn = mrow[r];
            float ls = 0.f;
#pragma unroll
            for (int j = 0; j < 4; j++) {
                float p = __expf(sacc[i][j] - mn);
                Ps[(tx * 4 + j) * 68 + r] = p;
                ls += p;
            }
            red[r * 17 + tx] = ls;
        }
        __syncthreads();
        if (tid < 64) {
            float s16 = 0.f;
#pragma unroll
            for (int j = 0; j < 16; j++) s16 += red[tid * 17 + j];
            lrow[tid] = lrow[tid] * arow[tid] + s16;
        }

        // O = O * alpha + P @ V
#pragma unroll
        for (int i = 0; i < 4; i++) {
            float al = arow[ty * 4 + i];
            oacc[i][0] *= al; oacc[i][1] *= al; oacc[i][2] *= al; oacc[i][3] *= al;
        }
#pragma unroll 8
        for (int k = 0; k < 64; k++) {
            float4 a = *(const float4*)(Ps + k * 68 + ty * 4);
            float4 c = *(const float4*)(Vs + k * 68 + tx * 4);
            oacc[0][0] += a.x * c.x; oacc[0][1] += a.x * c.y; oacc[0][2] += a.x * c.z; oacc[0][3] += a.x * c.w;
            oacc[1][0] += a.y * c.x; oacc[1][1] += a.y * c.y; oacc[1][2] += a.y * c.z; oacc[1][3] += a.y * c.w;
            oacc[2][0] += a.z * c.x; oacc[2][1] += a.z * c.y; oacc[2][2] += a.z * c.z; oacc[2][3] += a.z * c.w;
            oacc[3][0] += a.w * c.x; oacc[3][1] += a.w * c.y; oacc[3][2] += a.w * c.z; oacc[3][3] += a.w * c.w;
        }
    }
    __syncthreads();

#pragma unroll
    for (int i = 0; i < 4; i++) {
        int q = q0 + ty * 4 + i;
        float inv = 1.f / lrow[ty * 4 + i];
        float4 o;
        o.x = oacc[i][0] * inv; o.y = oacc[i][1] * inv;
        o.z = oacc[i][2] * inv; o.w = oacc[i][3] * inv;
        *(float4*)(out + ((size_t)(b * TT + q)) * EE + h * DD + tx * 4) = o;
    }
}

// ---------------- Per-row NLL ----------------
__global__ void nll_k(const float* __restrict__ logits, const int* __restrict__ tgt,
                      float* __restrict__ nll) {
    int row = blockIdx.x;
    const float* lr = logits + (size_t)row * VV;
    int tid = threadIdx.x;
    __shared__ float sh[256];
    float m = -1e30f;
    for (int i = tid; i < VV; i += 256) m = fmaxf(m, lr[i]);
    sh[tid] = m; __syncthreads();
    for (int o = 128; o; o >>= 1) { if (tid < o) sh[tid] = fmaxf(sh[tid], sh[tid + o]); __syncthreads(); }
    m = sh[0]; __syncthreads();
    float s = 0.f;
    for (int i = tid; i < VV; i += 256) s += __expf(lr[i] - m);
    sh[tid] = s; __syncthreads();
    for (int o = 128; o; o >>= 1) { if (tid < o) sh[tid] += sh[tid + o]; __syncthreads(); }
    if (tid == 0) nll[row] = logf(sh[0]) + m - lr[tgt[row]];
}

__global__ void loss_reduce_k(const float* __restrict__ nll, float* __restrict__ dst, int count) {
    __shared__ float sh[256];
    float s = 0.f;
    for (int i = threadIdx.x; i < MM; i += 256) s += nll[i];
    sh[threadIdx.x] = s; __syncthreads();
    for (int o = 128; o; o >>= 1) { if (threadIdx.x < o) sh[threadIdx.x] += sh[threadIdx.x + o]; __syncthreads(); }
    if (threadIdx.x == 0) {
        float loss = sh[0] * (1.f / (float)MM);
        for (int i = 0; i < count; i++) dst[i] = loss;
    }
}

// ---------------- Launch ----------------
extern "C" void kernel_launch(void* const* d_in, const int* in_sizes, int n_in,
                              void* d_out, int out_size) {
    const int*   idx     = (const int*)  d_in[0];
    const int*   targets = (const int*)  d_in[1];
    const float* wte     = (const float*)d_in[2];
    const float* wpe     = (const float*)d_in[3];
    const float* ln1_g   = (const float*)d_in[4];
    const float* ln1_b   = (const float*)d_in[5];
    const float* qkv_w   = (const float*)d_in[6];
    const float* qkv_b   = (const float*)d_in[7];
    const float* o_w     = (const float*)d_in[8];
    const float* o_b     = (const float*)d_in[9];
    const float* ln2_g   = (const float*)d_in[10];
    const float* ln2_b   = (const float*)d_in[11];
    const float* up_w    = (const float*)d_in[12];
    const float* up_b    = (const float*)d_in[13];
    const float* down_w  = (const float*)d_in[14];
    const float* down_b  = (const float*)d_in[15];
    const float* lnf_g   = (const float*)d_in[16];
    const float* lnf_b   = (const float*)d_in[17];
    const float* lm_b    = (const float*)d_in[18];

    float *h, *x, *qkv, *attn, *mlp, *nll, *logits_scratch;
    cudaGetSymbolAddress((void**)&h,    g_h);
    cudaGetSymbolAddress((void**)&x,    g_x);
    cudaGetSymbolAddress((void**)&qkv,  g_qkv);
    cudaGetSymbolAddress((void**)&attn, g_attn);
    cudaGetSymbolAddress((void**)&mlp,  g_mlp);
    cudaGetSymbolAddress((void**)&nll,  g_nll);
    cudaGetSymbolAddress((void**)&logits_scratch, g_logits);

    static bool attr_set = false;
    if (!attr_set) {
        cudaFuncSetAttribute(flash_attn_k, cudaFuncAttributeMaxDynamicSharedMemorySize, FA_SMEM_BYTES);
        attr_set = true;
    }

    float* logits = ((long long)out_size >= NBTV) ? (float*)d_out : logits_scratch;

    embed_k<<<MM, 256>>>(idx, wte, wpe, h);

    for (int l = 0; l < LL; l++) {
        layernorm_k<<<MM, 256>>>(h, ln1_g + (size_t)l * EE, ln1_b + (size_t)l * EE, x);
        mmagemm_k<false, 0, false><<<dim3(MM / 128, 3 * EE / 128), 256>>>(
            x, qkv_w + (size_t)l * EE * 3 * EE, qkv_b + (size_t)l * 3 * EE, nullptr,
            qkv, MM, 3 * EE, EE);
        flash_attn_k<<<dim3(TT / 64, BB * HH), 256, FA_SMEM_BYTES>>>(qkv, attn);
        mmagemm_k<false, 0, true><<<dim3(MM / 128, EE / 128), 256>>>(
            attn, o_w + (size_t)l * EE * EE, o_b + (size_t)l * EE, h,
            h, MM, EE, EE);
        layernorm_k<<<MM, 256>>>(h, ln2_g + (size_t)l * EE, ln2_b + (size_t)l * EE, x);
        mmagemm_k<false, 1, false><<<dim3(MM / 128, 4 * EE / 128), 256>>>(
            x, up_w + (size_t)l * EE * 4 * EE, up_b + (size_t)l * 4 * EE, nullptr,
            mlp, MM, 4 * EE, EE);
        mmagemm_k<false, 0, true><<<dim3(MM / 128, EE / 128), 256>>>(
            mlp, down_w + (size_t)l * 4 * EE * EE, down_b + (size_t)l * EE, h,
            h, MM, EE, 4 * EE);
    }

    layernorm_k<<<MM, 256>>>(h, lnf_g, lnf_b, x);
    mmagemm_k<true, 0, false><<<dim3(MM / 128, (VV + 127) / 128), 256>>>(
        x, wte, lm_b, nullptr, logits, MM, VV, EE);

    nll_k<<<MM, 256>>>(logits, targets, nll);

    long long extra = (long long)out_size - NBTV;
    if (extra > 0) {
        loss_reduce_k<<<1, 256>>>(nll, (float*)d_out + NBTV, (int)extra);
    } else if ((long long)out_size < NBTV) {
        loss_reduce_k<<<1, 256>>>(nll, (float*)d_out, out_size);
    }
}

// round 5
// speedup vs baseline: 2.9112x; 1.0855x over previous
#include <cuda_runtime.h>
#include <math.h>
#include <stdint.h>

// ---------------- Problem constants ----------------
static constexpr int BB = 2;
static constexpr int TT = 1024;
static constexpr int EE = 1024;
static constexpr int HH = 16;
static constexpr int DD = 64;
static constexpr int LL = 12;
static constexpr int VV = 50257;
static constexpr int MM = BB * TT;
static constexpr long long NBTV = (long long)MM * VV;

// ---------------- Scratch ----------------
__device__ float g_h   [(size_t)MM * EE];
__device__ float g_x   [(size_t)MM * EE];
__device__ float g_qkv [(size_t)MM * 3 * EE];
__device__ float g_attn[(size_t)MM * EE];
__device__ float g_mlp [(size_t)MM * 4 * EE];
__device__ float g_nll [MM];
__device__ float g_logits[(size_t)MM * VV];

// ---------------- Helpers ----------------
__device__ __forceinline__ float tf32r(float x) {
    uint32_t u;
    asm("cvt.rna.tf32.f32 %0, %1;" : "=r"(u) : "f"(x));
    return __uint_as_float(u);
}

__device__ __forceinline__ void mma_tf32(float c[4], const uint32_t a[4], const uint32_t b[2]) {
    asm volatile(
        "mma.sync.aligned.m16n8k8.row.col.f32.tf32.tf32.f32 "
        "{%0,%1,%2,%3}, {%4,%5,%6,%7}, {%8,%9}, {%0,%1,%2,%3};"
        : "+f"(c[0]), "+f"(c[1]), "+f"(c[2]), "+f"(c[3])
        : "r"(a[0]), "r"(a[1]), "r"(a[2]), "r"(a[3]), "r"(b[0]), "r"(b[1]));
}

// ---------------- Embedding ----------------
__global__ void embed_k(const int* __restrict__ idx, const float* __restrict__ wte,
                        const float* __restrict__ wpe, float* __restrict__ h) {
    int bt = blockIdx.x;
    int t  = bt % TT;
    int tok = idx[bt];
    int i = threadIdx.x * 4;
    float4 a = *(const float4*)(wte + (size_t)tok * EE + i);
    float4 p = *(const float4*)(wpe + (size_t)t   * EE + i);
    a.x += p.x; a.y += p.y; a.z += p.z; a.w += p.w;
    *(float4*)(h + (size_t)bt * EE + i) = a;
}

// ---------------- LayerNorm ----------------
__global__ void layernorm_k(const float* __restrict__ xin, const float* __restrict__ g,
                            const float* __restrict__ bb, float* __restrict__ y) {
    __shared__ float rs[8], rq[8];
    int row = blockIdx.x, tid = threadIdx.x;
    const float* xr = xin + (size_t)row * EE;
    float4 v = *(const float4*)(xr + tid * 4);
    float s = v.x + v.y + v.z + v.w;
    float q = v.x * v.x + v.y * v.y + v.z * v.z + v.w * v.w;
#pragma unroll
    for (int o = 16; o; o >>= 1) {
        s += __shfl_xor_sync(0xffffffffu, s, o);
        q += __shfl_xor_sync(0xffffffffu, q, o);
    }
    if ((tid & 31) == 0) { rs[tid >> 5] = s; rq[tid >> 5] = q; }
    __syncthreads();
    if (tid == 0) {
        float S = 0.f, Q = 0.f;
#pragma unroll
        for (int i = 0; i < 8; i++) { S += rs[i]; Q += rq[i]; }
        rs[0] = S; rq[0] = Q;
    }
    __syncthreads();
    float mean = rs[0] * (1.f / EE);
    float var  = rq[0] * (1.f / EE) - mean * mean;
    float rstd = rsqrtf(var + 1e-5f);
    float4 gg = *(const float4*)(g  + tid * 4);
    float4 be = *(const float4*)(bb + tid * 4);
    float4 o;
    o.x = (v.x - mean) * rstd * gg.x + be.x;
    o.y = (v.y - mean) * rstd * gg.y + be.y;
    o.z = (v.z - mean) * rstd * gg.z + be.z;
    o.w = (v.w - mean) * rstd * gg.w + be.w;
    *(float4*)(y + (size_t)row * EE + tid * 4) = o;
}

// ---------------- Tensor-core GEMM (tf32 mma.sync), K-tile 32, 2 CTAs/SM ----------------
// C = act(A@B + bias) [+ Res]
// A: [M,K] row-major. B: [K,N] (TRANSB=false) or [N,K] (TRANSB=true).
// Block tile 128x128x32, 256 threads = 8 warps (2x4), warp tile 64x32.
template<bool TRANSB, int ACT, bool RES>
__global__ __launch_bounds__(256, 2)
void mmagemm_k(const float* __restrict__ A, const float* __restrict__ Bm,
               const float* __restrict__ bias, const float* __restrict__ Res,
               float* __restrict__ C, int M, int N, int K) {
    constexpr int AST = 36;       // As row stride (floats): [128][36]
    constexpr int BST = 136;      // Bs row stride (floats): [32][136]
    __shared__ float As[2][128 * AST];
    __shared__ float Bs[2][32 * BST];

    const int tid  = threadIdx.x;
    const int lane = tid & 31;
    const int wid  = tid >> 5;
    const int wm   = wid >> 2;       // 0..1
    const int wn   = wid & 3;        // 0..3
    const int g    = lane >> 2;      // 0..7
    const int t    = lane & 3;       // 0..3

    const int row0 = blockIdx.x * 128;
    const int col0 = blockIdx.y * 128;

    // A fill: 4 float4 per thread; idx -> row=idx>>3, col4=idx&7
    const int a_row = tid >> 3;          // base rows 0..31, +32 per u
    const int a_c4  = tid & 7;
    // B non-trans fill: idx -> k=idx>>5, n4=idx&31
    const int b_k  = tid >> 5;           // 0..7, +8 per u
    const int b_n4 = tid & 31;
    // B trans fill: idx -> n=idx>>3, k4=idx&7
    const int bt_n  = tid >> 3;          // 0..31, +32 per u
    const int bt_k4 = tid & 7;

    float4 ag[4], bg[4];

    auto ld_global = [&](int k0) {
#pragma unroll
        for (int u = 0; u < 4; u++)
            ag[u] = *(const float4*)(A + (size_t)(row0 + a_row + 32 * u) * K + k0 + a_c4 * 4);
        if (!TRANSB) {
#pragma unroll
            for (int u = 0; u < 4; u++)
                bg[u] = *(const float4*)(Bm + (size_t)(k0 + b_k + 8 * u) * N + col0 + b_n4 * 4);
        } else {
#pragma unroll
            for (int u = 0; u < 4; u++) {
                int n = col0 + bt_n + 32 * u;
                bg[u] = (n < N) ? *(const float4*)(Bm + (size_t)n * K + k0 + bt_k4 * 4)
                                : make_float4(0.f, 0.f, 0.f, 0.f);
            }
        }
    };

    auto st_smem = [&](int buf) {
#pragma unroll
        for (int u = 0; u < 4; u++) {
            float* ap = &As[buf][(a_row + 32 * u) * AST + a_c4 * 4];
            ap[0] = tf32r(ag[u].x); ap[1] = tf32r(ag[u].y);
            ap[2] = tf32r(ag[u].z); ap[3] = tf32r(ag[u].w);
        }
        if (!TRANSB) {
#pragma unroll
            for (int u = 0; u < 4; u++) {
                float* bp = &Bs[buf][(b_k + 8 * u) * BST + b_n4 * 4];
                bp[0] = tf32r(bg[u].x); bp[1] = tf32r(bg[u].y);
                bp[2] = tf32r(bg[u].z); bp[3] = tf32r(bg[u].w);
            }
        } else {
#pragma unroll
            for (int u = 0; u < 4; u++) {
                int n = bt_n + 32 * u;
                Bs[buf][(bt_k4 * 4 + 0) * BST + n] = tf32r(bg[u].x);
                Bs[buf][(bt_k4 * 4 + 1) * BST + n] = tf32r(bg[u].y);
                Bs[buf][(bt_k4 * 4 + 2) * BST + n] = tf32r(bg[u].z);
                Bs[buf][(bt_k4 * 4 + 3) * BST + n] = tf32r(bg[u].w);
            }
        }
    };

    float acc[4][4][4] = {};

    const int nIters = K >> 5;
    int buf = 0;
    ld_global(0);
    st_smem(0);
    __syncthreads();

    for (int it = 0; it < nIters; ++it) {
        if (it + 1 < nIters) ld_global((it + 1) << 5);

        const float* Ab = As[buf];
        const float* Bb = Bs[buf];
#pragma unroll
        for (int ks = 0; ks < 4; ks++) {
            uint32_t afr[4][4];
            uint32_t bfr[4][2];
#pragma unroll
            for (int mt = 0; mt < 4; mt++) {
                int r = wm * 64 + mt * 16 + g;
                int kk = ks * 8 + t;
                afr[mt][0] = __float_as_uint(Ab[(r)     * AST + kk]);
                afr[mt][1] = __float_as_uint(Ab[(r + 8) * AST + kk]);
                afr[mt][2] = __float_as_uint(Ab[(r)     * AST + kk + 4]);
                afr[mt][3] = __float_as_uint(Ab[(r + 8) * AST + kk + 4]);
            }
#pragma unroll
            for (int nt = 0; nt < 4; nt++) {
                int c = wn * 32 + nt * 8 + g;
                bfr[nt][0] = __float_as_uint(Bb[(ks * 8 + t)     * BST + c]);
                bfr[nt][1] = __float_as_uint(Bb[(ks * 8 + t + 4) * BST + c]);
            }
#pragma unroll
            for (int mt = 0; mt < 4; mt++)
#pragma unroll
                for (int nt = 0; nt < 4; nt++)
                    mma_tf32(acc[mt][nt], afr[mt], bfr[nt]);
        }

        if (it + 1 < nIters) {
            st_smem(buf ^ 1);
            __syncthreads();
            buf ^= 1;
        }
    }

    // ---- epilogue ----
#pragma unroll
    for (int mt = 0; mt < 4; mt++) {
        int r0 = row0 + wm * 64 + mt * 16 + g;
#pragma unroll
        for (int nt = 0; nt < 4; nt++) {
            int c = col0 + wn * 32 + nt * 8 + t * 2;
#pragma unroll
            for (int half = 0; half < 2; half++) {
                int r = r0 + half * 8;
                float v0 = acc[mt][nt][half * 2 + 0];
                float v1 = acc[mt][nt][half * 2 + 1];
                if (!TRANSB) {
                    v0 += bias[c]; v1 += bias[c + 1];
                    if (ACT == 1) {
                        v0 = 0.5f * v0 * (1.f + erff(v0 * 0.70710678118654752f));
                        v1 = 0.5f * v1 * (1.f + erff(v1 * 0.70710678118654752f));
                    }
                    if (RES) {
                        v0 += Res[(size_t)r * N + c];
                        v1 += Res[(size_t)r * N + c + 1];
                    }
                    *(float2*)(C + (size_t)r * N + c) = make_float2(v0, v1);
                } else {
                    if (c < N)     C[(size_t)r * N + c]     = v0 + bias[c];
                    if (c + 1 < N) C[(size_t)r * N + c + 1] = v1 + bias[c + 1];
                }
            }
        }
    }
}

// ---------------- Fused FP32 flash attention ----------------
static constexpr int FA_Q  = 0;
static constexpr int FA_K  = 64 * 68;
static constexpr int FA_V  = 2 * 64 * 68;
static constexpr int FA_P  = 3 * 64 * 68;
static constexpr int FA_R  = 4 * 64 * 68;
static constexpr int FA_M  = FA_R + 64 * 17;
static constexpr int FA_L  = FA_M + 64;
static constexpr int FA_A  = FA_L + 64;
static constexpr int FA_FLOATS = FA_A + 64;
static constexpr int FA_SMEM_BYTES = FA_FLOATS * 4;

__global__ __launch_bounds__(256)
void flash_attn_k(const float* __restrict__ qkv, float* __restrict__ out) {
    extern __shared__ float sm[];
    float* Qs   = sm + FA_Q;
    float* Ks   = sm + FA_K;
    float* Vs   = sm + FA_V;
    float* Ps   = sm + FA_P;
    float* red  = sm + FA_R;
    float* mrow = sm + FA_M;
    float* lrow = sm + FA_L;
    float* arow = sm + FA_A;

    const int tid = threadIdx.x;
    const int tx = tid & 15, ty = tid >> 4;
    const int qi = gridDim.x - 1 - blockIdx.x;
    const int q0 = qi * 64;
    const int bh = blockIdx.y;
    const int b = bh / HH, h = bh % HH;

    const float* base = qkv + (size_t)b * TT * 3 * EE + h * DD;

    {
        int r = tid >> 2;
        int c = tid & 3;
        const float* qp = base + (size_t)(q0 + r) * 3 * EE;
#pragma unroll
        for (int u = 0; u < 4; u++) {
            int d = (c + 4 * u) * 4;
            float4 v = *(const float4*)(qp + d);
            Qs[(d + 0) * 68 + r] = v.x;
            Qs[(d + 1) * 68 + r] = v.y;
            Qs[(d + 2) * 68 + r] = v.z;
            Qs[(d + 3) * 68 + r] = v.w;
        }
    }
    if (tid < 64) { mrow[tid] = -1e30f; lrow[tid] = 0.f; }

    float oacc[4][4] = {};
    const int nch = qi + 1;

    for (int ch = 0; ch < nch; ch++) {
        const int kt = ch * 64;
        __syncthreads();
        {
            int r = tid >> 2;
            int c = tid & 3;
            const float* kp = base + (size_t)(kt + r) * 3 * EE + EE;
            const float* vp = base + (size_t)(kt + r) * 3 * EE + 2 * EE;
#pragma unroll
            for (int u = 0; u < 4; u++) {
                int d = (c + 4 * u) * 4;
                float4 kv = *(const float4*)(kp + d);
                Ks[(d + 0) * 68 + r] = kv.x;
                Ks[(d + 1) * 68 + r] = kv.y;
                Ks[(d + 2) * 68 + r] = kv.z;
                Ks[(d + 3) * 68 + r] = kv.w;
                float4 vv = *(const float4*)(vp + d);
                *(float4*)(Vs + r * 68 + d) = vv;
            }
        }
        __syncthreads();

        float sacc[4][4] = {};
#pragma unroll 8
        for (int d = 0; d < 64; d++) {
            float4 a = *(const float4*)(Qs + d * 68 + ty * 4);
            float4 c = *(const float4*)(Ks + d * 68 + tx * 4);
            sacc[0][0] += a.x * c.x; sacc[0][1] += a.x * c.y; sacc[0][2] += a.x * c.z; sacc[0][3] += a.x * c.w;
            sacc[1][0] += a.y * c.x; sacc[1][1] += a.y * c.y; sacc[1][2] += a.y * c.z; sacc[1][3] += a.y * c.w;
            sacc[2][0] += a.z * c.x; sacc[2][1] += a.z * c.y; sacc[2][2] += a.z * c.z; sacc[2][3] += a.z * c.w;
            sacc[3][0] += a.w * c.x; sacc[3][1] += a.w * c.y; sacc[3][2] += a.w * c.z; sacc[3][3] += a.w * c.w;
        }
        const bool diag = (kt == q0);
#pragma unroll
        for (int i = 0; i < 4; i++) {
            int q = q0 + ty * 4 + i;
            float lm = -1e30f;
#pragma unroll
            for (int j = 0; j < 4; j++) {
                float s = sacc[i][j] * 0.125f;
                if (diag && (kt + tx * 4 + j > q)) s = -1e30f;
                sacc[i][j] = s;
                lm = fmaxf(lm, s);
            }
            red[(ty * 4 + i) * 17 + tx] = lm;
        }
        __syncthreads();
        if (tid < 64) {
            float m16 = -1e30f;
#pragma unroll
            for (int j = 0; j < 16; j++) m16 = fmaxf(m16, red[tid * 17 + j]);
            float mold = mrow[tid];
            float mnew = fmaxf(mold, m16);
            arow[tid] = __expf(mold - mnew);
            mrow[tid] = mnew;
        }
        __syncthreads();

#pragma unroll
        for (int i = 0; i < 4; i++) {
            int r = ty * 4 + i;
            float mn = mrow[r];
            float ls = 0.f;
#pragma unroll
            for (int j = 0; j < 4; j++) {
                float p = __expf(sacc[i][j] - mn);
                Ps[(tx * 4 + j) * 68 + r] = p;
                ls += p;
            }
            red[r * 17 + tx] = ls;
        }
        __syncthreads();
        if (tid < 64) {
            float s16 = 0.f;
#pragma unroll
            for (int j = 0; j < 16; j++) s16 += red[tid * 17 + j];
            lrow[tid] = lrow[tid] * arow[tid] + s16;
        }

#pragma unroll
        for (int i = 0; i < 4; i++) {
            float al = arow[ty * 4 + i];
            oacc[i][0] *= al; oacc[i][1] *= al; oacc[i][2] *= al; oacc[i][3] *= al;
        }
#pragma unroll 8
        for (int k = 0; k < 64; k++) {
            float4 a = *(const float4*)(Ps + k * 68 + ty * 4);
            float4 c = *(const float4*)(Vs + k * 68 + tx * 4);
            oacc[0][0] += a.x * c.x; oacc[0][1] += a.x * c.y; oacc[0][2] += a.x * c.z; oacc[0][3] += a.x * c.w;
            oacc[1][0] += a.y * c.x; oacc[1][1] += a.y * c.y; oacc[1][2] += a.y * c.z; oacc[1][3] += a.y * c.w;
            oacc[2][0] += a.z * c.x; oacc[2][1] += a.z * c.y; oacc[2][2] += a.z * c.z; oacc[2][3] += a.z * c.w;
            oacc[3][0] += a.w * c.x; oacc[3][1] += a.w * c.y; oacc[3][2] += a.w * c.z; oacc[3][3] += a.w * c.w;
        }
    }
    __syncthreads();

#pragma unroll
    for (int i = 0; i < 4; i++) {
        int q = q0 + ty * 4 + i;
        float inv = 1.f / lrow[ty * 4 + i];
        float4 o;
        o.x = oacc[i][0] * inv; o.y = oacc[i][1] * inv;
        o.z = oacc[i][2] * inv; o.w = oacc[i][3] * inv;
        *(float4*)(out + ((size_t)(b * TT + q)) * EE + h * DD + tx * 4) = o;
    }
}

// ---------------- Per-row NLL ----------------
__global__ void nll_k(const float* __restrict__ logits, const int* __restrict__ tgt,
                      float* __restrict__ nll) {
    int row = blockIdx.x;
    const float* lr = logits + (size_t)row * VV;
    int tid = threadIdx.x;
    __shared__ float sh[256];
    float m = -1e30f;
    for (int i = tid; i < VV; i += 256) m = fmaxf(m, lr[i]);
    sh[tid] = m; __syncthreads();
    for (int o = 128; o; o >>= 1) { if (tid < o) sh[tid] = fmaxf(sh[tid], sh[tid + o]); __syncthreads(); }
    m = sh[0]; __syncthreads();
    float s = 0.f;
    for (int i = tid; i < VV; i += 256) s += __expf(lr[i] - m);
    sh[tid] = s; __syncthreads();
    for (int o = 128; o; o >>= 1) { if (tid < o) sh[tid] += sh[tid + o]; __syncthreads(); }
    if (tid == 0) nll[row] = logf(sh[0]) + m - lr[tgt[row]];
}

__global__ void loss_reduce_k(const float* __restrict__ nll, float* __restrict__ dst, int count) {
    __shared__ float sh[256];
    float s = 0.f;
    for (int i = threadIdx.x; i < MM; i += 256) s += nll[i];
    sh[threadIdx.x] = s; __syncthreads();
    for (int o = 128; o; o >>= 1) { if (threadIdx.x < o) sh[threadIdx.x] += sh[threadIdx.x + o]; __syncthreads(); }
    if (threadIdx.x == 0) {
        float loss = sh[0] * (1.f / (float)MM);
        for (int i = 0; i < count; i++) dst[i] = loss;
    }
}

// ---------------- Launch ----------------
extern "C" void kernel_launch(void* const* d_in, const int* in_sizes, int n_in,
                              void* d_out, int out_size) {
    const int*   idx     = (const int*)  d_in[0];
    const int*   targets = (const int*)  d_in[1];
    const float* wte     = (const float*)d_in[2];
    const float* wpe     = (const float*)d_in[3];
    const float* ln1_g   = (const float*)d_in[4];
    const float* ln1_b   = (const float*)d_in[5];
    const float* qkv_w   = (const float*)d_in[6];
    const float* qkv_b   = (const float*)d_in[7];
    const float* o_w     = (const float*)d_in[8];
    const float* o_b     = (const float*)d_in[9];
    const float* ln2_g   = (const float*)d_in[10];
    const float* ln2_b   = (const float*)d_in[11];
    const float* up_w    = (const float*)d_in[12];
    const float* up_b    = (const float*)d_in[13];
    const float* down_w  = (const float*)d_in[14];
    const float* down_b  = (const float*)d_in[15];
    const float* lnf_g   = (const float*)d_in[16];
    const float* lnf_b   = (const float*)d_in[17];
    const float* lm_b    = (const float*)d_in[18];

    float *h, *x, *qkv, *attn, *mlp, *nll, *logits_scratch;
    cudaGetSymbolAddress((void**)&h,    g_h);
    cudaGetSymbolAddress((void**)&x,    g_x);
    cudaGetSymbolAddress((void**)&qkv,  g_qkv);
    cudaGetSymbolAddress((void**)&attn, g_attn);
    cudaGetSymbolAddress((void**)&mlp,  g_mlp);
    cudaGetSymbolAddress((void**)&nll,  g_nll);
    cudaGetSymbolAddress((void**)&logits_scratch, g_logits);

    static bool attr_set = false;
    if (!attr_set) {
        cudaFuncSetAttribute(flash_attn_k, cudaFuncAttributeMaxDynamicSharedMemorySize, FA_SMEM_BYTES);
        attr_set = true;
    }

    float* logits = ((long long)out_size >= NBTV) ? (float*)d_out : logits_scratch;

    embed_k<<<MM, 256>>>(idx, wte, wpe, h);

    for (int l = 0; l < LL; l++) {
        layernorm_k<<<MM, 256>>>(h, ln1_g + (size_t)l * EE, ln1_b + (size_t)l * EE, x);
        mmagemm_k<false, 0, false><<<dim3(MM / 128, 3 * EE / 128), 256>>>(
            x, qkv_w + (size_t)l * EE * 3 * EE, qkv_b + (size_t)l * 3 * EE, nullptr,
            qkv, MM, 3 * EE, EE);
        flash_attn_k<<<dim3(TT / 64, BB * HH), 256, FA_SMEM_BYTES>>>(qkv, attn);
        mmagemm_k<false, 0, true><<<dim3(MM / 128, EE / 128), 256>>>(
            attn, o_w + (size_t)l * EE * EE, o_b + (size_t)l * EE, h,
            h, MM, EE, EE);
        layernorm_k<<<MM, 256>>>(h, ln2_g + (size_t)l * EE, ln2_b + (size_t)l * EE, x);
        mmagemm_k<false, 1, false><<<dim3(MM / 128, 4 * EE / 128), 256>>>(
            x, up_w + (size_t)l * EE * 4 * EE, up_b + (size_t)l * 4 * EE, nullptr,
            mlp, MM, 4 * EE, EE);
        mmagemm_k<false, 0, true><<<dim3(MM / 128, EE / 128), 256>>>(
            mlp, down_w + (size_t)l * 4 * EE * EE, down_b + (size_t)l * EE, h,
            h, MM, EE, 4 * EE);
    }

    layernorm_k<<<MM, 256>>>(h, lnf_g, lnf_b, x);
    mmagemm_k<true, 0, false><<<dim3(MM / 128, (VV + 127) / 128), 256>>>(
        x, wte, lm_b, nullptr, logits, MM, VV, EE);

    nll_k<<<MM, 256>>>(logits, targets, nll);

    long long extra = (long long)out_size - NBTV;
    if (extra > 0) {
        loss_reduce_k<<<1, 256>>>(nll, (float*)d_out + NBTV, (int)extra);
    } else if ((long long)out_size < NBTV) {
        loss_reduce_k<<<1, 256>>>(nll, (float*)d_out, out_size);
    }
}

// round 6
// speedup vs baseline: 2.9951x; 1.0288x over previous
#include <cuda_runtime.h>
#include <math.h>
#include <stdint.h>

// ---------------- Problem constants ----------------
static constexpr int BB = 2;
static constexpr int TT = 1024;
static constexpr int EE = 1024;
static constexpr int HH = 16;
static constexpr int DD = 64;
static constexpr int LL = 12;
static constexpr int VV = 50257;
static constexpr int MM = BB * TT;
static constexpr long long NBTV = (long long)MM * VV;
static constexpr int NU = 40;       // split-KV work units per (b,h)

// ---------------- Scratch ----------------
__device__ float g_h   [(size_t)MM * EE];
__device__ float g_x   [(size_t)MM * EE];
__device__ float g_qkv [(size_t)MM * 3 * EE];
__device__ float g_attn[(size_t)MM * EE];
__device__ float g_mlp [(size_t)MM * 4 * EE];
__device__ float g_nll [MM];
__device__ float g_logits[(size_t)MM * VV];
// split-KV partials: [bh][unit][row 64][d 64], and per-row m/l
__device__ float g_pO[(size_t)BB * HH * NU * 64 * 64];
__device__ float g_pm[(size_t)BB * HH * NU * 64];
__device__ float g_pl[(size_t)BB * HH * NU * 64];

// unit -> (q-tile, split) mapping; units ordered big-first
__constant__ int c_qi[NU] = {15,15,15,15, 14,14,14,14, 13,13,13,13, 12,12,12,12,
                             11,11,11, 10,10,10, 9,9,9, 8,8,8, 7,7, 6,6, 5,5, 4,4,
                             3, 2, 1, 0};
__constant__ int c_sp[NU] = {0,1,2,3, 0,1,2,3, 0,1,2,3, 0,1,2,3,
                             0,1,2, 0,1,2, 0,1,2, 0,1,2, 0,1, 0,1, 0,1, 0,1,
                             0, 0, 0, 0};
// q-tile -> first unit / num splits
__constant__ int c_u0[16] = {39,38,37,36, 34,32,30,28, 25,22,19,16, 12,8,4,0};
__constant__ int c_ns[16] = {1,1,1,1, 2,2,2,2, 3,3,3,3, 4,4,4,4};

// ---------------- Helpers ----------------
__device__ __forceinline__ float tf32r(float x) {
    uint32_t u;
    asm("cvt.rna.tf32.f32 %0, %1;" : "=r"(u) : "f"(x));
    return __uint_as_float(u);
}

__device__ __forceinline__ void mma_tf32(float c[4], const uint32_t a[4], const uint32_t b[2]) {
    asm volatile(
        "mma.sync.aligned.m16n8k8.row.col.f32.tf32.tf32.f32 "
        "{%0,%1,%2,%3}, {%4,%5,%6,%7}, {%8,%9}, {%0,%1,%2,%3};"
        : "+f"(c[0]), "+f"(c[1]), "+f"(c[2]), "+f"(c[3])
        : "r"(a[0]), "r"(a[1]), "r"(a[2]), "r"(a[3]), "r"(b[0]), "r"(b[1]));
}

// ---------------- Embedding ----------------
__global__ void embed_k(const int* __restrict__ idx, const float* __restrict__ wte,
                        const float* __restrict__ wpe, float* __restrict__ h) {
    int bt = blockIdx.x;
    int t  = bt % TT;
    int tok = idx[bt];
    int i = threadIdx.x * 4;
    float4 a = *(const float4*)(wte + (size_t)tok * EE + i);
    float4 p = *(const float4*)(wpe + (size_t)t   * EE + i);
    a.x += p.x; a.y += p.y; a.z += p.z; a.w += p.w;
    *(float4*)(h + (size_t)bt * EE + i) = a;
}

// ---------------- LayerNorm ----------------
__global__ void layernorm_k(const float* __restrict__ xin, const float* __restrict__ g,
                            const float* __restrict__ bb, float* __restrict__ y) {
    __shared__ float rs[8], rq[8];
    int row = blockIdx.x, tid = threadIdx.x;
    const float* xr = xin + (size_t)row * EE;
    float4 v = *(const float4*)(xr + tid * 4);
    float s = v.x + v.y + v.z + v.w;
    float q = v.x * v.x + v.y * v.y + v.z * v.z + v.w * v.w;
#pragma unroll
    for (int o = 16; o; o >>= 1) {
        s += __shfl_xor_sync(0xffffffffu, s, o);
        q += __shfl_xor_sync(0xffffffffu, q, o);
    }
    if ((tid & 31) == 0) { rs[tid >> 5] = s; rq[tid >> 5] = q; }
    __syncthreads();
    if (tid == 0) {
        float S = 0.f, Q = 0.f;
#pragma unroll
        for (int i = 0; i < 8; i++) { S += rs[i]; Q += rq[i]; }
        rs[0] = S; rq[0] = Q;
    }
    __syncthreads();
    float mean = rs[0] * (1.f / EE);
    float var  = rq[0] * (1.f / EE) - mean * mean;
    float rstd = rsqrtf(var + 1e-5f);
    float4 gg = *(const float4*)(g  + tid * 4);
    float4 be = *(const float4*)(bb + tid * 4);
    float4 o;
    o.x = (v.x - mean) * rstd * gg.x + be.x;
    o.y = (v.y - mean) * rstd * gg.y + be.y;
    o.z = (v.z - mean) * rstd * gg.z + be.z;
    o.w = (v.w - mean) * rstd * gg.w + be.w;
    *(float4*)(y + (size_t)row * EE + tid * 4) = o;
}

// ---------------- Tensor-core GEMM (tf32 mma.sync), K-tile 32, 2 CTAs/SM ----------------
template<bool TRANSB, int ACT, bool RES>
__global__ __launch_bounds__(256, 2)
void mmagemm_k(const float* __restrict__ A, const float* __restrict__ Bm,
               const float* __restrict__ bias, const float* __restrict__ Res,
               float* __restrict__ C, int M, int N, int K) {
    constexpr int AST = 36;
    constexpr int BST = 136;
    __shared__ float As[2][128 * AST];
    __shared__ float Bs[2][32 * BST];

    const int tid  = threadIdx.x;
    const int lane = tid & 31;
    const int wid  = tid >> 5;
    const int wm   = wid >> 2;
    const int wn   = wid & 3;
    const int g    = lane >> 2;
    const int t    = lane & 3;

    const int row0 = blockIdx.x * 128;
    const int col0 = blockIdx.y * 128;

    const int a_row = tid >> 3;
    const int a_c4  = tid & 7;
    const int b_k  = tid >> 5;
    const int b_n4 = tid & 31;
    const int bt_n  = tid >> 3;
    const int bt_k4 = tid & 7;

    float4 ag[4], bg[4];

    auto ld_global = [&](int k0) {
#pragma unroll
        for (int u = 0; u < 4; u++)
            ag[u] = *(const float4*)(A + (size_t)(row0 + a_row + 32 * u) * K + k0 + a_c4 * 4);
        if (!TRANSB) {
#pragma unroll
            for (int u = 0; u < 4; u++)
                bg[u] = *(const float4*)(Bm + (size_t)(k0 + b_k + 8 * u) * N + col0 + b_n4 * 4);
        } else {
#pragma unroll
            for (int u = 0; u < 4; u++) {
                int n = col0 + bt_n + 32 * u;
                bg[u] = (n < N) ? *(const float4*)(Bm + (size_t)n * K + k0 + bt_k4 * 4)
                                : make_float4(0.f, 0.f, 0.f, 0.f);
            }
        }
    };

    auto st_smem = [&](int buf) {
#pragma unroll
        for (int u = 0; u < 4; u++) {
            float* ap = &As[buf][(a_row + 32 * u) * AST + a_c4 * 4];
            ap[0] = tf32r(ag[u].x); ap[1] = tf32r(ag[u].y);
            ap[2] = tf32r(ag[u].z); ap[3] = tf32r(ag[u].w);
        }
        if (!TRANSB) {
#pragma unroll
            for (int u = 0; u < 4; u++) {
                float* bp = &Bs[buf][(b_k + 8 * u) * BST + b_n4 * 4];
                bp[0] = tf32r(bg[u].x); bp[1] = tf32r(bg[u].y);
                bp[2] = tf32r(bg[u].z); bp[3] = tf32r(bg[u].w);
            }
        } else {
#pragma unroll
            for (int u = 0; u < 4; u++) {
                int n = bt_n + 32 * u;
                Bs[buf][(bt_k4 * 4 + 0) * BST + n] = tf32r(bg[u].x);
                Bs[buf][(bt_k4 * 4 + 1) * BST + n] = tf32r(bg[u].y);
                Bs[buf][(bt_k4 * 4 + 2) * BST + n] = tf32r(bg[u].z);
                Bs[buf][(bt_k4 * 4 + 3) * BST + n] = tf32r(bg[u].w);
            }
        }
    };

    float acc[4][4][4] = {};

    const int nIters = K >> 5;
    int buf = 0;
    ld_global(0);
    st_smem(0);
    __syncthreads();

    for (int it = 0; it < nIters; ++it) {
        if (it + 1 < nIters) ld_global((it + 1) << 5);

        const float* Ab = As[buf];
        const float* Bb = Bs[buf];
#pragma unroll
        for (int ks = 0; ks < 4; ks++) {
            uint32_t afr[4][4];
            uint32_t bfr[4][2];
#pragma unroll
            for (int mt = 0; mt < 4; mt++) {
                int r = wm * 64 + mt * 16 + g;
                int kk = ks * 8 + t;
                afr[mt][0] = __float_as_uint(Ab[(r)     * AST + kk]);
                afr[mt][1] = __float_as_uint(Ab[(r + 8) * AST + kk]);
                afr[mt][2] = __float_as_uint(Ab[(r)     * AST + kk + 4]);
                afr[mt][3] = __float_as_uint(Ab[(r + 8) * AST + kk + 4]);
            }
#pragma unroll
            for (int nt = 0; nt < 4; nt++) {
                int c = wn * 32 + nt * 8 + g;
                bfr[nt][0] = __float_as_uint(Bb[(ks * 8 + t)     * BST + c]);
                bfr[nt][1] = __float_as_uint(Bb[(ks * 8 + t + 4) * BST + c]);
            }
#pragma unroll
            for (int mt = 0; mt < 4; mt++)
#pragma unroll
                for (int nt = 0; nt < 4; nt++)
                    mma_tf32(acc[mt][nt], afr[mt], bfr[nt]);
        }

        if (it + 1 < nIters) {
            st_smem(buf ^ 1);
            __syncthreads();
            buf ^= 1;
        }
    }

#pragma unroll
    for (int mt = 0; mt < 4; mt++) {
        int r0 = row0 + wm * 64 + mt * 16 + g;
#pragma unroll
        for (int nt = 0; nt < 4; nt++) {
            int c = col0 + wn * 32 + nt * 8 + t * 2;
#pragma unroll
            for (int half = 0; half < 2; half++) {
                int r = r0 + half * 8;
                float v0 = acc[mt][nt][half * 2 + 0];
                float v1 = acc[mt][nt][half * 2 + 1];
                if (!TRANSB) {
                    v0 += bias[c]; v1 += bias[c + 1];
                    if (ACT == 1) {
                        v0 = 0.5f * v0 * (1.f + erff(v0 * 0.70710678118654752f));
                        v1 = 0.5f * v1 * (1.f + erff(v1 * 0.70710678118654752f));
                    }
                    if (RES) {
                        v0 += Res[(size_t)r * N + c];
                        v1 += Res[(size_t)r * N + c + 1];
                    }
                    *(float2*)(C + (size_t)r * N + c) = make_float2(v0, v1);
                } else {
                    if (c < N)     C[(size_t)r * N + c]     = v0 + bias[c];
                    if (c + 1 < N) C[(size_t)r * N + c + 1] = v1 + bias[c + 1];
                }
            }
        }
    }
}

// ---------------- Split-KV fused FP32 flash attention ----------------
// One block per (work unit, b*h). Unit = (q-tile, key-split of <=4 chunks).
// Writes unnormalized O + per-row (m, l) partials; fa_combine_k merges.
static constexpr int FA_Q  = 0;
static constexpr int FA_K  = 64 * 68;
static constexpr int FA_V  = 2 * 64 * 68;
static constexpr int FA_P  = 3 * 64 * 68;
static constexpr int FA_R  = 4 * 64 * 68;
static constexpr int FA_M  = FA_R + 64 * 17;
static constexpr int FA_L  = FA_M + 64;
static constexpr int FA_A  = FA_L + 64;
static constexpr int FA_FLOATS = FA_A + 64;
static constexpr int FA_SMEM_BYTES = FA_FLOATS * 4;

__global__ __launch_bounds__(256)
void flash_attn_k(const float* __restrict__ qkv, float* __restrict__ pO,
                  float* __restrict__ pm, float* __restrict__ pl) {
    extern __shared__ float sm[];
    float* Qs   = sm + FA_Q;
    float* Ks   = sm + FA_K;
    float* Vs   = sm + FA_V;
    float* Ps   = sm + FA_P;
    float* red  = sm + FA_R;
    float* mrow = sm + FA_M;
    float* lrow = sm + FA_L;
    float* arow = sm + FA_A;

    const int tid = threadIdx.x;
    const int tx = tid & 15, ty = tid >> 4;
    const int u  = blockIdx.x;           // 0..NU-1, big units first
    const int bh = blockIdx.y;
    const int qi = c_qi[u];
    const int sp = c_sp[u];
    const int q0 = qi * 64;
    const int b = bh / HH, h = bh % HH;

    const float* base = qkv + (size_t)b * TT * 3 * EE + h * DD;

    // load Q tile transposed: Qs[d][row]
    {
        int r = tid >> 2;
        int c = tid & 3;
        const float* qp = base + (size_t)(q0 + r) * 3 * EE;
#pragma unroll
        for (int uu = 0; uu < 4; uu++) {
            int d = (c + 4 * uu) * 4;
            float4 v = *(const float4*)(qp + d);
            Qs[(d + 0) * 68 + r] = v.x;
            Qs[(d + 1) * 68 + r] = v.y;
            Qs[(d + 2) * 68 + r] = v.z;
            Qs[(d + 3) * 68 + r] = v.w;
        }
    }
    if (tid < 64) { mrow[tid] = -1e30f; lrow[tid] = 0.f; }

    float oacc[4][4] = {};
    const int c0 = sp * 4;
    const int c1 = min(c0 + 4, qi + 1);

    for (int ch = c0; ch < c1; ch++) {
        const int kt = ch * 64;
        __syncthreads();
        {
            int r = tid >> 2;
            int c = tid & 3;
            const float* kp = base + (size_t)(kt + r) * 3 * EE + EE;
            const float* vp = base + (size_t)(kt + r) * 3 * EE + 2 * EE;
#pragma unroll
            for (int uu = 0; uu < 4; uu++) {
                int d = (c + 4 * uu) * 4;
                float4 kv = *(const float4*)(kp + d);
                Ks[(d + 0) * 68 + r] = kv.x;
                Ks[(d + 1) * 68 + r] = kv.y;
                Ks[(d + 2) * 68 + r] = kv.z;
                Ks[(d + 3) * 68 + r] = kv.w;
                float4 vv = *(const float4*)(vp + d);
                *(float4*)(Vs + r * 68 + d) = vv;
            }
        }
        __syncthreads();

        float sacc[4][4] = {};
#pragma unroll 8
        for (int d = 0; d < 64; d++) {
            float4 a = *(const float4*)(Qs + d * 68 + ty * 4);
            float4 c = *(const float4*)(Ks + d * 68 + tx * 4);
            sacc[0][0] += a.x * c.x; sacc[0][1] += a.x * c.y; sacc[0][2] += a.x * c.z; sacc[0][3] += a.x * c.w;
            sacc[1][0] += a.y * c.x; sacc[1][1] += a.y * c.y; sacc[1][2] += a.y * c.z; sacc[1][3] += a.y * c.w;
            sacc[2][0] += a.z * c.x; sacc[2][1] += a.z * c.y; sacc[2][2] += a.z * c.z; sacc[2][3] += a.z * c.w;
            sacc[3][0] += a.w * c.x; sacc[3][1] += a.w * c.y; sacc[3][2] += a.w * c.z; sacc[3][3] += a.w * c.w;
        }
        const bool diag = (ch == qi);
#pragma unroll
        for (int i = 0; i < 4; i++) {
            int q = q0 + ty * 4 + i;
            float lm = -1e30f;
#pragma unroll
            for (int j = 0; j < 4; j++) {
                float s = sacc[i][j] * 0.125f;
                if (diag && (kt + tx * 4 + j > q)) s = -1e30f;
                sacc[i][j] = s;
                lm = fmaxf(lm, s);
            }
            red[(ty * 4 + i) * 17 + tx] = lm;
        }
        __syncthreads();
        if (tid < 64) {
            float m16 = -1e30f;
#pragma unroll
            for (int j = 0; j < 16; j++) m16 = fmaxf(m16, red[tid * 17 + j]);
            float mold = mrow[tid];
            float mnew = fmaxf(mold, m16);
            arow[tid] = __expf(mold - mnew);
            mrow[tid] = mnew;
        }
        __syncthreads();

#pragma unroll
        for (int i = 0; i < 4; i++) {
            int r = ty * 4 + i;
            float mn = mrow[r];
            float ls = 0.f;
#pragma unroll
            for (int j = 0; j < 4; j++) {
                float p = __expf(sacc[i][j] - mn);
                Ps[(tx * 4 + j) * 68 + r] = p;
                ls += p;
            }
            red[r * 17 + tx] = ls;
        }
        __syncthreads();
        if (tid < 64) {
            float s16 = 0.f;
#pragma unroll
            for (int j = 0; j < 16; j++) s16 += red[tid * 17 + j];
            lrow[tid] = lrow[tid] * arow[tid] + s16;
        }

#pragma unroll
        for (int i = 0; i < 4; i++) {
            float al = arow[ty * 4 + i];
            oacc[i][0] *= al; oacc[i][1] *= al; oacc[i][2] *= al; oacc[i][3] *= al;
        }
#pragma unroll 8
        for (int k = 0; k < 64; k++) {
            float4 a = *(const float4*)(Ps + k * 68 + ty * 4);
            float4 c = *(const float4*)(Vs + k * 68 + tx * 4);
            oacc[0][0] += a.x * c.x; oacc[0][1] += a.x * c.y; oacc[0][2] += a.x * c.z; oacc[0][3] += a.x * c.w;
            oacc[1][0] += a.y * c.x; oacc[1][1] += a.y * c.y; oacc[1][2] += a.y * c.z; oacc[1][3] += a.y * c.w;
            oacc[2][0] += a.z * c.x; oacc[2][1] += a.z * c.y; oacc[2][2] += a.z * c.z; oacc[2][3] += a.z * c.w;
            oacc[3][0] += a.w * c.x; oacc[3][1] += a.w * c.y; oacc[3][2] += a.w * c.z; oacc[3][3] += a.w * c.w;
        }
    }
    __syncthreads();

    // store unnormalized partials
    float* po = pO + ((size_t)(bh * NU + u) * 64) * 64;
#pragma unroll
    for (int i = 0; i < 4; i++) {
        int r = ty * 4 + i;
        *(float4*)(po + r * 64 + tx * 4) =
            make_float4(oacc[i][0], oacc[i][1], oacc[i][2], oacc[i][3]);
    }
    if (tid < 64) {
        pm[(size_t)(bh * NU + u) * 64 + tid] = mrow[tid];
        pl[(size_t)(bh * NU + u) * 64 + tid] = lrow[tid];
    }
}

// Combine split partials: out = sum_s w_s * O_s / sum_s w_s * l_s, w_s = exp(m_s - M)
__global__ __launch_bounds__(256)
void fa_combine_k(const float* __restrict__ pO, const float* __restrict__ pm,
                  const float* __restrict__ pl, float* __restrict__ out) {
    const int qi = blockIdx.x;
    const int bh = blockIdx.y;
    const int b = bh / HH, h = bh % HH;
    const int ns = c_ns[qi];
    const int u0 = c_u0[qi];
    const int tid = threadIdx.x;
    const int r4 = tid >> 6;        // 0..3
    const int d  = tid & 63;
    for (int p = 0; p < 16; p++) {
        int row = p * 4 + r4;
        float M = -1e30f;
        for (int s = 0; s < ns; s++)
            M = fmaxf(M, pm[(size_t)(bh * NU + u0 + s) * 64 + row]);
        float L = 0.f, O = 0.f;
        for (int s = 0; s < ns; s++) {
            size_t ub = (size_t)(bh * NU + u0 + s);
            float w = __expf(pm[ub * 64 + row] - M);
            L += w * pl[ub * 64 + row];
            O += w * pO[(ub * 64 + row) * 64 + d];
        }
        out[((size_t)(b * TT + qi * 64 + row)) * EE + h * DD + d] = O / L;
    }
}

// ---------------- Per-row NLL ----------------
__global__ void nll_k(const float* __restrict__ logits, const int* __restrict__ tgt,
                      float* __restrict__ nll) {
    int row = blockIdx.x;
    const float* lr = logits + (size_t)row * VV;
    int tid = threadIdx.x;
    __shared__ float sh[256];
    float m = -1e30f;
    for (int i = tid; i < VV; i += 256) m = fmaxf(m, lr[i]);
    sh[tid] = m; __syncthreads();
    for (int o = 128; o; o >>= 1) { if (tid < o) sh[tid] = fmaxf(sh[tid], sh[tid + o]); __syncthreads(); }
    m = sh[0]; __syncthreads();
    float s = 0.f;
    for (int i = tid; i < VV; i += 256) s += __expf(lr[i] - m);
    sh[tid] = s; __syncthreads();
    for (int o = 128; o; o >>= 1) { if (tid < o) sh[tid] += sh[tid + o]; __syncthreads(); }
    if (tid == 0) nll[row] = logf(sh[0]) + m - lr[tgt[row]];
}

__global__ void loss_reduce_k(const float* __restrict__ nll, float* __restrict__ dst, int count) {
    __shared__ float sh[256];
    float s = 0.f;
    for (int i = threadIdx.x; i < MM; i += 256) s += nll[i];
    sh[threadIdx.x] = s; __syncthreads();
    for (int o = 128; o; o >>= 1) { if (threadIdx.x < o) sh[threadIdx.x] += sh[threadIdx.x + o]; __syncthreads(); }
    if (threadIdx.x == 0) {
        float loss = sh[0] * (1.f / (float)MM);
        for (int i = 0; i < count; i++) dst[i] = loss;
    }
}

// ---------------- Launch ----------------
extern "C" void kernel_launch(void* const* d_in, const int* in_sizes, int n_in,
                              void* d_out, int out_size) {
    const int*   idx     = (const int*)  d_in[0];
    const int*   targets = (const int*)  d_in[1];
    const float* wte     = (const float*)d_in[2];
    const float* wpe     = (const float*)d_in[3];
    const float* ln1_g   = (const float*)d_in[4];
    const float* ln1_b   = (const float*)d_in[5];
    const float* qkv_w   = (const float*)d_in[6];
    const float* qkv_b   = (const float*)d_in[7];
    const float* o_w     = (const float*)d_in[8];
    const float* o_b     = (const float*)d_in[9];
    const float* ln2_g   = (const float*)d_in[10];
    const float* ln2_b   = (const float*)d_in[11];
    const float* up_w    = (const float*)d_in[12];
    const float* up_b    = (const float*)d_in[13];
    const float* down_w  = (const float*)d_in[14];
    const float* down_b  = (const float*)d_in[15];
    const float* lnf_g   = (const float*)d_in[16];
    const float* lnf_b   = (const float*)d_in[17];
    const float* lm_b    = (const float*)d_in[18];

    float *h, *x, *qkv, *attn, *mlp, *nll, *logits_scratch, *pO, *pm, *pl;
    cudaGetSymbolAddress((void**)&h,    g_h);
    cudaGetSymbolAddress((void**)&x,    g_x);
    cudaGetSymbolAddress((void**)&qkv,  g_qkv);
    cudaGetSymbolAddress((void**)&attn, g_attn);
    cudaGetSymbolAddress((void**)&mlp,  g_mlp);
    cudaGetSymbolAddress((void**)&nll,  g_nll);
    cudaGetSymbolAddress((void**)&logits_scratch, g_logits);
    cudaGetSymbolAddress((void**)&pO,   g_pO);
    cudaGetSymbolAddress((void**)&pm,   g_pm);
    cudaGetSymbolAddress((void**)&pl,   g_pl);

    static bool attr_set = false;
    if (!attr_set) {
        cudaFuncSetAttribute(flash_attn_k, cudaFuncAttributeMaxDynamicSharedMemorySize, FA_SMEM_BYTES);
        attr_set = true;
    }

    float* logits = ((long long)out_size >= NBTV) ? (float*)d_out : logits_scratch;

    embed_k<<<MM, 256>>>(idx, wte, wpe, h);

    for (int l = 0; l < LL; l++) {
        layernorm_k<<<MM, 256>>>(h, ln1_g + (size_t)l * EE, ln1_b + (size_t)l * EE, x);
        mmagemm_k<false, 0, false><<<dim3(MM / 128, 3 * EE / 128), 256>>>(
            x, qkv_w + (size_t)l * EE * 3 * EE, qkv_b + (size_t)l * 3 * EE, nullptr,
            qkv, MM, 3 * EE, EE);
        flash_attn_k<<<dim3(NU, BB * HH), 256, FA_SMEM_BYTES>>>(qkv, pO, pm, pl);
        fa_combine_k<<<dim3(TT / 64, BB * HH), 256>>>(pO, pm, pl, attn);
        mmagemm_k<false, 0, true><<<dim3(MM / 128, EE / 128), 256>>>(
            attn, o_w + (size_t)l * EE * EE, o_b + (size_t)l * EE, h,
            h, MM, EE, EE);
        layernorm_k<<<MM, 256>>>(h, ln2_g + (size_t)l * EE, ln2_b + (size_t)l * EE, x);
        mmagemm_k<false, 1, false><<<dim3(MM / 128, 4 * EE / 128), 256>>>(
            x, up_w + (size_t)l * EE * 4 * EE, up_b + (size_t)l * 4 * EE, nullptr,
            mlp, MM, 4 * EE, EE);
        mmagemm_k<false, 0, true><<<dim3(MM / 128, EE / 128), 256>>>(
            mlp, down_w + (size_t)l * 4 * EE * EE, down_b + (size_t)l * EE, h,
            h, MM, EE, 4 * EE);
    }

    layernorm_k<<<MM, 256>>>(h, lnf_g, lnf_b, x);
    mmagemm_k<true, 0, false><<<dim3(MM / 128, (VV + 127) / 128), 256>>>(
        x, wte, lm_b, nullptr, logits, MM, VV, EE);

    nll_k<<<MM, 256>>>(logits, targets, nll);

    long long extra = (long long)out_size - NBTV;
    if (extra > 0) {
        loss_reduce_k<<<1, 256>>>(nll, (float*)d_out + NBTV, (int)extra);
    } else if ((long long)out_size < NBTV) {
        loss_reduce_k<<<1, 256>>>(nll, (float*)d_out, out_size);
    }
}

// round 7
// speedup vs baseline: 3.4265x; 1.1440x over previous
#include <cuda_runtime.h>
#include <math.h>
#include <stdint.h>

// ---------------- Problem constants ----------------
static constexpr int BB = 2;
static constexpr int TT = 1024;
static constexpr int EE = 1024;
static constexpr int HH = 16;
static constexpr int DD = 64;
static constexpr int LL = 12;
static constexpr int VV = 50257;
static constexpr int MM = BB * TT;
static constexpr long long NBTV = (long long)MM * VV;
static constexpr int NU = 40;       // split-KV work units per (b,h)

// ---------------- Scratch ----------------
__device__ float g_h   [(size_t)MM * EE];
__device__ float g_x   [(size_t)MM * EE];
__device__ float g_qkv [(size_t)MM * 3 * EE];
__device__ float g_attn[(size_t)MM * EE];
__device__ float g_mlp [(size_t)MM * 4 * EE];
__device__ float g_nll [MM];
__device__ float g_logits[(size_t)MM * VV];
// split-KV partials
__device__ float g_pO[(size_t)BB * HH * NU * 64 * 64];
__device__ float g_pm[(size_t)BB * HH * NU * 64];
__device__ float g_pl[(size_t)BB * HH * NU * 64];
// tf32-pre-rounded weights
__device__ float g_qkvR [(size_t)LL * EE * 3 * EE];
__device__ float g_oR   [(size_t)LL * EE * EE];
__device__ float g_upR  [(size_t)LL * EE * 4 * EE];
__device__ float g_downR[(size_t)LL * 4 * EE * EE];
__device__ float g_wteR [(size_t)VV * EE];

// unit -> (q-tile, split) mapping; units ordered big-first
__constant__ int c_qi[NU] = {15,15,15,15, 14,14,14,14, 13,13,13,13, 12,12,12,12,
                             11,11,11, 10,10,10, 9,9,9, 8,8,8, 7,7, 6,6, 5,5, 4,4,
                             3, 2, 1, 0};
__constant__ int c_sp[NU] = {0,1,2,3, 0,1,2,3, 0,1,2,3, 0,1,2,3,
                             0,1,2, 0,1,2, 0,1,2, 0,1,2, 0,1, 0,1, 0,1, 0,1,
                             0, 0, 0, 0};
__constant__ int c_u0[16] = {39,38,37,36, 34,32,30,28, 25,22,19,16, 12,8,4,0};
__constant__ int c_ns[16] = {1,1,1,1, 2,2,2,2, 3,3,3,3, 4,4,4,4};

// ---------------- Helpers ----------------
__device__ __forceinline__ float tf32r(float x) {
    uint32_t u;
    asm("cvt.rna.tf32.f32 %0, %1;" : "=r"(u) : "f"(x));
    return __uint_as_float(u);
}

__device__ __forceinline__ uint32_t smem_u32(const void* p) {
    uint32_t r;
    asm("{ .reg .u64 t; cvta.to.shared.u64 t, %1; cvt.u32.u64 %0, t; }" : "=r"(r) : "l"(p));
    return r;
}

__device__ __forceinline__ void mma_tf32(float c[4], const uint32_t a[4], const uint32_t b[2]) {
    asm volatile(
        "mma.sync.aligned.m16n8k8.row.col.f32.tf32.tf32.f32 "
        "{%0,%1,%2,%3}, {%4,%5,%6,%7}, {%8,%9}, {%0,%1,%2,%3};"
        : "+f"(c[0]), "+f"(c[1]), "+f"(c[2]), "+f"(c[3])
        : "r"(a[0]), "r"(a[1]), "r"(a[2]), "r"(a[3]), "r"(b[0]), "r"(b[1]));
}

// ---------------- tf32 rounding copy (weights, once per launch) ----------------
__global__ void roundcpy_k(const float* __restrict__ src, float* __restrict__ dst, int n4) {
    int i = blockIdx.x * 256 + threadIdx.x;
    if (i < n4) {
        float4 v = *(const float4*)(src + (size_t)i * 4);
        v.x = tf32r(v.x); v.y = tf32r(v.y); v.z = tf32r(v.z); v.w = tf32r(v.w);
        *(float4*)(dst + (size_t)i * 4) = v;
    }
}

// ---------------- Embedding ----------------
__global__ void embed_k(const int* __restrict__ idx, const float* __restrict__ wte,
                        const float* __restrict__ wpe, float* __restrict__ h) {
    int bt = blockIdx.x;
    int t  = bt % TT;
    int tok = idx[bt];
    int i = threadIdx.x * 4;
    float4 a = *(const float4*)(wte + (size_t)tok * EE + i);
    float4 p = *(const float4*)(wpe + (size_t)t   * EE + i);
    a.x += p.x; a.y += p.y; a.z += p.z; a.w += p.w;
    *(float4*)(h + (size_t)bt * EE + i) = a;
}

// ---------------- LayerNorm (output tf32-rounded: feeds GEMM A only) ----------------
__global__ void layernorm_k(const float* __restrict__ xin, const float* __restrict__ g,
                            const float* __restrict__ bb, float* __restrict__ y) {
    __shared__ float rs[8], rq[8];
    int row = blockIdx.x, tid = threadIdx.x;
    const float* xr = xin + (size_t)row * EE;
    float4 v = *(const float4*)(xr + tid * 4);
    float s = v.x + v.y + v.z + v.w;
    float q = v.x * v.x + v.y * v.y + v.z * v.z + v.w * v.w;
#pragma unroll
    for (int o = 16; o; o >>= 1) {
        s += __shfl_xor_sync(0xffffffffu, s, o);
        q += __shfl_xor_sync(0xffffffffu, q, o);
    }
    if ((tid & 31) == 0) { rs[tid >> 5] = s; rq[tid >> 5] = q; }
    __syncthreads();
    if (tid == 0) {
        float S = 0.f, Q = 0.f;
#pragma unroll
        for (int i = 0; i < 8; i++) { S += rs[i]; Q += rq[i]; }
        rs[0] = S; rq[0] = Q;
    }
    __syncthreads();
    float mean = rs[0] * (1.f / EE);
    float var  = rq[0] * (1.f / EE) - mean * mean;
    float rstd = rsqrtf(var + 1e-5f);
    float4 gg = *(const float4*)(g  + tid * 4);
    float4 be = *(const float4*)(bb + tid * 4);
    float4 o;
    o.x = tf32r((v.x - mean) * rstd * gg.x + be.x);
    o.y = tf32r((v.y - mean) * rstd * gg.y + be.y);
    o.z = tf32r((v.z - mean) * rstd * gg.z + be.z);
    o.w = tf32r((v.w - mean) * rstd * gg.w + be.w);
    *(float4*)(y + (size_t)row * EE + tid * 4) = o;
}

// ---------------- cp.async 3-stage tf32 GEMM ----------------
// C = act(A@B + bias) [+ Res]; operands pre-rounded to tf32.
// A: [M,K] row-major. B: [K,N] (TRANSB=false) or [N,K] (TRANSB=true).
// 128x128x32 tile, 256 threads, 8 warps (2x4), warp 64x32.
static constexpr int G_AST = 36;
static constexpr int G_ASZ = 128 * G_AST;        // floats per A stage
static constexpr int G_BSZ_N = 32 * 136;         // B stage floats, normal [k][n]
static constexpr int G_BSZ_T = 128 * 36;         // B stage floats, transb [n][k]
static constexpr int NSMEM = 3 * (G_ASZ + G_BSZ_N) * 4;   // 107520
static constexpr int TSMEM = 3 * (G_ASZ + G_BSZ_T) * 4;   // 110592

template<bool TRANSB, int ACT, bool RES, bool ROUND_OUT>
__global__ __launch_bounds__(256, 2)
void cpgemm_k(const float* __restrict__ A, const float* __restrict__ Bw,
              const float* __restrict__ bias, const float* __restrict__ Res,
              float* __restrict__ C, int M, int N, int K) {
    extern __shared__ float smf[];
    constexpr int BST = TRANSB ? 36 : 136;
    constexpr int BSZ = TRANSB ? G_BSZ_T : G_BSZ_N;
    constexpr int STG = G_ASZ + BSZ;                 // floats per stage

    const uint32_t sb = smem_u32(smf);
    const int tid  = threadIdx.x;
    const int lane = tid & 31;
    const int wid  = tid >> 5;
    const int wm   = wid >> 2;
    const int wn   = wid & 3;
    const int g    = lane >> 2;
    const int t    = lane & 3;

    const int row0 = blockIdx.x * 128;
    const int col0 = blockIdx.y * 128;
    const int iters = K >> 5;

    auto issue_stage = [&](int it) {
        const int k0 = it << 5;
        const int s = it % 3;
        const uint32_t stA = sb + (uint32_t)(s * STG) * 4;
        const uint32_t stB = stA + (uint32_t)G_ASZ * 4;
#pragma unroll
        for (int u = 0; u < 4; u++) {
            int ca = u * 256 + tid;
            int r = ca >> 3, c16 = ca & 7;
            const float* gs = A + (size_t)(row0 + r) * K + k0 + c16 * 4;
            uint32_t sd = stA + (uint32_t)(r * G_AST + c16 * 4) * 4;
            asm volatile("cp.async.cg.shared.global [%0], [%1], 16;" :: "r"(sd), "l"(gs));
        }
        if (!TRANSB) {
#pragma unroll
            for (int u = 0; u < 4; u++) {
                int cb = u * 256 + tid;
                int k = cb >> 5, c16 = cb & 31;
                const float* gs = Bw + (size_t)(k0 + k) * N + col0 + c16 * 4;
                uint32_t sd = stB + (uint32_t)(k * BST + c16 * 4) * 4;
                asm volatile("cp.async.cg.shared.global [%0], [%1], 16;" :: "r"(sd), "l"(gs));
            }
        } else {
#pragma unroll
            for (int u = 0; u < 4; u++) {
                int cb = u * 256 + tid;
                int n = cb >> 3, c16 = cb & 7;
                const float* gs = Bw + (size_t)(col0 + n) * K + k0 + c16 * 4;
                uint32_t sd = stB + (uint32_t)(n * BST + c16 * 4) * 4;
                int sz = (col0 + n < N) ? 16 : 0;
                asm volatile("cp.async.cg.shared.global [%0], [%1], 16, %2;"
                             :: "r"(sd), "l"(gs), "r"(sz));
            }
        }
        asm volatile("cp.async.commit_group;" ::: "memory");
    };

    float acc[4][4][4] = {};

    issue_stage(0);
    issue_stage(1);

    for (int it = 0; it < iters; ++it) {
        if (it == iters - 1) {
            asm volatile("cp.async.wait_group 0;" ::: "memory");
        } else {
            asm volatile("cp.async.wait_group 1;" ::: "memory");
        }
        __syncthreads();
        if (it + 2 < iters) issue_stage(it + 2);

        const float* Ab = smf + (it % 3) * STG;
        const float* Bb = Ab + G_ASZ;
#pragma unroll
        for (int ks = 0; ks < 4; ks++) {
            uint32_t afr[4][4];
            uint32_t bfr[4][2];
            const int kk = ks * 8 + t;
#pragma unroll
            for (int mt = 0; mt < 4; mt++) {
                int r = wm * 64 + mt * 16 + g;
                afr[mt][0] = __float_as_uint(Ab[(r)     * G_AST + kk]);
                afr[mt][1] = __float_as_uint(Ab[(r + 8) * G_AST + kk]);
                afr[mt][2] = __float_as_uint(Ab[(r)     * G_AST + kk + 4]);
                afr[mt][3] = __float_as_uint(Ab[(r + 8) * G_AST + kk + 4]);
            }
#pragma unroll
            for (int nt = 0; nt < 4; nt++) {
                int c = wn * 32 + nt * 8 + g;
                if (!TRANSB) {
                    bfr[nt][0] = __float_as_uint(Bb[(kk)     * BST + c]);
                    bfr[nt][1] = __float_as_uint(Bb[(kk + 4) * BST + c]);
                } else {
                    bfr[nt][0] = __float_as_uint(Bb[c * BST + kk]);
                    bfr[nt][1] = __float_as_uint(Bb[c * BST + kk + 4]);
                }
            }
#pragma unroll
            for (int mt = 0; mt < 4; mt++)
#pragma unroll
                for (int nt = 0; nt < 4; nt++)
                    mma_tf32(acc[mt][nt], afr[mt], bfr[nt]);
        }
        __syncthreads();
    }

    // ---- epilogue ----
#pragma unroll
    for (int mt = 0; mt < 4; mt++) {
        int r0 = row0 + wm * 64 + mt * 16 + g;
#pragma unroll
        for (int nt = 0; nt < 4; nt++) {
            int c = col0 + wn * 32 + nt * 8 + t * 2;
#pragma unroll
            for (int half = 0; half < 2; half++) {
                int r = r0 + half * 8;
                float v0 = acc[mt][nt][half * 2 + 0];
                float v1 = acc[mt][nt][half * 2 + 1];
                if (!TRANSB) {
                    v0 += bias[c]; v1 += bias[c + 1];
                    if (ACT == 1) {
                        v0 = 0.5f * v0 * (1.f + erff(v0 * 0.70710678118654752f));
                        v1 = 0.5f * v1 * (1.f + erff(v1 * 0.70710678118654752f));
                    }
                    if (RES) {
                        v0 += Res[(size_t)r * N + c];
                        v1 += Res[(size_t)r * N + c + 1];
                    }
                    if (ROUND_OUT) { v0 = tf32r(v0); v1 = tf32r(v1); }
                    *(float2*)(C + (size_t)r * N + c) = make_float2(v0, v1);
                } else {
                    if (c < N)     C[(size_t)r * N + c]     = v0 + bias[c];
                    if (c + 1 < N) C[(size_t)r * N + c + 1] = v1 + bias[c + 1];
                }
            }
        }
    }
}

// ---------------- Split-KV fused FP32 flash attention ----------------
static constexpr int FA_Q  = 0;
static constexpr int FA_K  = 64 * 68;
static constexpr int FA_V  = 2 * 64 * 68;
static constexpr int FA_P  = 3 * 64 * 68;
static constexpr int FA_R  = 4 * 64 * 68;
static constexpr int FA_M  = FA_R + 64 * 17;
static constexpr int FA_L  = FA_M + 64;
static constexpr int FA_A  = FA_L + 64;
static constexpr int FA_FLOATS = FA_A + 64;
static constexpr int FA_SMEM_BYTES = FA_FLOATS * 4;

__global__ __launch_bounds__(256)
void flash_attn_k(const float* __restrict__ qkv, float* __restrict__ pO,
                  float* __restrict__ pm, float* __restrict__ pl) {
    extern __shared__ float sm[];
    float* Qs   = sm + FA_Q;
    float* Ks   = sm + FA_K;
    float* Vs   = sm + FA_V;
    float* Ps   = sm + FA_P;
    float* red  = sm + FA_R;
    float* mrow = sm + FA_M;
    float* lrow = sm + FA_L;
    float* arow = sm + FA_A;

    const int tid = threadIdx.x;
    const int tx = tid & 15, ty = tid >> 4;
    const int u  = blockIdx.x;
    const int bh = blockIdx.y;
    const int qi = c_qi[u];
    const int sp = c_sp[u];
    const int q0 = qi * 64;
    const int b = bh / HH, h = bh % HH;

    const float* base = qkv + (size_t)b * TT * 3 * EE + h * DD;

    {
        int r = tid >> 2;
        int c = tid & 3;
        const float* qp = base + (size_t)(q0 + r) * 3 * EE;
#pragma unroll
        for (int uu = 0; uu < 4; uu++) {
            int d = (c + 4 * uu) * 4;
            float4 v = *(const float4*)(qp + d);
            Qs[(d + 0) * 68 + r] = v.x;
            Qs[(d + 1) * 68 + r] = v.y;
            Qs[(d + 2) * 68 + r] = v.z;
            Qs[(d + 3) * 68 + r] = v.w;
        }
    }
    if (tid < 64) { mrow[tid] = -1e30f; lrow[tid] = 0.f; }

    float oacc[4][4] = {};
    const int c0 = sp * 4;
    const int c1 = min(c0 + 4, qi + 1);

    for (int ch = c0; ch < c1; ch++) {
        const int kt = ch * 64;
        __syncthreads();
        {
            int r = tid >> 2;
            int c = tid & 3;
            const float* kp = base + (size_t)(kt + r) * 3 * EE + EE;
            const float* vp = base + (size_t)(kt + r) * 3 * EE + 2 * EE;
#pragma unroll
            for (int uu = 0; uu < 4; uu++) {
                int d = (c + 4 * uu) * 4;
                float4 kv = *(const float4*)(kp + d);
                Ks[(d + 0) * 68 + r] = kv.x;
                Ks[(d + 1) * 68 + r] = kv.y;
                Ks[(d + 2) * 68 + r] = kv.z;
                Ks[(d + 3) * 68 + r] = kv.w;
                float4 vv = *(const float4*)(vp + d);
                *(float4*)(Vs + r * 68 + d) = vv;
            }
        }
        __syncthreads();

        float sacc[4][4] = {};
#pragma unroll 8
        for (int d = 0; d < 64; d++) {
            float4 a = *(const float4*)(Qs + d * 68 + ty * 4);
            float4 c = *(const float4*)(Ks + d * 68 + tx * 4);
            sacc[0][0] += a.x * c.x; sacc[0][1] += a.x * c.y; sacc[0][2] += a.x * c.z; sacc[0][3] += a.x * c.w;
            sacc[1][0] += a.y * c.x; sacc[1][1] += a.y * c.y; sacc[1][2] += a.y * c.z; sacc[1][3] += a.y * c.w;
            sacc[2][0] += a.z * c.x; sacc[2][1] += a.z * c.y; sacc[2][2] += a.z * c.z; sacc[2][3] += a.z * c.w;
            sacc[3][0] += a.w * c.x; sacc[3][1] += a.w * c.y; sacc[3][2] += a.w * c.z; sacc[3][3] += a.w * c.w;
        }
        const bool diag = (ch == qi);
#pragma unroll
        for (int i = 0; i < 4; i++) {
            int q = q0 + ty * 4 + i;
            float lm = -1e30f;
#pragma unroll
            for (int j = 0; j < 4; j++) {
                float s = sacc[i][j] * 0.125f;
                if (diag && (kt + tx * 4 + j > q)) s = -1e30f;
                sacc[i][j] = s;
                lm = fmaxf(lm, s);
            }
            red[(ty * 4 + i) * 17 + tx] = lm;
        }
        __syncthreads();
        if (tid < 64) {
            float m16 = -1e30f;
#pragma unroll
            for (int j = 0; j < 16; j++) m16 = fmaxf(m16, red[tid * 17 + j]);
            float mold = mrow[tid];
            float mnew = fmaxf(mold, m16);
            arow[tid] = __expf(mold - mnew);
            mrow[tid] = mnew;
        }
        __syncthreads();

#pragma unroll
        for (int i = 0; i < 4; i++) {
            int r = ty * 4 + i;
            float mn = mrow[r];
            float ls = 0.f;
#pragma unroll
            for (int j = 0; j < 4; j++) {
                float p = __expf(sacc[i][j] - mn);
                Ps[(tx * 4 + j) * 68 + r] = p;
                ls += p;
            }
            red[r * 17 + tx] = ls;
        }
        __syncthreads();
        if (tid < 64) {
            float s16 = 0.f;
#pragma unroll
            for (int j = 0; j < 16; j++) s16 += red[tid * 17 + j];
            lrow[tid] = lrow[tid] * arow[tid] + s16;
        }

#pragma unroll
        for (int i = 0; i < 4; i++) {
            float al = arow[ty * 4 + i];
            oacc[i][0] *= al; oacc[i][1] *= al; oacc[i][2] *= al; oacc[i][3] *= al;
        }
#pragma unroll 8
        for (int k = 0; k < 64; k++) {
            float4 a = *(const float4*)(Ps + k * 68 + ty * 4);
            float4 c = *(const float4*)(Vs + k * 68 + tx * 4);
            oacc[0][0] += a.x * c.x; oacc[0][1] += a.x * c.y; oacc[0][2] += a.x * c.z; oacc[0][3] += a.x * c.w;
            oacc[1][0] += a.y * c.x; oacc[1][1] += a.y * c.y; oacc[1][2] += a.y * c.z; oacc[1][3] += a.y * c.w;
            oacc[2][0] += a.z * c.x; oacc[2][1] += a.z * c.y; oacc[2][2] += a.z * c.z; oacc[2][3] += a.z * c.w;
            oacc[3][0] += a.w * c.x; oacc[3][1] += a.w * c.y; oacc[3][2] += a.w * c.z; oacc[3][3] += a.w * c.w;
        }
    }
    __syncthreads();

    float* po = pO + ((size_t)(bh * NU + u) * 64) * 64;
#pragma unroll
    for (int i = 0; i < 4; i++) {
        int r = ty * 4 + i;
        *(float4*)(po + r * 64 + tx * 4) =
            make_float4(oacc[i][0], oacc[i][1], oacc[i][2], oacc[i][3]);
    }
    if (tid < 64) {
        pm[(size_t)(bh * NU + u) * 64 + tid] = mrow[tid];
        pl[(size_t)(bh * NU + u) * 64 + tid] = lrow[tid];
    }
}

// Combine split partials; output tf32-rounded (feeds o-proj GEMM A)
__global__ __launch_bounds__(256)
void fa_combine_k(const float* __restrict__ pO, const float* __restrict__ pm,
                  const float* __restrict__ pl, float* __restrict__ out) {
    const int qi = blockIdx.x;
    const int bh = blockIdx.y;
    const int b = bh / HH, h = bh % HH;
    const int ns = c_ns[qi];
    const int u0 = c_u0[qi];
    const int tid = threadIdx.x;
    const int r4 = tid >> 6;
    const int d  = tid & 63;
    for (int p = 0; p < 16; p++) {
        int row = p * 4 + r4;
        float M = -1e30f;
        for (int s = 0; s < ns; s++)
            M = fmaxf(M, pm[(size_t)(bh * NU + u0 + s) * 64 + row]);
        float L = 0.f, O = 0.f;
        for (int s = 0; s < ns; s++) {
            size_t ub = (size_t)(bh * NU + u0 + s);
            float w = __expf(pm[ub * 64 + row] - M);
            L += w * pl[ub * 64 + row];
            O += w * pO[(ub * 64 + row) * 64 + d];
        }
        out[((size_t)(b * TT + qi * 64 + row)) * EE + h * DD + d] = tf32r(O / L);
    }
}

// ---------------- Per-row NLL ----------------
__global__ void nll_k(const float* __restrict__ logits, const int* __restrict__ tgt,
                      float* __restrict__ nll) {
    int row = blockIdx.x;
    const float* lr = logits + (size_t)row * VV;
    int tid = threadIdx.x;
    __shared__ float sh[256];
    float m = -1e30f;
    for (int i = tid; i < VV; i += 256) m = fmaxf(m, lr[i]);
    sh[tid] = m; __syncthreads();
    for (int o = 128; o; o >>= 1) { if (tid < o) sh[tid] = fmaxf(sh[tid], sh[tid + o]); __syncthreads(); }
    m = sh[0]; __syncthreads();
    float s = 0.f;
    for (int i = tid; i < VV; i += 256) s += __expf(lr[i] - m);
    sh[tid] = s; __syncthreads();
    for (int o = 128; o; o >>= 1) { if (tid < o) sh[tid] += sh[tid + o]; __syncthreads(); }
    if (tid == 0) nll[row] = logf(sh[0]) + m - lr[tgt[row]];
}

__global__ void loss_reduce_k(const float* __restrict__ nll, float* __restrict__ dst, int count) {
    __shared__ float sh[256];
    float s = 0.f;
    for (int i = threadIdx.x; i < MM; i += 256) s += nll[i];
    sh[threadIdx.x] = s; __syncthreads();
    for (int o = 128; o; o >>= 1) { if (threadIdx.x < o) sh[threadIdx.x] += sh[threadIdx.x + o]; __syncthreads(); }
    if (threadIdx.x == 0) {
        float loss = sh[0] * (1.f / (float)MM);
        for (int i = 0; i < count; i++) dst[i] = loss;
    }
}

// ---------------- Launch ----------------
extern "C" void kernel_launch(void* const* d_in, const int* in_sizes, int n_in,
                              void* d_out, int out_size) {
    const int*   idx     = (const int*)  d_in[0];
    const int*   targets = (const int*)  d_in[1];
    const float* wte     = (const float*)d_in[2];
    const float* wpe     = (const float*)d_in[3];
    const float* ln1_g   = (const float*)d_in[4];
    const float* ln1_b   = (const float*)d_in[5];
    const float* qkv_w   = (const float*)d_in[6];
    const float* qkv_b   = (const float*)d_in[7];
    const float* o_w     = (const float*)d_in[8];
    const float* o_b     = (const float*)d_in[9];
    const float* ln2_g   = (const float*)d_in[10];
    const float* ln2_b   = (const float*)d_in[11];
    const float* up_w    = (const float*)d_in[12];
    const float* up_b    = (const float*)d_in[13];
    const float* down_w  = (const float*)d_in[14];
    const float* down_b  = (const float*)d_in[15];
    const float* lnf_g   = (const float*)d_in[16];
    const float* lnf_b   = (const float*)d_in[17];
    const float* lm_b    = (const float*)d_in[18];

    float *h, *x, *qkv, *attn, *mlp, *nll, *logits_scratch, *pO, *pm, *pl;
    float *qkvR, *oR, *upR, *downR, *wteR;
    cudaGetSymbolAddress((void**)&h,    g_h);
    cudaGetSymbolAddress((void**)&x,    g_x);
    cudaGetSymbolAddress((void**)&qkv,  g_qkv);
    cudaGetSymbolAddress((void**)&attn, g_attn);
    cudaGetSymbolAddress((void**)&mlp,  g_mlp);
    cudaGetSymbolAddress((void**)&nll,  g_nll);
    cudaGetSymbolAddress((void**)&logits_scratch, g_logits);
    cudaGetSymbolAddress((void**)&pO,   g_pO);
    cudaGetSymbolAddress((void**)&pm,   g_pm);
    cudaGetSymbolAddress((void**)&pl,   g_pl);
    cudaGetSymbolAddress((void**)&qkvR,  g_qkvR);
    cudaGetSymbolAddress((void**)&oR,    g_oR);
    cudaGetSymbolAddress((void**)&upR,   g_upR);
    cudaGetSymbolAddress((void**)&downR, g_downR);
    cudaGetSymbolAddress((void**)&wteR,  g_wteR);

    static bool attr_set = false;
    if (!attr_set) {
        cudaFuncSetAttribute(flash_attn_k, cudaFuncAttributeMaxDynamicSharedMemorySize, FA_SMEM_BYTES);
        cudaFuncSetAttribute(cpgemm_k<false, 0, false, false>, cudaFuncAttributeMaxDynamicSharedMemorySize, NSMEM);
        cudaFuncSetAttribute(cpgemm_k<false, 0, true,  false>, cudaFuncAttributeMaxDynamicSharedMemorySize, NSMEM);
        cudaFuncSetAttribute(cpgemm_k<false, 1, false, true >, cudaFuncAttributeMaxDynamicSharedMemorySize, NSMEM);
        cudaFuncSetAttribute(cpgemm_k<true,  0, false, false>, cudaFuncAttributeMaxDynamicSharedMemorySize, TSMEM);
        attr_set = true;
    }

    float* logits = ((long long)out_size >= NBTV) ? (float*)d_out : logits_scratch;

    // one-time (per replay) tf32 pre-rounding of weights
    {
        int n;
        n = LL * EE * 3 * EE / 4;  roundcpy_k<<<(n + 255) / 256, 256>>>(qkv_w, qkvR, n);
        n = LL * EE * EE / 4;      roundcpy_k<<<(n + 255) / 256, 256>>>(o_w, oR, n);
        n = LL * EE * 4 * EE / 4;  roundcpy_k<<<(n + 255) / 256, 256>>>(up_w, upR, n);
        n = LL * 4 * EE * EE / 4;  roundcpy_k<<<(n + 255) / 256, 256>>>(down_w, downR, n);
        n = VV * EE / 4;           roundcpy_k<<<(n + 255) / 256, 256>>>(wte, wteR, n);
    }

    embed_k<<<MM, 256>>>(idx, wte, wpe, h);

    for (int l = 0; l < LL; l++) {
        layernorm_k<<<MM, 256>>>(h, ln1_g + (size_t)l * EE, ln1_b + (size_t)l * EE, x);
        cpgemm_k<false, 0, false, false><<<dim3(MM / 128, 3 * EE / 128), 256, NSMEM>>>(
            x, qkvR + (size_t)l * EE * 3 * EE, qkv_b + (size_t)l * 3 * EE, nullptr,
            qkv, MM, 3 * EE, EE);
        flash_attn_k<<<dim3(NU, BB * HH), 256, FA_SMEM_BYTES>>>(qkv, pO, pm, pl);
        fa_combine_k<<<dim3(TT / 64, BB * HH), 256>>>(pO, pm, pl, attn);
        cpgemm_k<false, 0, true, false><<<dim3(MM / 128, EE / 128), 256, NSMEM>>>(
            attn, oR + (size_t)l * EE * EE, o_b + (size_t)l * EE, h,
            h, MM, EE, EE);
        layernorm_k<<<MM, 256>>>(h, ln2_g + (size_t)l * EE, ln2_b + (size_t)l * EE, x);
        cpgemm_k<false, 1, false, true><<<dim3(MM / 128, 4 * EE / 128), 256, NSMEM>>>(
            x, upR + (size_t)l * EE * 4 * EE, up_b + (size_t)l * 4 * EE, nullptr,
            mlp, MM, 4 * EE, EE);
        cpgemm_k<false, 0, true, false><<<dim3(MM / 128, EE / 128), 256, NSMEM>>>(
            mlp, downR + (size_t)l * 4 * EE * EE, down_b + (size_t)l * EE, h,
            h, MM, EE, 4 * EE);
    }

    layernorm_k<<<MM, 256>>>(h, lnf_g, lnf_b, x);
    cpgemm_k<true, 0, false, false><<<dim3(MM / 128, (VV + 127) / 128), 256, TSMEM>>>(
        x, wteR, lm_b, nullptr, logits, MM, VV, EE);

    nll_k<<<MM, 256>>>(logits, targets, nll);

    long long extra = (long long)out_size - NBTV;
    if (extra > 0) {
        loss_reduce_k<<<1, 256>>>(nll, (float*)d_out + NBTV, (int)extra);
    } else if ((long long)out_size < NBTV) {
        loss_reduce_k<<<1, 256>>>(nll, (float*)d_out, out_size);
    }
}

// round 8
// speedup vs baseline: 3.4613x; 1.0101x over previous
#include <cuda_runtime.h>
#include <math.h>
#include <stdint.h>

// ---------------- Problem constants ----------------
static constexpr int BB = 2;
static constexpr int TT = 1024;
static constexpr int EE = 1024;
static constexpr int HH = 16;
static constexpr int DD = 64;
static constexpr int LL = 12;
static constexpr int VV = 50257;
static constexpr int MM = BB * TT;
static constexpr long long NBTV = (long long)MM * VV;
static constexpr int NU = 40;

// ---------------- Scratch ----------------
__device__ float g_h   [(size_t)MM * EE];
__device__ float g_x   [(size_t)MM * EE];
__device__ float g_qkv [(size_t)MM * 3 * EE];
__device__ float g_attn[(size_t)MM * EE];
__device__ float g_mlp [(size_t)MM * 4 * EE];
__device__ float g_nll [MM];
__device__ float g_logits[(size_t)MM * VV];
__device__ float g_pO[(size_t)BB * HH * NU * 64 * 64];
__device__ float g_pm[(size_t)BB * HH * NU * 64];
__device__ float g_pl[(size_t)BB * HH * NU * 64];
__device__ float g_qkvR [(size_t)LL * EE * 3 * EE];
__device__ float g_oR   [(size_t)LL * EE * EE];
__device__ float g_upR  [(size_t)LL * EE * 4 * EE];
__device__ float g_downR[(size_t)LL * 4 * EE * EE];
__device__ float g_wteR [(size_t)VV * EE];

__constant__ int c_qi[NU] = {15,15,15,15, 14,14,14,14, 13,13,13,13, 12,12,12,12,
                             11,11,11, 10,10,10, 9,9,9, 8,8,8, 7,7, 6,6, 5,5, 4,4,
                             3, 2, 1, 0};
__constant__ int c_sp[NU] = {0,1,2,3, 0,1,2,3, 0,1,2,3, 0,1,2,3,
                             0,1,2, 0,1,2, 0,1,2, 0,1,2, 0,1, 0,1, 0,1, 0,1,
                             0, 0, 0, 0};
__constant__ int c_u0[16] = {39,38,37,36, 34,32,30,28, 25,22,19,16, 12,8,4,0};
__constant__ int c_ns[16] = {1,1,1,1, 2,2,2,2, 3,3,3,3, 4,4,4,4};

// ---------------- Helpers ----------------
__device__ __forceinline__ float tf32r(float x) {
    uint32_t u;
    asm("cvt.rna.tf32.f32 %0, %1;" : "=r"(u) : "f"(x));
    return __uint_as_float(u);
}

__device__ __forceinline__ uint32_t smem_u32(const void* p) {
    uint32_t r;
    asm("{ .reg .u64 t; cvta.to.shared.u64 t, %1; cvt.u32.u64 %0, t; }" : "=r"(r) : "l"(p));
    return r;
}

__device__ __forceinline__ void mma_tf32(float c[4], const uint32_t a[4], const uint32_t b[2]) {
    asm volatile(
        "mma.sync.aligned.m16n8k8.row.col.f32.tf32.tf32.f32 "
        "{%0,%1,%2,%3}, {%4,%5,%6,%7}, {%8,%9}, {%0,%1,%2,%3};"
        : "+f"(c[0]), "+f"(c[1]), "+f"(c[2]), "+f"(c[3])
        : "r"(a[0]), "r"(a[1]), "r"(a[2]), "r"(a[3]), "r"(b[0]), "r"(b[1]));
}

// ---------------- tf32 rounding copy ----------------
__global__ void roundcpy_k(const float* __restrict__ src, float* __restrict__ dst, int n4) {
    int i = blockIdx.x * 256 + threadIdx.x;
    if (i < n4) {
        float4 v = *(const float4*)(src + (size_t)i * 4);
        v.x = tf32r(v.x); v.y = tf32r(v.y); v.z = tf32r(v.z); v.w = tf32r(v.w);
        *(float4*)(dst + (size_t)i * 4) = v;
    }
}

// ---------------- Embedding ----------------
__global__ void embed_k(const int* __restrict__ idx, const float* __restrict__ wte,
                        const float* __restrict__ wpe, float* __restrict__ h) {
    int bt = blockIdx.x;
    int t  = bt % TT;
    int tok = idx[bt];
    int i = threadIdx.x * 4;
    float4 a = *(const float4*)(wte + (size_t)tok * EE + i);
    float4 p = *(const float4*)(wpe + (size_t)t   * EE + i);
    a.x += p.x; a.y += p.y; a.z += p.z; a.w += p.w;
    *(float4*)(h + (size_t)bt * EE + i) = a;
}

// ---------------- LayerNorm (tf32-rounded output) ----------------
__global__ void layernorm_k(const float* __restrict__ xin, const float* __restrict__ g,
                            const float* __restrict__ bb, float* __restrict__ y) {
    __shared__ float rs[8], rq[8];
    int row = blockIdx.x, tid = threadIdx.x;
    const float* xr = xin + (size_t)row * EE;
    float4 v = *(const float4*)(xr + tid * 4);
    float s = v.x + v.y + v.z + v.w;
    float q = v.x * v.x + v.y * v.y + v.z * v.z + v.w * v.w;
#pragma unroll
    for (int o = 16; o; o >>= 1) {
        s += __shfl_xor_sync(0xffffffffu, s, o);
        q += __shfl_xor_sync(0xffffffffu, q, o);
    }
    if ((tid & 31) == 0) { rs[tid >> 5] = s; rq[tid >> 5] = q; }
    __syncthreads();
    if (tid == 0) {
        float S = 0.f, Q = 0.f;
#pragma unroll
        for (int i = 0; i < 8; i++) { S += rs[i]; Q += rq[i]; }
        rs[0] = S; rq[0] = Q;
    }
    __syncthreads();
    float mean = rs[0] * (1.f / EE);
    float var  = rq[0] * (1.f / EE) - mean * mean;
    float rstd = rsqrtf(var + 1e-5f);
    float4 gg = *(const float4*)(g  + tid * 4);
    float4 be = *(const float4*)(bb + tid * 4);
    float4 o;
    o.x = tf32r((v.x - mean) * rstd * gg.x + be.x);
    o.y = tf32r((v.y - mean) * rstd * gg.y + be.y);
    o.z = tf32r((v.z - mean) * rstd * gg.z + be.z);
    o.w = tf32r((v.w - mean) * rstd * gg.w + be.w);
    *(float4*)(y + (size_t)row * EE + tid * 4) = o;
}

// ---------------- cp.async 3-stage tf32 GEMM (1 sync/iter) ----------------
static constexpr int G_AST = 36;
static constexpr int G_ASZ = 128 * G_AST;
static constexpr int G_BSZ_N = 32 * 136;
static constexpr int G_BSZ_T = 128 * 36;
static constexpr int NSMEM = 3 * (G_ASZ + G_BSZ_N) * 4;
static constexpr int TSMEM = 3 * (G_ASZ + G_BSZ_T) * 4;

template<bool TRANSB, int ACT, bool RES, bool ROUND_OUT>
__global__ __launch_bounds__(256, 2)
void cpgemm_k(const float* __restrict__ A, const float* __restrict__ Bw,
              const float* __restrict__ bias, const float* __restrict__ Res,
              float* __restrict__ C, int M, int N, int K) {
    extern __shared__ float smf[];
    constexpr int BST = TRANSB ? 36 : 136;
    constexpr int BSZ = TRANSB ? G_BSZ_T : G_BSZ_N;
    constexpr int STG = G_ASZ + BSZ;

    const uint32_t sb = smem_u32(smf);
    const int tid  = threadIdx.x;
    const int lane = tid & 31;
    const int wid  = tid >> 5;
    const int wm   = wid >> 2;
    const int wn   = wid & 3;
    const int g    = lane >> 2;
    const int t    = lane & 3;

    const int row0 = blockIdx.x * 128;
    const int col0 = blockIdx.y * 128;
    const int iters = K >> 5;

    auto issue_stage = [&](int it) {
        const int k0 = it << 5;
        const int s = it % 3;
        const uint32_t stA = sb + (uint32_t)(s * STG) * 4;
        const uint32_t stB = stA + (uint32_t)G_ASZ * 4;
#pragma unroll
        for (int u = 0; u < 4; u++) {
            int ca = u * 256 + tid;
            int r = ca >> 3, c16 = ca & 7;
            const float* gs = A + (size_t)(row0 + r) * K + k0 + c16 * 4;
            uint32_t sd = stA + (uint32_t)(r * G_AST + c16 * 4) * 4;
            asm volatile("cp.async.cg.shared.global [%0], [%1], 16;" :: "r"(sd), "l"(gs));
        }
        if (!TRANSB) {
#pragma unroll
            for (int u = 0; u < 4; u++) {
                int cb = u * 256 + tid;
                int k = cb >> 5, c16 = cb & 31;
                const float* gs = Bw + (size_t)(k0 + k) * N + col0 + c16 * 4;
                uint32_t sd = stB + (uint32_t)(k * BST + c16 * 4) * 4;
                asm volatile("cp.async.cg.shared.global [%0], [%1], 16;" :: "r"(sd), "l"(gs));
            }
        } else {
#pragma unroll
            for (int u = 0; u < 4; u++) {
                int cb = u * 256 + tid;
                int n = cb >> 3, c16 = cb & 7;
                const float* gs = Bw + (size_t)(col0 + n) * K + k0 + c16 * 4;
                uint32_t sd = stB + (uint32_t)(n * BST + c16 * 4) * 4;
                int sz = (col0 + n < N) ? 16 : 0;
                asm volatile("cp.async.cg.shared.global [%0], [%1], 16, %2;"
                             :: "r"(sd), "l"(gs), "r"(sz));
            }
        }
        asm volatile("cp.async.commit_group;" ::: "memory");
    };

    float acc[4][4][4] = {};

    issue_stage(0);
    issue_stage(1);

    for (int it = 0; it < iters; ++it) {
        if (it == iters - 1) {
            asm volatile("cp.async.wait_group 0;" ::: "memory");
        } else {
            asm volatile("cp.async.wait_group 1;" ::: "memory");
        }
        __syncthreads();
        if (it + 2 < iters) issue_stage(it + 2);

        const float* Ab = smf + (it % 3) * STG;
        const float* Bb = Ab + G_ASZ;
#pragma unroll
        for (int ks = 0; ks < 4; ks++) {
            uint32_t afr[4][4];
            uint32_t bfr[4][2];
            const int kk = ks * 8 + t;
#pragma unroll
            for (int mt = 0; mt < 4; mt++) {
                int r = wm * 64 + mt * 16 + g;
                afr[mt][0] = __float_as_uint(Ab[(r)     * G_AST + kk]);
                afr[mt][1] = __float_as_uint(Ab[(r + 8) * G_AST + kk]);
                afr[mt][2] = __float_as_uint(Ab[(r)     * G_AST + kk + 4]);
                afr[mt][3] = __float_as_uint(Ab[(r + 8) * G_AST + kk + 4]);
            }
#pragma unroll
            for (int nt = 0; nt < 4; nt++) {
                int c = wn * 32 + nt * 8 + g;
                if (!TRANSB) {
                    bfr[nt][0] = __float_as_uint(Bb[(kk)     * BST + c]);
                    bfr[nt][1] = __float_as_uint(Bb[(kk + 4) * BST + c]);
                } else {
                    bfr[nt][0] = __float_as_uint(Bb[c * BST + kk]);
                    bfr[nt][1] = __float_as_uint(Bb[c * BST + kk + 4]);
                }
            }
#pragma unroll
            for (int mt = 0; mt < 4; mt++)
#pragma unroll
                for (int nt = 0; nt < 4; nt++)
                    mma_tf32(acc[mt][nt], afr[mt], bfr[nt]);
        }
        // no trailing sync: next iter's top sync orders reuse of this stage
    }

    // ---- epilogue ----
#pragma unroll
    for (int mt = 0; mt < 4; mt++) {
        int r0 = row0 + wm * 64 + mt * 16 + g;
#pragma unroll
        for (int nt = 0; nt < 4; nt++) {
            int c = col0 + wn * 32 + nt * 8 + t * 2;
#pragma unroll
            for (int half = 0; half < 2; half++) {
                int r = r0 + half * 8;
                float v0 = acc[mt][nt][half * 2 + 0];
                float v1 = acc[mt][nt][half * 2 + 1];
                if (!TRANSB) {
                    v0 += bias[c]; v1 += bias[c + 1];
                    if (ACT == 1) {
                        v0 = 0.5f * v0 * (1.f + erff(v0 * 0.70710678118654752f));
                        v1 = 0.5f * v1 * (1.f + erff(v1 * 0.70710678118654752f));
                    }
                    if (RES) {
                        v0 += Res[(size_t)r * N + c];
                        v1 += Res[(size_t)r * N + c + 1];
                    }
                    if (ROUND_OUT) { v0 = tf32r(v0); v1 = tf32r(v1); }
                    *(float2*)(C + (size_t)r * N + c) = make_float2(v0, v1);
                } else {
                    if (c < N)     C[(size_t)r * N + c]     = v0 + bias[c];
                    if (c + 1 < N) C[(size_t)r * N + c + 1] = v1 + bias[c + 1];
                }
            }
        }
    }
}

// ---------------- Split-KV flash attention: shuffle reductions, register m/l ----------------
// The 16 threads owning one S-row (fixed ty) are a contiguous half-warp.
static constexpr int FB_FLOATS = 4 * 64 * 68;       // Qs, Ks, Vs, Ps
static constexpr int FB_SMEM_BYTES = FB_FLOATS * 4; // 69632

__global__ __launch_bounds__(256)
void flash_attn_k(const float* __restrict__ qkv, float* __restrict__ pO,
                  float* __restrict__ pm, float* __restrict__ pl) {
    extern __shared__ float sm[];
    float* Qs = sm;
    float* Ks = sm + 64 * 68;
    float* Vs = sm + 2 * 64 * 68;
    float* Ps = sm + 3 * 64 * 68;

    const int tid = threadIdx.x;
    const int tx = tid & 15, ty = tid >> 4;
    const int u  = blockIdx.x;
    const int bh = blockIdx.y;
    const int qi = c_qi[u];
    const int sp = c_sp[u];
    const int q0 = qi * 64;
    const int b = bh / HH, h = bh % HH;

    const float* base = qkv + (size_t)b * TT * 3 * EE + h * DD;

    {
        int r = tid >> 2;
        int c = tid & 3;
        const float* qp = base + (size_t)(q0 + r) * 3 * EE;
#pragma unroll
        for (int uu = 0; uu < 4; uu++) {
            int d = (c + 4 * uu) * 4;
            float4 v = *(const float4*)(qp + d);
            Qs[(d + 0) * 68 + r] = v.x;
            Qs[(d + 1) * 68 + r] = v.y;
            Qs[(d + 2) * 68 + r] = v.z;
            Qs[(d + 3) * 68 + r] = v.w;
        }
    }

    float m_old[4], lsum[4];
#pragma unroll
    for (int i = 0; i < 4; i++) { m_old[i] = -1e30f; lsum[i] = 0.f; }
    float oacc[4][4] = {};
    const int c0 = sp * 4;
    const int c1 = min(c0 + 4, qi + 1);

    for (int ch = c0; ch < c1; ch++) {
        const int kt = ch * 64;
        __syncthreads();   // Ks/Vs/Ps (and Qs on first iter) safe to rewrite
        {
            int r = tid >> 2;
            int c = tid & 3;
            const float* kp = base + (size_t)(kt + r) * 3 * EE + EE;
            const float* vp = base + (size_t)(kt + r) * 3 * EE + 2 * EE;
#pragma unroll
            for (int uu = 0; uu < 4; uu++) {
                int d = (c + 4 * uu) * 4;
                float4 kv = *(const float4*)(kp + d);
                Ks[(d + 0) * 68 + r] = kv.x;
                Ks[(d + 1) * 68 + r] = kv.y;
                Ks[(d + 2) * 68 + r] = kv.z;
                Ks[(d + 3) * 68 + r] = kv.w;
                float4 vv = *(const float4*)(vp + d);
                *(float4*)(Vs + r * 68 + d) = vv;
            }
        }
        __syncthreads();

        float sacc[4][4] = {};
#pragma unroll 8
        for (int d = 0; d < 64; d++) {
            float4 a = *(const float4*)(Qs + d * 68 + ty * 4);
            float4 c = *(const float4*)(Ks + d * 68 + tx * 4);
            sacc[0][0] += a.x * c.x; sacc[0][1] += a.x * c.y; sacc[0][2] += a.x * c.z; sacc[0][3] += a.x * c.w;
            sacc[1][0] += a.y * c.x; sacc[1][1] += a.y * c.y; sacc[1][2] += a.y * c.z; sacc[1][3] += a.y * c.w;
            sacc[2][0] += a.z * c.x; sacc[2][1] += a.z * c.y; sacc[2][2] += a.z * c.z; sacc[2][3] += a.z * c.w;
            sacc[3][0] += a.w * c.x; sacc[3][1] += a.w * c.y; sacc[3][2] += a.w * c.z; sacc[3][3] += a.w * c.w;
        }
        const bool diag = (ch == qi);
#pragma unroll
        for (int i = 0; i < 4; i++) {
            int q = q0 + ty * 4 + i;
            float lm = -1e30f;
#pragma unroll
            for (int j = 0; j < 4; j++) {
                float s = sacc[i][j] * 0.125f;
                if (diag && (kt + tx * 4 + j > q)) s = -1e30f;
                sacc[i][j] = s;
                lm = fmaxf(lm, s);
            }
#pragma unroll
            for (int o = 1; o < 16; o <<= 1)
                lm = fmaxf(lm, __shfl_xor_sync(0xffffffffu, lm, o));
            float mnew = fmaxf(m_old[i], lm);
            float al = __expf(m_old[i] - mnew);
            m_old[i] = mnew;
            float ls = 0.f;
#pragma unroll
            for (int j = 0; j < 4; j++) {
                float p = __expf(sacc[i][j] - mnew);
                Ps[(tx * 4 + j) * 68 + ty * 4 + i] = p;
                ls += p;
            }
#pragma unroll
            for (int o = 1; o < 16; o <<= 1)
                ls += __shfl_xor_sync(0xffffffffu, ls, o);
            lsum[i] = lsum[i] * al + ls;
            oacc[i][0] *= al; oacc[i][1] *= al; oacc[i][2] *= al; oacc[i][3] *= al;
        }
        __syncthreads();   // Ps ready for PV

#pragma unroll 8
        for (int k = 0; k < 64; k++) {
            float4 a = *(const float4*)(Ps + k * 68 + ty * 4);
            float4 c = *(const float4*)(Vs + k * 68 + tx * 4);
            oacc[0][0] += a.x * c.x; oacc[0][1] += a.x * c.y; oacc[0][2] += a.x * c.z; oacc[0][3] += a.x * c.w;
            oacc[1][0] += a.y * c.x; oacc[1][1] += a.y * c.y; oacc[1][2] += a.y * c.z; oacc[1][3] += a.y * c.w;
            oacc[2][0] += a.z * c.x; oacc[2][1] += a.z * c.y; oacc[2][2] += a.z * c.z; oacc[2][3] += a.z * c.w;
            oacc[3][0] += a.w * c.x; oacc[3][1] += a.w * c.y; oacc[3][2] += a.w * c.z; oacc[3][3] += a.w * c.w;
        }
    }

    float* po = pO + ((size_t)(bh * NU + u) * 64) * 64;
#pragma unroll
    for (int i = 0; i < 4; i++) {
        int r = ty * 4 + i;
        *(float4*)(po + r * 64 + tx * 4) =
            make_float4(oacc[i][0], oacc[i][1], oacc[i][2], oacc[i][3]);
    }
    if (tx == 0) {
#pragma unroll
        for (int i = 0; i < 4; i++) {
            pm[(size_t)(bh * NU + u) * 64 + ty * 4 + i] = m_old[i];
            pl[(size_t)(bh * NU + u) * 64 + ty * 4 + i] = lsum[i];
        }
    }
}

// Combine split partials; tf32-rounded output
__global__ __launch_bounds__(256)
void fa_combine_k(const float* __restrict__ pO, const float* __restrict__ pm,
                  const float* __restrict__ pl, float* __restrict__ out) {
    const int qi = blockIdx.x;
    const int bh = blockIdx.y;
    const int b = bh / HH, h = bh % HH;
    const int ns = c_ns[qi];
    const int u0 = c_u0[qi];
    const int tid = threadIdx.x;
    const int r4 = tid >> 6;
    const int d  = tid & 63;
    for (int p = 0; p < 16; p++) {
        int row = p * 4 + r4;
        float M = -1e30f;
        for (int s = 0; s < ns; s++)
            M = fmaxf(M, pm[(size_t)(bh * NU + u0 + s) * 64 + row]);
        float L = 0.f, O = 0.f;
        for (int s = 0; s < ns; s++) {
            size_t ub = (size_t)(bh * NU + u0 + s);
            float w = __expf(pm[ub * 64 + row] - M);
            L += w * pl[ub * 64 + row];
            O += w * pO[(ub * 64 + row) * 64 + d];
        }
        out[((size_t)(b * TT + qi * 64 + row)) * EE + h * DD + d] = tf32r(O / L);
    }
}

// ---------------- Per-row NLL ----------------
__global__ void nll_k(const float* __restrict__ logits, const int* __restrict__ tgt,
                      float* __restrict__ nll) {
    int row = blockIdx.x;
    const float* lr = logits + (size_t)row * VV;
    int tid = threadIdx.x;
    __shared__ float sh[256];
    float m = -1e30f;
    for (int i = tid; i < VV; i += 256) m = fmaxf(m, lr[i]);
    sh[tid] = m; __syncthreads();
    for (int o = 128; o; o >>= 1) { if (tid < o) sh[tid] = fmaxf(sh[tid], sh[tid + o]); __syncthreads(); }
    m = sh[0]; __syncthreads();
    float s = 0.f;
    for (int i = tid; i < VV; i += 256) s += __expf(lr[i] - m);
    sh[tid] = s; __syncthreads();
    for (int o = 128; o; o >>= 1) { if (tid < o) sh[tid] += sh[tid + o]; __syncthreads(); }
    if (tid == 0) nll[row] = logf(sh[0]) + m - lr[tgt[row]];
}

__global__ void loss_reduce_k(const float* __restrict__ nll, float* __restrict__ dst, int count) {
    __shared__ float sh[256];
    float s = 0.f;
    for (int i = threadIdx.x; i < MM; i += 256) s += nll[i];
    sh[threadIdx.x] = s; __syncthreads();
    for (int o = 128; o; o >>= 1) { if (threadIdx.x < o) sh[threadIdx.x] += sh[threadIdx.x + o]; __syncthreads(); }
    if (threadIdx.x == 0) {
        float loss = sh[0] * (1.f / (float)MM);
        for (int i = 0; i < count; i++) dst[i] = loss;
    }
}

// ---------------- Launch ----------------
extern "C" void kernel_launch(void* const* d_in, const int* in_sizes, int n_in,
                              void* d_out, int out_size) {
    const int*   idx     = (const int*)  d_in[0];
    const int*   targets = (const int*)  d_in[1];
    const float* wte     = (const float*)d_in[2];
    const float* wpe     = (const float*)d_in[3];
    const float* ln1_g   = (const float*)d_in[4];
    const float* ln1_b   = (const float*)d_in[5];
    const float* qkv_w   = (const float*)d_in[6];
    const float* qkv_b   = (const float*)d_in[7];
    const float* o_w     = (const float*)d_in[8];
    const float* o_b     = (const float*)d_in[9];
    const float* ln2_g   = (const float*)d_in[10];
    const float* ln2_b   = (const float*)d_in[11];
    const float* up_w    = (const float*)d_in[12];
    const float* up_b    = (const float*)d_in[13];
    const float* down_w  = (const float*)d_in[14];
    const float* down_b  = (const float*)d_in[15];
    const float* lnf_g   = (const float*)d_in[16];
    const float* lnf_b   = (const float*)d_in[17];
    const float* lm_b    = (const float*)d_in[18];

    float *h, *x, *qkv, *attn, *mlp, *nll, *logits_scratch, *pO, *pm, *pl;
    float *qkvR, *oR, *upR, *downR, *wteR;
    cudaGetSymbolAddress((void**)&h,    g_h);
    cudaGetSymbolAddress((void**)&x,    g_x);
    cudaGetSymbolAddress((void**)&qkv,  g_qkv);
    cudaGetSymbolAddress((void**)&attn, g_attn);
    cudaGetSymbolAddress((void**)&mlp,  g_mlp);
    cudaGetSymbolAddress((void**)&nll,  g_nll);
    cudaGetSymbolAddress((void**)&logits_scratch, g_logits);
    cudaGetSymbolAddress((void**)&pO,   g_pO);
    cudaGetSymbolAddress((void**)&pm,   g_pm);
    cudaGetSymbolAddress((void**)&pl,   g_pl);
    cudaGetSymbolAddress((void**)&qkvR,  g_qkvR);
    cudaGetSymbolAddress((void**)&oR,    g_oR);
    cudaGetSymbolAddress((void**)&upR,   g_upR);
    cudaGetSymbolAddress((void**)&downR, g_downR);
    cudaGetSymbolAddress((void**)&wteR,  g_wteR);

    static bool attr_set = false;
    if (!attr_set) {
        cudaFuncSetAttribute(flash_attn_k, cudaFuncAttributeMaxDynamicSharedMemorySize, FB_SMEM_BYTES);
        cudaFuncSetAttribute(cpgemm_k<false, 0, false, false>, cudaFuncAttributeMaxDynamicSharedMemorySize, NSMEM);
        cudaFuncSetAttribute(cpgemm_k<false, 0, true,  false>, cudaFuncAttributeMaxDynamicSharedMemorySize, NSMEM);
        cudaFuncSetAttribute(cpgemm_k<false, 1, false, true >, cudaFuncAttributeMaxDynamicSharedMemorySize, NSMEM);
        cudaFuncSetAttribute(cpgemm_k<true,  0, false, false>, cudaFuncAttributeMaxDynamicSharedMemorySize, TSMEM);
        attr_set = true;
    }

    float* logits = ((long long)out_size >= NBTV) ? (float*)d_out : logits_scratch;

    {
        int n;
        n = LL * EE * 3 * EE / 4;  roundcpy_k<<<(n + 255) / 256, 256>>>(qkv_w, qkvR, n);
        n = LL * EE * EE / 4;      roundcpy_k<<<(n + 255) / 256, 256>>>(o_w, oR, n);
        n = LL * EE * 4 * EE / 4;  roundcpy_k<<<(n + 255) / 256, 256>>>(up_w, upR, n);
        n = LL * 4 * EE * EE / 4;  roundcpy_k<<<(n + 255) / 256, 256>>>(down_w, downR, n);
        n = VV * EE / 4;           roundcpy_k<<<(n + 255) / 256, 256>>>(wte, wteR, n);
    }

    embed_k<<<MM, 256>>>(idx, wte, wpe, h);

    for (int l = 0; l < LL; l++) {
        layernorm_k<<<MM, 256>>>(h, ln1_g + (size_t)l * EE, ln1_b + (size_t)l * EE, x);
        cpgemm_k<false, 0, false, false><<<dim3(MM / 128, 3 * EE / 128), 256, NSMEM>>>(
            x, qkvR + (size_t)l * EE * 3 * EE, qkv_b + (size_t)l * 3 * EE, nullptr,
            qkv, MM, 3 * EE, EE);
        flash_attn_k<<<dim3(NU, BB * HH), 256, FB_SMEM_BYTES>>>(qkv, pO, pm, pl);
        fa_combine_k<<<dim3(TT / 64, BB * HH), 256>>>(pO, pm, pl, attn);
        cpgemm_k<false, 0, true, false><<<dim3(MM / 128, EE / 128), 256, NSMEM>>>(
            attn, oR + (size_t)l * EE * EE, o_b + (size_t)l * EE, h,
            h, MM, EE, EE);
        layernorm_k<<<MM, 256>>>(h, ln2_g + (size_t)l * EE, ln2_b + (size_t)l * EE, x);
        cpgemm_k<false, 1, false, true><<<dim3(MM / 128, 4 * EE / 128), 256, NSMEM>>>(
            x, upR + (size_t)l * EE * 4 * EE, up_b + (size_t)l * 4 * EE, nullptr,
            mlp, MM, 4 * EE, EE);
        cpgemm_k<false, 0, true, false><<<dim3(MM / 128, EE / 128), 256, NSMEM>>>(
            mlp, downR + (size_t)l * 4 * EE * EE, down_b + (size_t)l * EE, h,
            h, MM, EE, 4 * EE);
    }

    layernorm_k<<<MM, 256>>>(h, lnf_g, lnf_b, x);
    cpgemm_k<true, 0, false, false><<<dim3(MM / 128, (VV + 127) / 128), 256, TSMEM>>>(
        x, wteR, lm_b, nullptr, logits, MM, VV, EE);

    nll_k<<<MM, 256>>>(logits, targets, nll);

    long long extra = (long long)out_size - NBTV;
    if (extra > 0) {
        loss_reduce_k<<<1, 256>>>(nll, (float*)d_out + NBTV, (int)extra);
    } else if ((long long)out_size < NBTV) {
        loss_reduce_k<<<1, 256>>>(nll, (float*)d_out, out_size);
    }
}

// round 9
// speedup vs baseline: 4.9645x; 1.4343x over previous
#include <cuda_runtime.h>
#include <cuda_fp16.h>
#include <math.h>
#include <stdint.h>

// ---------------- Problem constants ----------------
static constexpr int BB = 2;
static constexpr int TT = 1024;
static constexpr int EE = 1024;
static constexpr int HH = 16;
static constexpr int DD = 64;
static constexpr int LL = 12;
static constexpr int VV = 50257;
static constexpr int MM = BB * TT;
static constexpr long long NBTV = (long long)MM * VV;
static constexpr int NU = 40;

// ---------------- Scratch ----------------
__device__ float g_h   [(size_t)MM * EE];
__device__ __half g_xh  [(size_t)MM * EE];
__device__ float g_qkv [(size_t)MM * 3 * EE];
__device__ __half g_attnh[(size_t)MM * EE];
__device__ __half g_mlph [(size_t)MM * 4 * EE];
__device__ float g_nll [MM];
__device__ float g_logits[(size_t)MM * VV];
__device__ float g_pO[(size_t)BB * HH * NU * 64 * 64];
__device__ float g_pm[(size_t)BB * HH * NU * 64];
__device__ float g_pl[(size_t)BB * HH * NU * 64];
// fp16 weights, [N,K] K-major
__device__ __half g_qkvT [(size_t)LL * 3 * EE * EE];
__device__ __half g_oT   [(size_t)LL * EE * EE];
__device__ __half g_upT  [(size_t)LL * 4 * EE * EE];
__device__ __half g_downT[(size_t)LL * 4 * EE * EE];
__device__ __half g_wteH [(size_t)VV * EE];

__constant__ int c_qi[NU] = {15,15,15,15, 14,14,14,14, 13,13,13,13, 12,12,12,12,
                             11,11,11, 10,10,10, 9,9,9, 8,8,8, 7,7, 6,6, 5,5, 4,4,
                             3, 2, 1, 0};
__constant__ int c_sp[NU] = {0,1,2,3, 0,1,2,3, 0,1,2,3, 0,1,2,3,
                             0,1,2, 0,1,2, 0,1,2, 0,1,2, 0,1, 0,1, 0,1, 0,1,
                             0, 0, 0, 0};
__constant__ int c_u0[16] = {39,38,37,36, 34,32,30,28, 25,22,19,16, 12,8,4,0};
__constant__ int c_ns[16] = {1,1,1,1, 2,2,2,2, 3,3,3,3, 4,4,4,4};

// ---------------- Helpers ----------------
__device__ __forceinline__ uint32_t smem_u32(const void* p) {
    uint32_t r;
    asm("{ .reg .u64 t; cvta.to.shared.u64 t, %1; cvt.u32.u64 %0, t; }" : "=r"(r) : "l"(p));
    return r;
}

__device__ __forceinline__ void mma_f16(float c[4], const uint32_t a[4], const uint32_t b[2]) {
    asm volatile(
        "mma.sync.aligned.m16n8k16.row.col.f32.f16.f16.f32 "
        "{%0,%1,%2,%3}, {%4,%5,%6,%7}, {%8,%9}, {%0,%1,%2,%3};"
        : "+f"(c[0]), "+f"(c[1]), "+f"(c[2]), "+f"(c[3])
        : "r"(a[0]), "r"(a[1]), "r"(a[2]), "r"(a[3]), "r"(b[0]), "r"(b[1]));
}

__device__ __forceinline__ void st_half4(__half* p, float a, float b, float c, float d) {
    __half2 lo = __floats2half2_rn(a, b);
    __half2 hi = __floats2half2_rn(c, d);
    uint2 v = make_uint2(*(uint32_t*)&lo, *(uint32_t*)&hi);
    *(uint2*)p = v;
}

// ---------------- Weight prep: W[K,N] fp32 -> WT[N,K] half ----------------
__global__ void transh_k(const float* __restrict__ W, __half* __restrict__ WT,
                         int K, int N) {
    __shared__ float tl[32][33];
    size_t off = (size_t)blockIdx.z * K * N;
    int n0 = blockIdx.x * 32, k0 = blockIdx.y * 32;
    int lx = threadIdx.x, ly = threadIdx.y;
#pragma unroll
    for (int i = 0; i < 4; i++)
        tl[ly + 8 * i][lx] = W[off + (size_t)(k0 + ly + 8 * i) * N + n0 + lx];
    __syncthreads();
#pragma unroll
    for (int i = 0; i < 4; i++)
        WT[off + (size_t)(n0 + ly + 8 * i) * K + k0 + lx] =
            __float2half_rn(tl[lx][ly + 8 * i]);
}

// fp32 -> half straight copy (wte)
__global__ void halfcpy_k(const float* __restrict__ src, __half* __restrict__ dst, int n4) {
    int i = blockIdx.x * 256 + threadIdx.x;
    if (i < n4) {
        float4 v = *(const float4*)(src + (size_t)i * 4);
        st_half4(dst + (size_t)i * 4, v.x, v.y, v.z, v.w);
    }
}

// ---------------- Embedding ----------------
__global__ void embed_k(const int* __restrict__ idx, const float* __restrict__ wte,
                        const float* __restrict__ wpe, float* __restrict__ h) {
    int bt = blockIdx.x;
    int t  = bt % TT;
    int tok = idx[bt];
    int i = threadIdx.x * 4;
    float4 a = *(const float4*)(wte + (size_t)tok * EE + i);
    float4 p = *(const float4*)(wpe + (size_t)t   * EE + i);
    a.x += p.x; a.y += p.y; a.z += p.z; a.w += p.w;
    *(float4*)(h + (size_t)bt * EE + i) = a;
}

// ---------------- LayerNorm: fp32 in, half out ----------------
__global__ void layernorm_k(const float* __restrict__ xin, const float* __restrict__ g,
                            const float* __restrict__ bb, __half* __restrict__ y) {
    __shared__ float rs[8], rq[8];
    int row = blockIdx.x, tid = threadIdx.x;
    const float* xr = xin + (size_t)row * EE;
    float4 v = *(const float4*)(xr + tid * 4);
    float s = v.x + v.y + v.z + v.w;
    float q = v.x * v.x + v.y * v.y + v.z * v.z + v.w * v.w;
#pragma unroll
    for (int o = 16; o; o >>= 1) {
        s += __shfl_xor_sync(0xffffffffu, s, o);
        q += __shfl_xor_sync(0xffffffffu, q, o);
    }
    if ((tid & 31) == 0) { rs[tid >> 5] = s; rq[tid >> 5] = q; }
    __syncthreads();
    if (tid == 0) {
        float S = 0.f, Q = 0.f;
#pragma unroll
        for (int i = 0; i < 8; i++) { S += rs[i]; Q += rq[i]; }
        rs[0] = S; rq[0] = Q;
    }
    __syncthreads();
    float mean = rs[0] * (1.f / EE);
    float var  = rq[0] * (1.f / EE) - mean * mean;
    float rstd = rsqrtf(var + 1e-5f);
    float4 gg = *(const float4*)(g  + tid * 4);
    float4 be = *(const float4*)(bb + tid * 4);
    st_half4(y + (size_t)row * EE + tid * 4,
             (v.x - mean) * rstd * gg.x + be.x,
             (v.y - mean) * rstd * gg.y + be.y,
             (v.z - mean) * rstd * gg.z + be.z,
             (v.w - mean) * rstd * gg.w + be.w);
}

// ---------------- cp.async 3-stage fp16 GEMM (m16n8k16) ----------------
// C = act(A@B^T + bias) [+ Res]. A: [M,K] half. B: [N,K] half (K-major).
// 128x128 tile, K-chunk 64, 256 threads, 8 warps (2x4), warp 64x32.
static constexpr int H_AST = 72;                 // halfs per A/B smem row
static constexpr int H_STG = 2 * 128 * H_AST;    // halfs per stage (A + B)
static constexpr int HSMEM = 3 * H_STG * 2;      // bytes = 110592

template<int ACT, bool RES, bool GUARD, bool OUT_HALF>
__global__ __launch_bounds__(256, 2)
void hgemm_k(const __half* __restrict__ A, const __half* __restrict__ Bw,
             const float* __restrict__ bias, const float* __restrict__ Res,
             void* __restrict__ Cv, int M, int N, int K) {
    extern __shared__ __half smh[];
    const uint32_t sb = smem_u32(smh);
    const int tid  = threadIdx.x;
    const int lane = tid & 31;
    const int wid  = tid >> 5;
    const int wm   = wid >> 2;
    const int wn   = wid & 3;
    const int g    = lane >> 2;
    const int t    = lane & 3;

    const int row0 = blockIdx.x * 128;
    const int col0 = blockIdx.y * 128;
    const int iters = K >> 6;

    auto issue_stage = [&](int it) {
        const int k0 = it << 6;
        const int s = it % 3;
        const uint32_t stA = sb + (uint32_t)(s * H_STG) * 2;
        const uint32_t stB = stA + (uint32_t)(128 * H_AST) * 2;
#pragma unroll
        for (int u = 0; u < 4; u++) {
            int ca = u * 256 + tid;
            int r = ca >> 3, c16 = ca & 7;           // 8 x 16B chunks per row (64 halfs)
            const __half* gs = A + (size_t)(row0 + r) * K + k0 + c16 * 8;
            uint32_t sd = stA + (uint32_t)(r * H_AST + c16 * 8) * 2;
            asm volatile("cp.async.cg.shared.global [%0], [%1], 16;" :: "r"(sd), "l"(gs));
        }
#pragma unroll
        for (int u = 0; u < 4; u++) {
            int cb = u * 256 + tid;
            int n = cb >> 3, c16 = cb & 7;
            const __half* gs = Bw + (size_t)(col0 + n) * K + k0 + c16 * 8;
            uint32_t sd = stB + (uint32_t)(n * H_AST + c16 * 8) * 2;
            if (GUARD) {
                int sz = (col0 + n < N) ? 16 : 0;
                asm volatile("cp.async.cg.shared.global [%0], [%1], 16, %2;"
                             :: "r"(sd), "l"(gs), "r"(sz));
            } else {
                asm volatile("cp.async.cg.shared.global [%0], [%1], 16;" :: "r"(sd), "l"(gs));
            }
        }
        asm volatile("cp.async.commit_group;" ::: "memory");
    };

    float acc[4][4][4] = {};

    issue_stage(0);
    issue_stage(1);

    for (int it = 0; it < iters; ++it) {
        if (it == iters - 1) {
            asm volatile("cp.async.wait_group 0;" ::: "memory");
        } else {
            asm volatile("cp.async.wait_group 1;" ::: "memory");
        }
        __syncthreads();
        if (it + 2 < iters) issue_stage(it + 2);

        const __half* Ab = smh + (it % 3) * H_STG;
        const __half* Bb = Ab + 128 * H_AST;
#pragma unroll
        for (int ks = 0; ks < 4; ks++) {
            const int kk = ks * 16 + t * 2;
            uint32_t afr[4][4];
            uint32_t bfr[4][2];
#pragma unroll
            for (int mt = 0; mt < 4; mt++) {
                int r = wm * 64 + mt * 16 + g;
                afr[mt][0] = *(const uint32_t*)&Ab[(r)     * H_AST + kk];
                afr[mt][1] = *(const uint32_t*)&Ab[(r + 8) * H_AST + kk];
                afr[mt][2] = *(const uint32_t*)&Ab[(r)     * H_AST + kk + 8];
                afr[mt][3] = *(const uint32_t*)&Ab[(r + 8) * H_AST + kk + 8];
            }
#pragma unroll
            for (int nt = 0; nt < 4; nt++) {
                int c = wn * 32 + nt * 8 + g;
                bfr[nt][0] = *(const uint32_t*)&Bb[c * H_AST + kk];
                bfr[nt][1] = *(const uint32_t*)&Bb[c * H_AST + kk + 8];
            }
#pragma unroll
            for (int mt = 0; mt < 4; mt++)
#pragma unroll
                for (int nt = 0; nt < 4; nt++)
                    mma_f16(acc[mt][nt], afr[mt], bfr[nt]);
        }
    }

    // ---- epilogue ----
#pragma unroll
    for (int mt = 0; mt < 4; mt++) {
        int r0 = row0 + wm * 64 + mt * 16 + g;
#pragma unroll
        for (int nt = 0; nt < 4; nt++) {
            int c = col0 + wn * 32 + nt * 8 + t * 2;
#pragma unroll
            for (int half_i = 0; half_i < 2; half_i++) {
                int r = r0 + half_i * 8;
                float v0 = acc[mt][nt][half_i * 2 + 0];
                float v1 = acc[mt][nt][half_i * 2 + 1];
                if (GUARD) {
                    float* C = (float*)Cv;
                    if (c < N)     C[(size_t)r * N + c]     = v0 + bias[c];
                    if (c + 1 < N) C[(size_t)r * N + c + 1] = v1 + bias[c + 1];
                } else {
                    v0 += bias[c]; v1 += bias[c + 1];
                    if (ACT == 1) {
                        v0 = 0.5f * v0 * (1.f + erff(v0 * 0.70710678118654752f));
                        v1 = 0.5f * v1 * (1.f + erff(v1 * 0.70710678118654752f));
                    }
                    if (RES) {
                        v0 += Res[(size_t)r * N + c];
                        v1 += Res[(size_t)r * N + c + 1];
                    }
                    if (OUT_HALF) {
                        __half2 hv = __floats2half2_rn(v0, v1);
                        *(__half2*)((__half*)Cv + (size_t)r * N + c) = hv;
                    } else {
                        *(float2*)((float*)Cv + (size_t)r * N + c) = make_float2(v0, v1);
                    }
                }
            }
        }
    }
}

// ---------------- Split-KV flash attention (fp32, unchanged from R8) ----------------
static constexpr int FB_FLOATS = 4 * 64 * 68;
static constexpr int FB_SMEM_BYTES = FB_FLOATS * 4;

__global__ __launch_bounds__(256)
void flash_attn_k(const float* __restrict__ qkv, float* __restrict__ pO,
                  float* __restrict__ pm, float* __restrict__ pl) {
    extern __shared__ float sm[];
    float* Qs = sm;
    float* Ks = sm + 64 * 68;
    float* Vs = sm + 2 * 64 * 68;
    float* Ps = sm + 3 * 64 * 68;

    const int tid = threadIdx.x;
    const int tx = tid & 15, ty = tid >> 4;
    const int u  = blockIdx.x;
    const int bh = blockIdx.y;
    const int qi = c_qi[u];
    const int sp = c_sp[u];
    const int q0 = qi * 64;
    const int b = bh / HH, h = bh % HH;

    const float* base = qkv + (size_t)b * TT * 3 * EE + h * DD;

    {
        int r = tid >> 2;
        int c = tid & 3;
        const float* qp = base + (size_t)(q0 + r) * 3 * EE;
#pragma unroll
        for (int uu = 0; uu < 4; uu++) {
            int d = (c + 4 * uu) * 4;
            float4 v = *(const float4*)(qp + d);
            Qs[(d + 0) * 68 + r] = v.x;
            Qs[(d + 1) * 68 + r] = v.y;
            Qs[(d + 2) * 68 + r] = v.z;
            Qs[(d + 3) * 68 + r] = v.w;
        }
    }

    float m_old[4], lsum[4];
#pragma unroll
    for (int i = 0; i < 4; i++) { m_old[i] = -1e30f; lsum[i] = 0.f; }
    float oacc[4][4] = {};
    const int c0 = sp * 4;
    const int c1 = min(c0 + 4, qi + 1);

    for (int ch = c0; ch < c1; ch++) {
        const int kt = ch * 64;
        __syncthreads();
        {
            int r = tid >> 2;
            int c = tid & 3;
            const float* kp = base + (size_t)(kt + r) * 3 * EE + EE;
            const float* vp = base + (size_t)(kt + r) * 3 * EE + 2 * EE;
#pragma unroll
            for (int uu = 0; uu < 4; uu++) {
                int d = (c + 4 * uu) * 4;
                float4 kv = *(const float4*)(kp + d);
                Ks[(d + 0) * 68 + r] = kv.x;
                Ks[(d + 1) * 68 + r] = kv.y;
                Ks[(d + 2) * 68 + r] = kv.z;
                Ks[(d + 3) * 68 + r] = kv.w;
                float4 vv = *(const float4*)(vp + d);
                *(float4*)(Vs + r * 68 + d) = vv;
            }
        }
        __syncthreads();

        float sacc[4][4] = {};
#pragma unroll 8
        for (int d = 0; d < 64; d++) {
            float4 a = *(const float4*)(Qs + d * 68 + ty * 4);
            float4 c = *(const float4*)(Ks + d * 68 + tx * 4);
            sacc[0][0] += a.x * c.x; sacc[0][1] += a.x * c.y; sacc[0][2] += a.x * c.z; sacc[0][3] += a.x * c.w;
            sacc[1][0] += a.y * c.x; sacc[1][1] += a.y * c.y; sacc[1][2] += a.y * c.z; sacc[1][3] += a.y * c.w;
            sacc[2][0] += a.z * c.x; sacc[2][1] += a.z * c.y; sacc[2][2] += a.z * c.z; sacc[2][3] += a.z * c.w;
            sacc[3][0] += a.w * c.x; sacc[3][1] += a.w * c.y; sacc[3][2] += a.w * c.z; sacc[3][3] += a.w * c.w;
        }
        const bool diag = (ch == qi);
#pragma unroll
        for (int i = 0; i < 4; i++) {
            int q = q0 + ty * 4 + i;
            float lm = -1e30f;
#pragma unroll
            for (int j = 0; j < 4; j++) {
                float s = sacc[i][j] * 0.125f;
                if (diag && (kt + tx * 4 + j > q)) s = -1e30f;
                sacc[i][j] = s;
                lm = fmaxf(lm, s);
            }
#pragma unroll
            for (int o = 1; o < 16; o <<= 1)
                lm = fmaxf(lm, __shfl_xor_sync(0xffffffffu, lm, o));
            float mnew = fmaxf(m_old[i], lm);
            float al = __expf(m_old[i] - mnew);
            m_old[i] = mnew;
            float ls = 0.f;
#pragma unroll
            for (int j = 0; j < 4; j++) {
                float p = __expf(sacc[i][j] - mnew);
                Ps[(tx * 4 + j) * 68 + ty * 4 + i] = p;
                ls += p;
            }
#pragma unroll
            for (int o = 1; o < 16; o <<= 1)
                ls += __shfl_xor_sync(0xffffffffu, ls, o);
            lsum[i] = lsum[i] * al + ls;
            oacc[i][0] *= al; oacc[i][1] *= al; oacc[i][2] *= al; oacc[i][3] *= al;
        }
        __syncthreads();

#pragma unroll 8
        for (int k = 0; k < 64; k++) {
            float4 a = *(const float4*)(Ps + k * 68 + ty * 4);
            float4 c = *(const float4*)(Vs + k * 68 + tx * 4);
            oacc[0][0] += a.x * c.x; oacc[0][1] += a.x * c.y; oacc[0][2] += a.x * c.z; oacc[0][3] += a.x * c.w;
            oacc[1][0] += a.y * c.x; oacc[1][1] += a.y * c.y; oacc[1][2] += a.y * c.z; oacc[1][3] += a.y * c.w;
            oacc[2][0] += a.z * c.x; oacc[2][1] += a.z * c.y; oacc[2][2] += a.z * c.z; oacc[2][3] += a.z * c.w;
            oacc[3][0] += a.w * c.x; oacc[3][1] += a.w * c.y; oacc[3][2] += a.w * c.z; oacc[3][3] += a.w * c.w;
        }
    }

    float* po = pO + ((size_t)(bh * NU + u) * 64) * 64;
#pragma unroll
    for (int i = 0; i < 4; i++) {
        int r = ty * 4 + i;
        *(float4*)(po + r * 64 + tx * 4) =
            make_float4(oacc[i][0], oacc[i][1], oacc[i][2], oacc[i][3]);
    }
    if (tx == 0) {
#pragma unroll
        for (int i = 0; i < 4; i++) {
            pm[(size_t)(bh * NU + u) * 64 + ty * 4 + i] = m_old[i];
            pl[(size_t)(bh * NU + u) * 64 + ty * 4 + i] = lsum[i];
        }
    }
}

// Combine split partials; half output (feeds o-proj GEMM A)
__global__ __launch_bounds__(256)
void fa_combine_k(const float* __restrict__ pO, const float* __restrict__ pm,
                  const float* __restrict__ pl, __half* __restrict__ out) {
    const int qi = blockIdx.x;
    const int bh = blockIdx.y;
    const int b = bh / HH, h = bh % HH;
    const int ns = c_ns[qi];
    const int u0 = c_u0[qi];
    const int tid = threadIdx.x;
    const int r4 = tid >> 6;
    const int d  = tid & 63;
    for (int p = 0; p < 16; p++) {
        int row = p * 4 + r4;
        float M = -1e30f;
        for (int s = 0; s < ns; s++)
            M = fmaxf(M, pm[(size_t)(bh * NU + u0 + s) * 64 + row]);
        float L = 0.f, O = 0.f;
        for (int s = 0; s < ns; s++) {
            size_t ub = (size_t)(bh * NU + u0 + s);
            float w = __expf(pm[ub * 64 + row] - M);
            L += w * pl[ub * 64 + row];
            O += w * pO[(ub * 64 + row) * 64 + d];
        }
        out[((size_t)(b * TT + qi * 64 + row)) * EE + h * DD + d] = __float2half_rn(O / L);
    }
}

// ---------------- Per-row NLL ----------------
__global__ void nll_k(const float* __restrict__ logits, const int* __restrict__ tgt,
                      float* __restrict__ nll) {
    int row = blockIdx.x;
    const float* lr = logits + (size_t)row * VV;
    int tid = threadIdx.x;
    __shared__ float sh[256];
    float m = -1e30f;
    for (int i = tid; i < VV; i += 256) m = fmaxf(m, lr[i]);
    sh[tid] = m; __syncthreads();
    for (int o = 128; o; o >>= 1) { if (tid < o) sh[tid] = fmaxf(sh[tid], sh[tid + o]); __syncthreads(); }
    m = sh[0]; __syncthreads();
    float s = 0.f;
    for (int i = tid; i < VV; i += 256) s += __expf(lr[i] - m);
    sh[tid] = s; __syncthreads();
    for (int o = 128; o; o >>= 1) { if (tid < o) sh[tid] += sh[tid + o]; __syncthreads(); }
    if (tid == 0) nll[row] = logf(sh[0]) + m - lr[tgt[row]];
}

__global__ void loss_reduce_k(const float* __restrict__ nll, float* __restrict__ dst, int count) {
    __shared__ float sh[256];
    float s = 0.f;
    for (int i = threadIdx.x; i < MM; i += 256) s += nll[i];
    sh[threadIdx.x] = s; __syncthreads();
    for (int o = 128; o; o >>= 1) { if (threadIdx.x < o) sh[threadIdx.x] += sh[threadIdx.x + o]; __syncthreads(); }
    if (threadIdx.x == 0) {
        float loss = sh[0] * (1.f / (float)MM);
        for (int i = 0; i < count; i++) dst[i] = loss;
    }
}

// ---------------- Launch ----------------
extern "C" void kernel_launch(void* const* d_in, const int* in_sizes, int n_in,
                              void* d_out, int out_size) {
    const int*   idx     = (const int*)  d_in[0];
    const int*   targets = (const int*)  d_in[1];
    const float* wte     = (const float*)d_in[2];
    const float* wpe     = (const float*)d_in[3];
    const float* ln1_g   = (const float*)d_in[4];
    const float* ln1_b   = (const float*)d_in[5];
    const float* qkv_w   = (const float*)d_in[6];
    const float* qkv_b   = (const float*)d_in[7];
    const float* o_w     = (const float*)d_in[8];
    const float* o_b     = (const float*)d_in[9];
    const float* ln2_g   = (const float*)d_in[10];
    const float* ln2_b   = (const float*)d_in[11];
    const float* up_w    = (const float*)d_in[12];
    const float* up_b    = (const float*)d_in[13];
    const float* down_w  = (const float*)d_in[14];
    const float* down_b  = (const float*)d_in[15];
    const float* lnf_g   = (const float*)d_in[16];
    const float* lnf_b   = (const float*)d_in[17];
    const float* lm_b    = (const float*)d_in[18];

    float *h, *qkv, *nll, *logits_scratch, *pO, *pm, *pl;
    __half *xh, *attnh, *mlph, *qkvT, *oT, *upT, *downT, *wteH;
    cudaGetSymbolAddress((void**)&h,    g_h);
    cudaGetSymbolAddress((void**)&xh,   g_xh);
    cudaGetSymbolAddress((void**)&qkv,  g_qkv);
    cudaGetSymbolAddress((void**)&attnh, g_attnh);
    cudaGetSymbolAddress((void**)&mlph, g_mlph);
    cudaGetSymbolAddress((void**)&nll,  g_nll);
    cudaGetSymbolAddress((void**)&logits_scratch, g_logits);
    cudaGetSymbolAddress((void**)&pO,   g_pO);
    cudaGetSymbolAddress((void**)&pm,   g_pm);
    cudaGetSymbolAddress((void**)&pl,   g_pl);
    cudaGetSymbolAddress((void**)&qkvT,  g_qkvT);
    cudaGetSymbolAddress((void**)&oT,    g_oT);
    cudaGetSymbolAddress((void**)&upT,   g_upT);
    cudaGetSymbolAddress((void**)&downT, g_downT);
    cudaGetSymbolAddress((void**)&wteH,  g_wteH);

    static bool attr_set = false;
    if (!attr_set) {
        cudaFuncSetAttribute(flash_attn_k, cudaFuncAttributeMaxDynamicSharedMemorySize, FB_SMEM_BYTES);
        cudaFuncSetAttribute(hgemm_k<0, false, false, false>, cudaFuncAttributeMaxDynamicSharedMemorySize, HSMEM);
        cudaFuncSetAttribute(hgemm_k<0, true,  false, false>, cudaFuncAttributeMaxDynamicSharedMemorySize, HSMEM);
        cudaFuncSetAttribute(hgemm_k<1, false, false, true >, cudaFuncAttributeMaxDynamicSharedMemorySize, HSMEM);
        cudaFuncSetAttribute(hgemm_k<0, false, true,  false>, cudaFuncAttributeMaxDynamicSharedMemorySize, HSMEM);
        attr_set = true;
    }

    float* logits = ((long long)out_size >= NBTV) ? (float*)d_out : logits_scratch;

    // one-time (per replay) fp16 weight prep: transpose to [N,K] + round
    transh_k<<<dim3(3 * EE / 32, EE / 32, LL), dim3(32, 8)>>>(qkv_w, qkvT, EE, 3 * EE);
    transh_k<<<dim3(EE / 32, EE / 32, LL), dim3(32, 8)>>>(o_w, oT, EE, EE);
    transh_k<<<dim3(4 * EE / 32, EE / 32, LL), dim3(32, 8)>>>(up_w, upT, EE, 4 * EE);
    transh_k<<<dim3(EE / 32, 4 * EE / 32, LL), dim3(32, 8)>>>(down_w, downT, 4 * EE, EE);
    {
        int n = VV * EE / 4;
        halfcpy_k<<<(n + 255) / 256, 256>>>(wte, wteH, n);
    }

    embed_k<<<MM, 256>>>(idx, wte, wpe, h);

    for (int l = 0; l < LL; l++) {
        layernorm_k<<<MM, 256>>>(h, ln1_g + (size_t)l * EE, ln1_b + (size_t)l * EE, xh);
        hgemm_k<0, false, false, false><<<dim3(MM / 128, 3 * EE / 128), 256, HSMEM>>>(
            xh, qkvT + (size_t)l * 3 * EE * EE, qkv_b + (size_t)l * 3 * EE, nullptr,
            qkv, MM, 3 * EE, EE);
        flash_attn_k<<<dim3(NU, BB * HH), 256, FB_SMEM_BYTES>>>(qkv, pO, pm, pl);
        fa_combine_k<<<dim3(TT / 64, BB * HH), 256>>>(pO, pm, pl, attnh);
        hgemm_k<0, true, false, false><<<dim3(MM / 128, EE / 128), 256, HSMEM>>>(
            attnh, oT + (size_t)l * EE * EE, o_b + (size_t)l * EE, h,
            h, MM, EE, EE);
        layernorm_k<<<MM, 256>>>(h, ln2_g + (size_t)l * EE, ln2_b + (size_t)l * EE, xh);
        hgemm_k<1, false, false, true><<<dim3(MM / 128, 4 * EE / 128), 256, HSMEM>>>(
            xh, upT + (size_t)l * 4 * EE * EE, up_b + (size_t)l * 4 * EE, nullptr,
            mlph, MM, 4 * EE, EE);
        hgemm_k<0, true, false, false><<<dim3(MM / 128, EE / 128), 256, HSMEM>>>(
            mlph, downT + (size_t)l * 4 * EE * EE, down_b + (size_t)l * EE, h,
            h, MM, EE, 4 * EE);
    }

    layernorm_k<<<MM, 256>>>(h, lnf_g, lnf_b, xh);
    hgemm_k<0, false, true, false><<<dim3(MM / 128, (VV + 127) / 128), 256, HSMEM>>>(
        xh, wteH, lm_b, nullptr, logits, MM, VV, EE);

    nll_k<<<MM, 256>>>(logits, targets, nll);

    long long extra = (long long)out_size - NBTV;
    if (extra > 0) {
        loss_reduce_k<<<1, 256>>>(nll, (float*)d_out + NBTV, (int)extra);
    } else if ((long long)out_size < NBTV) {
        loss_reduce_k<<<1, 256>>>(nll, (float*)d_out, out_size);
    }
}

// round 10
// speedup vs baseline: 6.0443x; 1.2175x over previous
#include <cuda_runtime.h>
#include <cuda_fp16.h>
#include <math.h>
#include <stdint.h>

// ---------------- Problem constants ----------------
static constexpr int BB = 2;
static constexpr int TT = 1024;
static constexpr int EE = 1024;
static constexpr int HH = 16;
static constexpr int DD = 64;
static constexpr int LL = 12;
static constexpr int VV = 50257;
static constexpr int MM = BB * TT;
static constexpr long long NBTV = (long long)MM * VV;
static constexpr int NU = 40;

// ---------------- Scratch ----------------
__device__ float g_h   [(size_t)MM * EE];
__device__ __half g_xh  [(size_t)MM * EE];
__device__ float g_qkv [(size_t)MM * 3 * EE];
__device__ __half g_attnh[(size_t)MM * EE];
__device__ __half g_mlph [(size_t)MM * 4 * EE];
__device__ float g_nll [MM];
__device__ float g_logits[(size_t)MM * VV];
__device__ float g_pO[(size_t)BB * HH * NU * 64 * 64];
__device__ float g_pm[(size_t)BB * HH * NU * 64];
__device__ float g_pl[(size_t)BB * HH * NU * 64];
__device__ __half g_qkvT [(size_t)LL * 3 * EE * EE];
__device__ __half g_oT   [(size_t)LL * EE * EE];
__device__ __half g_upT  [(size_t)LL * 4 * EE * EE];
__device__ __half g_downT[(size_t)LL * 4 * EE * EE];
__device__ __half g_wteH [(size_t)VV * EE];

__constant__ int c_qi[NU] = {15,15,15,15, 14,14,14,14, 13,13,13,13, 12,12,12,12,
                             11,11,11, 10,10,10, 9,9,9, 8,8,8, 7,7, 6,6, 5,5, 4,4,
                             3, 2, 1, 0};
__constant__ int c_sp[NU] = {0,1,2,3, 0,1,2,3, 0,1,2,3, 0,1,2,3,
                             0,1,2, 0,1,2, 0,1,2, 0,1,2, 0,1, 0,1, 0,1, 0,1,
                             0, 0, 0, 0};
__constant__ int c_u0[16] = {39,38,37,36, 34,32,30,28, 25,22,19,16, 12,8,4,0};
__constant__ int c_ns[16] = {1,1,1,1, 2,2,2,2, 3,3,3,3, 4,4,4,4};

// ---------------- Helpers ----------------
__device__ __forceinline__ uint32_t smem_u32(const void* p) {
    uint32_t r;
    asm("{ .reg .u64 t; cvta.to.shared.u64 t, %1; cvt.u32.u64 %0, t; }" : "=r"(r) : "l"(p));
    return r;
}

__device__ __forceinline__ void mma_f16(float c[4], const uint32_t a[4], const uint32_t b[2]) {
    asm volatile(
        "mma.sync.aligned.m16n8k16.row.col.f32.f16.f16.f32 "
        "{%0,%1,%2,%3}, {%4,%5,%6,%7}, {%8,%9}, {%0,%1,%2,%3};"
        : "+f"(c[0]), "+f"(c[1]), "+f"(c[2]), "+f"(c[3])
        : "r"(a[0]), "r"(a[1]), "r"(a[2]), "r"(a[3]), "r"(b[0]), "r"(b[1]));
}

__device__ __forceinline__ void st_half4(__half* p, float a, float b, float c, float d) {
    __half2 lo = __floats2half2_rn(a, b);
    __half2 hi = __floats2half2_rn(c, d);
    uint2 v = make_uint2(*(uint32_t*)&lo, *(uint32_t*)&hi);
    *(uint2*)p = v;
}

__device__ __forceinline__ uint32_t pack_h2(float a, float b) {
    __half2 h = __floats2half2_rn(a, b);
    return *(uint32_t*)&h;
}

// ---------------- Weight prep: W[K,N] fp32 -> WT[N,K] half ----------------
__global__ void transh_k(const float* __restrict__ W, __half* __restrict__ WT,
                         int K, int N) {
    __shared__ float tl[32][33];
    size_t off = (size_t)blockIdx.z * K * N;
    int n0 = blockIdx.x * 32, k0 = blockIdx.y * 32;
    int lx = threadIdx.x, ly = threadIdx.y;
#pragma unroll
    for (int i = 0; i < 4; i++)
        tl[ly + 8 * i][lx] = W[off + (size_t)(k0 + ly + 8 * i) * N + n0 + lx];
    __syncthreads();
#pragma unroll
    for (int i = 0; i < 4; i++)
        WT[off + (size_t)(n0 + ly + 8 * i) * K + k0 + lx] =
            __float2half_rn(tl[lx][ly + 8 * i]);
}

__global__ void halfcpy_k(const float* __restrict__ src, __half* __restrict__ dst, int n4) {
    int i = blockIdx.x * 256 + threadIdx.x;
    if (i < n4) {
        float4 v = *(const float4*)(src + (size_t)i * 4);
        st_half4(dst + (size_t)i * 4, v.x, v.y, v.z, v.w);
    }
}

// ---------------- Embedding ----------------
__global__ void embed_k(const int* __restrict__ idx, const float* __restrict__ wte,
                        const float* __restrict__ wpe, float* __restrict__ h) {
    int bt = blockIdx.x;
    int t  = bt % TT;
    int tok = idx[bt];
    int i = threadIdx.x * 4;
    float4 a = *(const float4*)(wte + (size_t)tok * EE + i);
    float4 p = *(const float4*)(wpe + (size_t)t   * EE + i);
    a.x += p.x; a.y += p.y; a.z += p.z; a.w += p.w;
    *(float4*)(h + (size_t)bt * EE + i) = a;
}

// ---------------- LayerNorm: fp32 in, half out ----------------
__global__ void layernorm_k(const float* __restrict__ xin, const float* __restrict__ g,
                            const float* __restrict__ bb, __half* __restrict__ y) {
    __shared__ float rs[8], rq[8];
    int row = blockIdx.x, tid = threadIdx.x;
    const float* xr = xin + (size_t)row * EE;
    float4 v = *(const float4*)(xr + tid * 4);
    float s = v.x + v.y + v.z + v.w;
    float q = v.x * v.x + v.y * v.y + v.z * v.z + v.w * v.w;
#pragma unroll
    for (int o = 16; o; o >>= 1) {
        s += __shfl_xor_sync(0xffffffffu, s, o);
        q += __shfl_xor_sync(0xffffffffu, q, o);
    }
    if ((tid & 31) == 0) { rs[tid >> 5] = s; rq[tid >> 5] = q; }
    __syncthreads();
    if (tid == 0) {
        float S = 0.f, Q = 0.f;
#pragma unroll
        for (int i = 0; i < 8; i++) { S += rs[i]; Q += rq[i]; }
        rs[0] = S; rq[0] = Q;
    }
    __syncthreads();
    float mean = rs[0] * (1.f / EE);
    float var  = rq[0] * (1.f / EE) - mean * mean;
    float rstd = rsqrtf(var + 1e-5f);
    float4 gg = *(const float4*)(g  + tid * 4);
    float4 be = *(const float4*)(bb + tid * 4);
    st_half4(y + (size_t)row * EE + tid * 4,
             (v.x - mean) * rstd * gg.x + be.x,
             (v.y - mean) * rstd * gg.y + be.y,
             (v.z - mean) * rstd * gg.z + be.z,
             (v.w - mean) * rstd * gg.w + be.w);
}

// ---------------- cp.async 3-stage fp16 GEMM (m16n8k16) ----------------
static constexpr int H_AST = 72;
static constexpr int H_STG = 2 * 128 * H_AST;
static constexpr int HSMEM = 3 * H_STG * 2;

template<int ACT, bool RES, bool GUARD, bool OUT_HALF>
__global__ __launch_bounds__(256, 2)
void hgemm_k(const __half* __restrict__ A, const __half* __restrict__ Bw,
             const float* __restrict__ bias, const float* __restrict__ Res,
             void* __restrict__ Cv, int M, int N, int K) {
    extern __shared__ __half smh[];
    const uint32_t sb = smem_u32(smh);
    const int tid  = threadIdx.x;
    const int lane = tid & 31;
    const int wid  = tid >> 5;
    const int wm   = wid >> 2;
    const int wn   = wid & 3;
    const int g    = lane >> 2;
    const int t    = lane & 3;

    const int row0 = blockIdx.x * 128;
    const int col0 = blockIdx.y * 128;
    const int iters = K >> 6;

    auto issue_stage = [&](int it) {
        const int k0 = it << 6;
        const int s = it % 3;
        const uint32_t stA = sb + (uint32_t)(s * H_STG) * 2;
        const uint32_t stB = stA + (uint32_t)(128 * H_AST) * 2;
#pragma unroll
        for (int u = 0; u < 4; u++) {
            int ca = u * 256 + tid;
            int r = ca >> 3, c16 = ca & 7;
            const __half* gs = A + (size_t)(row0 + r) * K + k0 + c16 * 8;
            uint32_t sd = stA + (uint32_t)(r * H_AST + c16 * 8) * 2;
            asm volatile("cp.async.cg.shared.global [%0], [%1], 16;" :: "r"(sd), "l"(gs));
        }
#pragma unroll
        for (int u = 0; u < 4; u++) {
            int cb = u * 256 + tid;
            int n = cb >> 3, c16 = cb & 7;
            const __half* gs = Bw + (size_t)(col0 + n) * K + k0 + c16 * 8;
            uint32_t sd = stB + (uint32_t)(n * H_AST + c16 * 8) * 2;
            if (GUARD) {
                int sz = (col0 + n < N) ? 16 : 0;
                asm volatile("cp.async.cg.shared.global [%0], [%1], 16, %2;"
                             :: "r"(sd), "l"(gs), "r"(sz));
            } else {
                asm volatile("cp.async.cg.shared.global [%0], [%1], 16;" :: "r"(sd), "l"(gs));
            }
        }
        asm volatile("cp.async.commit_group;" ::: "memory");
    };

    float acc[4][4][4] = {};

    issue_stage(0);
    issue_stage(1);

    for (int it = 0; it < iters; ++it) {
        if (it == iters - 1) {
            asm volatile("cp.async.wait_group 0;" ::: "memory");
        } else {
            asm volatile("cp.async.wait_group 1;" ::: "memory");
        }
        __syncthreads();
        if (it + 2 < iters) issue_stage(it + 2);

        const __half* Ab = smh + (it % 3) * H_STG;
        const __half* Bb = Ab + 128 * H_AST;
#pragma unroll
        for (int ks = 0; ks < 4; ks++) {
            const int kk = ks * 16 + t * 2;
            uint32_t afr[4][4];
            uint32_t bfr[4][2];
#pragma unroll
            for (int mt = 0; mt < 4; mt++) {
                int r = wm * 64 + mt * 16 + g;
                afr[mt][0] = *(const uint32_t*)&Ab[(r)     * H_AST + kk];
                afr[mt][1] = *(const uint32_t*)&Ab[(r + 8) * H_AST + kk];
                afr[mt][2] = *(const uint32_t*)&Ab[(r)     * H_AST + kk + 8];
                afr[mt][3] = *(const uint32_t*)&Ab[(r + 8) * H_AST + kk + 8];
            }
#pragma unroll
            for (int nt = 0; nt < 4; nt++) {
                int c = wn * 32 + nt * 8 + g;
                bfr[nt][0] = *(const uint32_t*)&Bb[c * H_AST + kk];
                bfr[nt][1] = *(const uint32_t*)&Bb[c * H_AST + kk + 8];
            }
#pragma unroll
            for (int mt = 0; mt < 4; mt++)
#pragma unroll
                for (int nt = 0; nt < 4; nt++)
                    mma_f16(acc[mt][nt], afr[mt], bfr[nt]);
        }
    }

#pragma unroll
    for (int mt = 0; mt < 4; mt++) {
        int r0 = row0 + wm * 64 + mt * 16 + g;
#pragma unroll
        for (int nt = 0; nt < 4; nt++) {
            int c = col0 + wn * 32 + nt * 8 + t * 2;
#pragma unroll
            for (int half_i = 0; half_i < 2; half_i++) {
                int r = r0 + half_i * 8;
                float v0 = acc[mt][nt][half_i * 2 + 0];
                float v1 = acc[mt][nt][half_i * 2 + 1];
                if (GUARD) {
                    float* C = (float*)Cv;
                    if (c < N)     C[(size_t)r * N + c]     = v0 + bias[c];
                    if (c + 1 < N) C[(size_t)r * N + c + 1] = v1 + bias[c + 1];
                } else {
                    v0 += bias[c]; v1 += bias[c + 1];
                    if (ACT == 1) {
                        v0 = 0.5f * v0 * (1.f + erff(v0 * 0.70710678118654752f));
                        v1 = 0.5f * v1 * (1.f + erff(v1 * 0.70710678118654752f));
                    }
                    if (RES) {
                        v0 += Res[(size_t)r * N + c];
                        v1 += Res[(size_t)r * N + c + 1];
                    }
                    if (OUT_HALF) {
                        __half2 hv = __floats2half2_rn(v0, v1);
                        *(__half2*)((__half*)Cv + (size_t)r * N + c) = hv;
                    } else {
                        *(float2*)((float*)Cv + (size_t)r * N + c) = make_float2(v0, v1);
                    }
                }
            }
        }
    }
}

// ---------------- Tensor-core split-KV flash attention (fp16 mma, FA2 register reuse) ----------------
// 128 threads / 4 warps; warp w owns rows w*16..w*16+15 of the 64-row q-tile.
// Per key-chunk (64 keys): S = Q@K^T via 32 mma, in-register softmax (quad shuffles),
// P stays in registers as A-fragments, PV via 32 mma into O accumulators.
static constexpr int FH_PAD = 72;    // halfs per row

__global__ __launch_bounds__(128)
void flash_attn_k(const float* __restrict__ qkv, float* __restrict__ pO,
                  float* __restrict__ pm, float* __restrict__ pl) {
    __shared__ __half Qh[64 * FH_PAD];
    __shared__ __half Kh[64 * FH_PAD];
    __shared__ __half Vt[64 * FH_PAD];   // transposed: Vt[d][key]

    const int tid  = threadIdx.x;
    const int lane = tid & 31;
    const int wid  = tid >> 5;
    const int g    = lane >> 2;
    const int t    = lane & 3;
    const int wr   = wid * 16;

    const int u  = blockIdx.x;
    const int bh = blockIdx.y;
    const int qi = c_qi[u];
    const int sp = c_sp[u];
    const int q0 = qi * 64;
    const int b = bh / HH, h = bh % HH;

    const float* base = qkv + (size_t)b * TT * 3 * EE + h * DD;

    // load Q tile (64x64 fp32 -> half). 128 threads: row = tid>>1, half-row = tid&1.
    {
        int r = tid >> 1, cpart = tid & 1;
        const float* qp = base + (size_t)(q0 + r) * 3 * EE + cpart * 32;
#pragma unroll
        for (int i = 0; i < 8; i++) {
            float4 v = *(const float4*)(qp + i * 4);
            st_half4(Qh + r * FH_PAD + cpart * 32 + i * 4, v.x, v.y, v.z, v.w);
        }
    }

    float m_old[2] = {-1e30f, -1e30f};
    float lsum[2]  = {0.f, 0.f};
    float oacc[8][4] = {};
    const int c0 = sp * 4;
    const int c1 = min(c0 + 4, qi + 1);

    for (int ch = c0; ch < c1; ch++) {
        const int kt = ch * 64;
        __syncthreads();   // prev chunk's Vt reads done (and first iter: nothing)
        {
            int r = tid >> 1, cpart = tid & 1;
            const float* kp = base + (size_t)(kt + r) * 3 * EE + EE + cpart * 32;
            const float* vp = base + (size_t)(kt + r) * 3 * EE + 2 * EE + cpart * 32;
#pragma unroll
            for (int i = 0; i < 8; i++) {
                float4 kv = *(const float4*)(kp + i * 4);
                st_half4(Kh + r * FH_PAD + cpart * 32 + i * 4, kv.x, kv.y, kv.z, kv.w);
                float4 vv = *(const float4*)(vp + i * 4);
                int d = cpart * 32 + i * 4;
                Vt[(d + 0) * FH_PAD + r] = __float2half_rn(vv.x);
                Vt[(d + 1) * FH_PAD + r] = __float2half_rn(vv.y);
                Vt[(d + 2) * FH_PAD + r] = __float2half_rn(vv.z);
                Vt[(d + 3) * FH_PAD + r] = __float2half_rn(vv.w);
            }
        }
        __syncthreads();

        // ---- S = Q @ K^T : 8 n8-tiles x 4 k16-tiles ----
        float sacc[8][4] = {};
#pragma unroll
        for (int j = 0; j < 4; j++) {
            const int kk = j * 16 + t * 2;
            uint32_t a[4];
            a[0] = *(const uint32_t*)&Qh[(wr + g)     * FH_PAD + kk];
            a[1] = *(const uint32_t*)&Qh[(wr + g + 8) * FH_PAD + kk];
            a[2] = *(const uint32_t*)&Qh[(wr + g)     * FH_PAD + kk + 8];
            a[3] = *(const uint32_t*)&Qh[(wr + g + 8) * FH_PAD + kk + 8];
#pragma unroll
            for (int nt = 0; nt < 8; nt++) {
                uint32_t bfr[2];
                bfr[0] = *(const uint32_t*)&Kh[(nt * 8 + g) * FH_PAD + kk];
                bfr[1] = *(const uint32_t*)&Kh[(nt * 8 + g) * FH_PAD + kk + 8];
                mma_f16(sacc[nt], a, bfr);
            }
        }

        // ---- online softmax; P packed to fp16 A-fragments in registers ----
        const bool diag = (ch == qi);
        uint32_t ap[4][4];
        float al[2];
#pragma unroll
        for (int rh = 0; rh < 2; rh++) {
            int row = q0 + wr + g + rh * 8;
            float pv[16];
            float lm = -1e30f;
#pragma unroll
            for (int nt = 0; nt < 8; nt++) {
#pragma unroll
                for (int jj = 0; jj < 2; jj++) {
                    float s = sacc[nt][rh * 2 + jj] * 0.125f;
                    if (diag && (kt + nt * 8 + t * 2 + jj > row)) s = -1e30f;
                    pv[nt * 2 + jj] = s;
                    lm = fmaxf(lm, s);
                }
            }
            lm = fmaxf(lm, __shfl_xor_sync(0xffffffffu, lm, 1));
            lm = fmaxf(lm, __shfl_xor_sync(0xffffffffu, lm, 2));
            float mnew = fmaxf(m_old[rh], lm);
            al[rh] = __expf(m_old[rh] - mnew);
            m_old[rh] = mnew;
            float ls = 0.f;
#pragma unroll
            for (int k = 0; k < 16; k++) {
                pv[k] = __expf(pv[k] - mnew);
                ls += pv[k];
            }
            ls += __shfl_xor_sync(0xffffffffu, ls, 1);
            ls += __shfl_xor_sync(0xffffffffu, ls, 2);
            lsum[rh] = lsum[rh] * al[rh] + ls;
            // pack: k16-tile j covers key-cols from acc tiles 2j, 2j+1
#pragma unroll
            for (int j = 0; j < 4; j++) {
                ap[j][rh]     = pack_h2(pv[4 * j + 0], pv[4 * j + 1]);
                ap[j][rh + 2] = pack_h2(pv[4 * j + 2], pv[4 * j + 3]);
            }
        }
        // fix fragment ordering: a = {rowg k0, rowg+8 k0, rowg k8, rowg+8 k8}
        // ap[j][0]=rowg 2j-cols, ap[j][1]=rowg+8 2j-cols? built above as:
        // ap[j][rh] = rowg(rh=0)/rowg+8(rh=1) cols of tile 2j; ap[j][rh+2] = tile 2j+1.
        // Required: a0=rowg tile2j, a1=rowg+8 tile2j, a2=rowg tile2j+1, a3=rowg+8 tile2j+1. Matches.

        // ---- O = O*alpha + P @ V : 8 n8-tiles (d) x 4 k16-tiles (keys) ----
#pragma unroll
        for (int dt = 0; dt < 8; dt++) {
            oacc[dt][0] *= al[0]; oacc[dt][1] *= al[0];
            oacc[dt][2] *= al[1]; oacc[dt][3] *= al[1];
        }
#pragma unroll
        for (int j = 0; j < 4; j++) {
            const int kk = j * 16 + t * 2;
#pragma unroll
            for (int dt = 0; dt < 8; dt++) {
                uint32_t bfr[2];
                bfr[0] = *(const uint32_t*)&Vt[(dt * 8 + g) * FH_PAD + kk];
                bfr[1] = *(const uint32_t*)&Vt[(dt * 8 + g) * FH_PAD + kk + 8];
                mma_f16(oacc[dt], ap[j], bfr);
            }
        }
    }

    // ---- store unnormalized partials ----
    float* po = pO + ((size_t)(bh * NU + u) * 64) * 64;
    int r0 = wr + g;
#pragma unroll
    for (int dt = 0; dt < 8; dt++) {
        *(float2*)(po + (size_t)r0 * 64 + dt * 8 + t * 2)       = make_float2(oacc[dt][0], oacc[dt][1]);
        *(float2*)(po + (size_t)(r0 + 8) * 64 + dt * 8 + t * 2) = make_float2(oacc[dt][2], oacc[dt][3]);
    }
    if (t == 0) {
        pm[(size_t)(bh * NU + u) * 64 + r0]     = m_old[0];
        pm[(size_t)(bh * NU + u) * 64 + r0 + 8] = m_old[1];
        pl[(size_t)(bh * NU + u) * 64 + r0]     = lsum[0];
        pl[(size_t)(bh * NU + u) * 64 + r0 + 8] = lsum[1];
    }
}

// Combine split partials; half output (feeds o-proj GEMM A)
__global__ __launch_bounds__(256)
void fa_combine_k(const float* __restrict__ pO, const float* __restrict__ pm,
                  const float* __restrict__ pl, __half* __restrict__ out) {
    const int qi = blockIdx.x;
    const int bh = blockIdx.y;
    const int b = bh / HH, h = bh % HH;
    const int ns = c_ns[qi];
    const int u0 = c_u0[qi];
    const int tid = threadIdx.x;
    const int r4 = tid >> 6;
    const int d  = tid & 63;
    for (int p = 0; p < 16; p++) {
        int row = p * 4 + r4;
        float M = -1e30f;
        for (int s = 0; s < ns; s++)
            M = fmaxf(M, pm[(size_t)(bh * NU + u0 + s) * 64 + row]);
        float L = 0.f, O = 0.f;
        for (int s = 0; s < ns; s++) {
            size_t ub = (size_t)(bh * NU + u0 + s);
            float w = __expf(pm[ub * 64 + row] - M);
            L += w * pl[ub * 64 + row];
            O += w * pO[(ub * 64 + row) * 64 + d];
        }
        out[((size_t)(b * TT + qi * 64 + row)) * EE + h * DD + d] = __float2half_rn(O / L);
    }
}

// ---------------- Per-row NLL ----------------
__global__ void nll_k(const float* __restrict__ logits, const int* __restrict__ tgt,
                      float* __restrict__ nll) {
    int row = blockIdx.x;
    const float* lr = logits + (size_t)row * VV;
    int tid = threadIdx.x;
    __shared__ float sh[256];
    float m = -1e30f;
    for (int i = tid; i < VV; i += 256) m = fmaxf(m, lr[i]);
    sh[tid] = m; __syncthreads();
    for (int o = 128; o; o >>= 1) { if (tid < o) sh[tid] = fmaxf(sh[tid], sh[tid + o]); __syncthreads(); }
    m = sh[0]; __syncthreads();
    float s = 0.f;
    for (int i = tid; i < VV; i += 256) s += __expf(lr[i] - m);
    sh[tid] = s; __syncthreads();
    for (int o = 128; o; o >>= 1) { if (tid < o) sh[tid] += sh[tid + o]; __syncthreads(); }
    if (tid == 0) nll[row] = logf(sh[0]) + m - lr[tgt[row]];
}

__global__ void loss_reduce_k(const float* __restrict__ nll, float* __restrict__ dst, int count) {
    __shared__ float sh[256];
    float s = 0.f;
    for (int i = threadIdx.x; i < MM; i += 256) s += nll[i];
    sh[threadIdx.x] = s; __syncthreads();
    for (int o = 128; o; o >>= 1) { if (threadIdx.x < o) sh[threadIdx.x] += sh[threadIdx.x + o]; __syncthreads(); }
    if (threadIdx.x == 0) {
        float loss = sh[0] * (1.f / (float)MM);
        for (int i = 0; i < count; i++) dst[i] = loss;
    }
}

// ---------------- Launch ----------------
extern "C" void kernel_launch(void* const* d_in, const int* in_sizes, int n_in,
                              void* d_out, int out_size) {
    const int*   idx     = (const int*)  d_in[0];
    const int*   targets = (const int*)  d_in[1];
    const float* wte     = (const float*)d_in[2];
    const float* wpe     = (const float*)d_in[3];
    const float* ln1_g   = (const float*)d_in[4];
    const float* ln1_b   = (const float*)d_in[5];
    const float* qkv_w   = (const float*)d_in[6];
    const float* qkv_b   = (const float*)d_in[7];
    const float* o_w     = (const float*)d_in[8];
    const float* o_b     = (const float*)d_in[9];
    const float* ln2_g   = (const float*)d_in[10];
    const float* ln2_b   = (const float*)d_in[11];
    const float* up_w    = (const float*)d_in[12];
    const float* up_b    = (const float*)d_in[13];
    const float* down_w  = (const float*)d_in[14];
    const float* down_b  = (const float*)d_in[15];
    const float* lnf_g   = (const float*)d_in[16];
    const float* lnf_b   = (const float*)d_in[17];
    const float* lm_b    = (const float*)d_in[18];

    float *h, *qkv, *nll, *logits_scratch, *pO, *pm, *pl;
    __half *xh, *attnh, *mlph, *qkvT, *oT, *upT, *downT, *wteH;
    cudaGetSymbolAddress((void**)&h,    g_h);
    cudaGetSymbolAddress((void**)&xh,   g_xh);
    cudaGetSymbolAddress((void**)&qkv,  g_qkv);
    cudaGetSymbolAddress((void**)&attnh, g_attnh);
    cudaGetSymbolAddress((void**)&mlph, g_mlph);
    cudaGetSymbolAddress((void**)&nll,  g_nll);
    cudaGetSymbolAddress((void**)&logits_scratch, g_logits);
    cudaGetSymbolAddress((void**)&pO,   g_pO);
    cudaGetSymbolAddress((void**)&pm,   g_pm);
    cudaGetSymbolAddress((void**)&pl,   g_pl);
    cudaGetSymbolAddress((void**)&qkvT,  g_qkvT);
    cudaGetSymbolAddress((void**)&oT,    g_oT);
    cudaGetSymbolAddress((void**)&upT,   g_upT);
    cudaGetSymbolAddress((void**)&downT, g_downT);
    cudaGetSymbolAddress((void**)&wteH,  g_wteH);

    static bool attr_set = false;
    if (!attr_set) {
        cudaFuncSetAttribute(hgemm_k<0, false, false, false>, cudaFuncAttributeMaxDynamicSharedMemorySize, HSMEM);
        cudaFuncSetAttribute(hgemm_k<0, true,  false, false>, cudaFuncAttributeMaxDynamicSharedMemorySize, HSMEM);
        cudaFuncSetAttribute(hgemm_k<1, false, false, true >, cudaFuncAttributeMaxDynamicSharedMemorySize, HSMEM);
        cudaFuncSetAttribute(hgemm_k<0, false, true,  false>, cudaFuncAttributeMaxDynamicSharedMemorySize, HSMEM);
        attr_set = true;
    }

    float* logits = ((long long)out_size >= NBTV) ? (float*)d_out : logits_scratch;

    transh_k<<<dim3(3 * EE / 32, EE / 32, LL), dim3(32, 8)>>>(qkv_w, qkvT, EE, 3 * EE);
    transh_k<<<dim3(EE / 32, EE / 32, LL), dim3(32, 8)>>>(o_w, oT, EE, EE);
    transh_k<<<dim3(4 * EE / 32, EE / 32, LL), dim3(32, 8)>>>(up_w, upT, EE, 4 * EE);
    transh_k<<<dim3(EE / 32, 4 * EE / 32, LL), dim3(32, 8)>>>(down_w, downT, 4 * EE, EE);
    {
        int n = VV * EE / 4;
        halfcpy_k<<<(n + 255) / 256, 256>>>(wte, wteH, n);
    }

    embed_k<<<MM, 256>>>(idx, wte, wpe, h);

    for (int l = 0; l < LL; l++) {
        layernorm_k<<<MM, 256>>>(h, ln1_g + (size_t)l * EE, ln1_b + (size_t)l * EE, xh);
        hgemm_k<0, false, false, false><<<dim3(MM / 128, 3 * EE / 128), 256, HSMEM>>>(
            xh, qkvT + (size_t)l * 3 * EE * EE, qkv_b + (size_t)l * 3 * EE, nullptr,
            qkv, MM, 3 * EE, EE);
        flash_attn_k<<<dim3(NU, BB * HH), 128>>>(qkv, pO, pm, pl);
        fa_combine_k<<<dim3(TT / 64, BB * HH), 256>>>(pO, pm, pl, attnh);
        hgemm_k<0, true, false, false><<<dim3(MM / 128, EE / 128), 256, HSMEM>>>(
            attnh, oT + (size_t)l * EE * EE, o_b + (size_t)l * EE, h,
            h, MM, EE, EE);
        layernorm_k<<<MM, 256>>>(h, ln2_g + (size_t)l * EE, ln2_b + (size_t)l * EE, xh);
        hgemm_k<1, false, false, true><<<dim3(MM / 128, 4 * EE / 128), 256, HSMEM>>>(
            xh, upT + (size_t)l * 4 * EE * EE, up_b + (size_t)l * 4 * EE, nullptr,
            mlph, MM, 4 * EE, EE);
        hgemm_k<0, true, false, false><<<dim3(MM / 128, EE / 128), 256, HSMEM>>>(
            mlph, downT + (size_t)l * 4 * EE * EE, down_b + (size_t)l * EE, h,
            h, MM, EE, 4 * EE);
    }

    layernorm_k<<<MM, 256>>>(h, lnf_g, lnf_b, xh);
    hgemm_k<0, false, true, false><<<dim3(MM / 128, (VV + 127) / 128), 256, HSMEM>>>(
        xh, wteH, lm_b, nullptr, logits, MM, VV, EE);

    nll_k<<<MM, 256>>>(logits, targets, nll);

    long long extra = (long long)out_size - NBTV;
    if (extra > 0) {
        loss_reduce_k<<<1, 256>>>(nll, (float*)d_out + NBTV, (int)extra);
    } else if ((long long)out_size < NBTV) {
        loss_reduce_k<<<1, 256>>>(nll, (float*)d_out, out_size);
    }
}

// round 11
// speedup vs baseline: 6.8441x; 1.1323x over previous
#include <cuda_runtime.h>
#include <cuda_fp16.h>
#include <math.h>
#include <stdint.h>

// ---------------- Problem constants ----------------
static constexpr int BB = 2;
static constexpr int TT = 1024;
static constexpr int EE = 1024;
static constexpr int HH = 16;
static constexpr int DD = 64;
static constexpr int LL = 12;
static constexpr int VV = 50257;
static constexpr int MM = BB * TT;
static constexpr long long NBTV = (long long)MM * VV;
static constexpr int NU = 40;

// ---------------- Scratch ----------------
__device__ float g_h   [(size_t)MM * EE];
__device__ __half g_xh  [(size_t)MM * EE];
__device__ __half g_qkvh[(size_t)MM * 3 * EE];
__device__ __half g_attnh[(size_t)MM * EE];
__device__ __half g_mlph [(size_t)MM * 4 * EE];
__device__ float g_nll [MM];
__device__ float g_logits[(size_t)MM * VV];
__device__ float g_pO[(size_t)BB * HH * NU * 64 * 64];
__device__ float g_pm[(size_t)BB * HH * NU * 64];
__device__ float g_pl[(size_t)BB * HH * NU * 64];
__device__ __half g_qkvT [(size_t)LL * 3 * EE * EE];
__device__ __half g_oT   [(size_t)LL * EE * EE];
__device__ __half g_upT  [(size_t)LL * 4 * EE * EE];
__device__ __half g_downT[(size_t)LL * 4 * EE * EE];
__device__ __half g_wteH [(size_t)VV * EE];

__constant__ int c_qi[NU] = {15,15,15,15, 14,14,14,14, 13,13,13,13, 12,12,12,12,
                             11,11,11, 10,10,10, 9,9,9, 8,8,8, 7,7, 6,6, 5,5, 4,4,
                             3, 2, 1, 0};
__constant__ int c_sp[NU] = {0,1,2,3, 0,1,2,3, 0,1,2,3, 0,1,2,3,
                             0,1,2, 0,1,2, 0,1,2, 0,1,2, 0,1, 0,1, 0,1, 0,1,
                             0, 0, 0, 0};
__constant__ int c_u0[16] = {39,38,37,36, 34,32,30,28, 25,22,19,16, 12,8,4,0};
__constant__ int c_ns[16] = {1,1,1,1, 2,2,2,2, 3,3,3,3, 4,4,4,4};

// ---------------- Helpers ----------------
__device__ __forceinline__ uint32_t smem_u32(const void* p) {
    uint32_t r;
    asm("{ .reg .u64 t; cvta.to.shared.u64 t, %1; cvt.u32.u64 %0, t; }" : "=r"(r) : "l"(p));
    return r;
}

__device__ __forceinline__ void mma_f16(float c[4], const uint32_t a[4], const uint32_t b[2]) {
    asm volatile(
        "mma.sync.aligned.m16n8k16.row.col.f32.f16.f16.f32 "
        "{%0,%1,%2,%3}, {%4,%5,%6,%7}, {%8,%9}, {%0,%1,%2,%3};"
        : "+f"(c[0]), "+f"(c[1]), "+f"(c[2]), "+f"(c[3])
        : "r"(a[0]), "r"(a[1]), "r"(a[2]), "r"(a[3]), "r"(b[0]), "r"(b[1]));
}

__device__ __forceinline__ void ldsm_x4(uint32_t r[4], uint32_t addr) {
    asm volatile("ldmatrix.sync.aligned.m8n8.x4.shared.b16 {%0,%1,%2,%3}, [%4];"
        : "=r"(r[0]), "=r"(r[1]), "=r"(r[2]), "=r"(r[3]) : "r"(addr));
}

__device__ __forceinline__ void st_half4(__half* p, float a, float b, float c, float d) {
    __half2 lo = __floats2half2_rn(a, b);
    __half2 hi = __floats2half2_rn(c, d);
    uint2 v = make_uint2(*(uint32_t*)&lo, *(uint32_t*)&hi);
    *(uint2*)p = v;
}

__device__ __forceinline__ uint32_t pack_h2(float a, float b) {
    __half2 h = __floats2half2_rn(a, b);
    return *(uint32_t*)&h;
}

// ---------------- Weight prep: W[K,N] fp32 -> WT[N,K] half ----------------
__global__ void transh_k(const float* __restrict__ W, __half* __restrict__ WT,
                         int K, int N) {
    __shared__ float tl[32][33];
    size_t off = (size_t)blockIdx.z * K * N;
    int n0 = blockIdx.x * 32, k0 = blockIdx.y * 32;
    int lx = threadIdx.x, ly = threadIdx.y;
#pragma unroll
    for (int i = 0; i < 4; i++)
        tl[ly + 8 * i][lx] = W[off + (size_t)(k0 + ly + 8 * i) * N + n0 + lx];
    __syncthreads();
#pragma unroll
    for (int i = 0; i < 4; i++)
        WT[off + (size_t)(n0 + ly + 8 * i) * K + k0 + lx] =
            __float2half_rn(tl[lx][ly + 8 * i]);
}

__global__ void halfcpy_k(const float* __restrict__ src, __half* __restrict__ dst, int n4) {
    int i = blockIdx.x * 256 + threadIdx.x;
    if (i < n4) {
        float4 v = *(const float4*)(src + (size_t)i * 4);
        st_half4(dst + (size_t)i * 4, v.x, v.y, v.z, v.w);
    }
}

// ---------------- Embedding ----------------
__global__ void embed_k(const int* __restrict__ idx, const float* __restrict__ wte,
                        const float* __restrict__ wpe, float* __restrict__ h) {
    int bt = blockIdx.x;
    int t  = bt % TT;
    int tok = idx[bt];
    int i = threadIdx.x * 4;
    float4 a = *(const float4*)(wte + (size_t)tok * EE + i);
    float4 p = *(const float4*)(wpe + (size_t)t   * EE + i);
    a.x += p.x; a.y += p.y; a.z += p.z; a.w += p.w;
    *(float4*)(h + (size_t)bt * EE + i) = a;
}

// ---------------- LayerNorm: fp32 in, half out ----------------
__global__ void layernorm_k(const float* __restrict__ xin, const float* __restrict__ g,
                            const float* __restrict__ bb, __half* __restrict__ y) {
    __shared__ float rs[8], rq[8];
    int row = blockIdx.x, tid = threadIdx.x;
    const float* xr = xin + (size_t)row * EE;
    float4 v = *(const float4*)(xr + tid * 4);
    float s = v.x + v.y + v.z + v.w;
    float q = v.x * v.x + v.y * v.y + v.z * v.z + v.w * v.w;
#pragma unroll
    for (int o = 16; o; o >>= 1) {
        s += __shfl_xor_sync(0xffffffffu, s, o);
        q += __shfl_xor_sync(0xffffffffu, q, o);
    }
    if ((tid & 31) == 0) { rs[tid >> 5] = s; rq[tid >> 5] = q; }
    __syncthreads();
    if (tid == 0) {
        float S = 0.f, Q = 0.f;
#pragma unroll
        for (int i = 0; i < 8; i++) { S += rs[i]; Q += rq[i]; }
        rs[0] = S; rq[0] = Q;
    }
    __syncthreads();
    float mean = rs[0] * (1.f / EE);
    float var  = rq[0] * (1.f / EE) - mean * mean;
    float rstd = rsqrtf(var + 1e-5f);
    float4 gg = *(const float4*)(g  + tid * 4);
    float4 be = *(const float4*)(bb + tid * 4);
    st_half4(y + (size_t)row * EE + tid * 4,
             (v.x - mean) * rstd * gg.x + be.x,
             (v.y - mean) * rstd * gg.y + be.y,
             (v.z - mean) * rstd * gg.z + be.z,
             (v.w - mean) * rstd * gg.w + be.w);
}

// ---------------- cp.async 3-stage fp16 GEMM with ldmatrix fragments ----------------
static constexpr int H_AST = 72;
static constexpr int H_STG = 2 * 128 * H_AST;
static constexpr int HSMEM = 3 * H_STG * 2;

template<int ACT, bool RES, bool GUARD, bool OUT_HALF>
__global__ __launch_bounds__(256, 2)
void hgemm_k(const __half* __restrict__ A, const __half* __restrict__ Bw,
             const float* __restrict__ bias, const float* __restrict__ Res,
             void* __restrict__ Cv, int M, int N, int K) {
    extern __shared__ __half smh[];
    const uint32_t sb = smem_u32(smh);
    const int tid  = threadIdx.x;
    const int lane = tid & 31;
    const int wid  = tid >> 5;
    const int wm   = wid >> 2;
    const int wn   = wid & 3;
    const int g    = lane >> 2;
    const int t    = lane & 3;
    // ldmatrix lane-address components
    const int la16  = lane & 15;               // A: row within fragment
    const int lac8  = (lane >> 4) << 3;        // A: col half-select
    const int lbrow = ((lane >> 4) << 3) + (lane & 7);   // B: row within pair
    const int lbcol = ((lane >> 3) & 1) << 3;            // B: col half-select

    const int row0 = blockIdx.x * 128;
    const int col0 = blockIdx.y * 128;
    const int iters = K >> 6;

    auto issue_stage = [&](int it) {
        const int k0 = it << 6;
        const int s = it % 3;
        const uint32_t stA = sb + (uint32_t)(s * H_STG) * 2;
        const uint32_t stB = stA + (uint32_t)(128 * H_AST) * 2;
#pragma unroll
        for (int u = 0; u < 4; u++) {
            int ca = u * 256 + tid;
            int r = ca >> 3, c16 = ca & 7;
            const __half* gs = A + (size_t)(row0 + r) * K + k0 + c16 * 8;
            uint32_t sd = stA + (uint32_t)(r * H_AST + c16 * 8) * 2;
            asm volatile("cp.async.cg.shared.global [%0], [%1], 16;" :: "r"(sd), "l"(gs));
        }
#pragma unroll
        for (int u = 0; u < 4; u++) {
            int cb = u * 256 + tid;
            int n = cb >> 3, c16 = cb & 7;
            const __half* gs = Bw + (size_t)(col0 + n) * K + k0 + c16 * 8;
            uint32_t sd = stB + (uint32_t)(n * H_AST + c16 * 8) * 2;
            if (GUARD) {
                int sz = (col0 + n < N) ? 16 : 0;
                asm volatile("cp.async.cg.shared.global [%0], [%1], 16, %2;"
                             :: "r"(sd), "l"(gs), "r"(sz));
            } else {
                asm volatile("cp.async.cg.shared.global [%0], [%1], 16;" :: "r"(sd), "l"(gs));
            }
        }
        asm volatile("cp.async.commit_group;" ::: "memory");
    };

    float acc[4][4][4] = {};

    issue_stage(0);
    issue_stage(1);

    for (int it = 0; it < iters; ++it) {
        if (it == iters - 1) {
            asm volatile("cp.async.wait_group 0;" ::: "memory");
        } else {
            asm volatile("cp.async.wait_group 1;" ::: "memory");
        }
        __syncthreads();
        if (it + 2 < iters) issue_stage(it + 2);

        const uint32_t stA = sb + (uint32_t)((it % 3) * H_STG) * 2;
        const uint32_t stB = stA + (uint32_t)(128 * H_AST) * 2;
        const uint32_t aBase = stA + (uint32_t)((wm * 64 + la16) * H_AST + lac8) * 2;
        const uint32_t bBase = stB + (uint32_t)((wn * 32 + lbrow) * H_AST + lbcol) * 2;
#pragma unroll
        for (int ks = 0; ks < 4; ks++) {
            uint32_t afr[4][4];
            uint32_t bfr[4][2];
#pragma unroll
            for (int mt = 0; mt < 4; mt++)
                ldsm_x4(afr[mt], aBase + (uint32_t)(mt * 16 * H_AST + ks * 16) * 2);
#pragma unroll
            for (int ntp = 0; ntp < 2; ntp++) {
                uint32_t bp[4];
                ldsm_x4(bp, bBase + (uint32_t)(ntp * 16 * H_AST + ks * 16) * 2);
                bfr[2 * ntp][0]     = bp[0]; bfr[2 * ntp][1]     = bp[1];
                bfr[2 * ntp + 1][0] = bp[2]; bfr[2 * ntp + 1][1] = bp[3];
            }
#pragma unroll
            for (int mt = 0; mt < 4; mt++)
#pragma unroll
                for (int nt = 0; nt < 4; nt++)
                    mma_f16(acc[mt][nt], afr[mt], bfr[nt]);
        }
    }

#pragma unroll
    for (int mt = 0; mt < 4; mt++) {
        int r0 = row0 + wm * 64 + mt * 16 + g;
#pragma unroll
        for (int nt = 0; nt < 4; nt++) {
            int c = col0 + wn * 32 + nt * 8 + t * 2;
#pragma unroll
            for (int half_i = 0; half_i < 2; half_i++) {
                int r = r0 + half_i * 8;
                float v0 = acc[mt][nt][half_i * 2 + 0];
                float v1 = acc[mt][nt][half_i * 2 + 1];
                if (GUARD) {
                    float* C = (float*)Cv;
                    if (c < N)     C[(size_t)r * N + c]     = v0 + bias[c];
                    if (c + 1 < N) C[(size_t)r * N + c + 1] = v1 + bias[c + 1];
                } else {
                    v0 += bias[c]; v1 += bias[c + 1];
                    if (ACT == 1) {
                        v0 = 0.5f * v0 * (1.f + erff(v0 * 0.70710678118654752f));
                        v1 = 0.5f * v1 * (1.f + erff(v1 * 0.70710678118654752f));
                    }
                    if (RES) {
                        v0 += Res[(size_t)r * N + c];
                        v1 += Res[(size_t)r * N + c + 1];
                    }
                    if (OUT_HALF) {
                        __half2 hv = __floats2half2_rn(v0, v1);
                        *(__half2*)((__half*)Cv + (size_t)r * N + c) = hv;
                    } else {
                        *(float2*)((float*)Cv + (size_t)r * N + c) = make_float2(v0, v1);
                    }
                }
            }
        }
    }
}

// ---------------- Tensor-core split-KV flash attention (half qkv input) ----------------
static constexpr int FH_PAD = 72;

__global__ __launch_bounds__(128)
void flash_attn_k(const __half* __restrict__ qkv, float* __restrict__ pO,
                  float* __restrict__ pm, float* __restrict__ pl) {
    __shared__ __half Qh[64 * FH_PAD];
    __shared__ __half Kh[64 * FH_PAD];
    __shared__ __half Vt[64 * FH_PAD];   // transposed: Vt[d][key]

    const int tid  = threadIdx.x;
    const int lane = tid & 31;
    const int wid  = tid >> 5;
    const int g    = lane >> 2;
    const int t    = lane & 3;
    const int wr   = wid * 16;

    const int u  = blockIdx.x;
    const int bh = blockIdx.y;
    const int qi = c_qi[u];
    const int sp = c_sp[u];
    const int q0 = qi * 64;
    const int b = bh / HH, h = bh % HH;

    const __half* base = qkv + (size_t)b * TT * 3 * EE + h * DD;

    // load Q tile (64x64 half). 128 threads: row = tid>>1, half-row part = tid&1.
    {
        int r = tid >> 1, cpart = tid & 1;
        const __half* qp = base + (size_t)(q0 + r) * 3 * EE + cpart * 32;
#pragma unroll
        for (int i = 0; i < 4; i++)
            *(uint4*)(Qh + r * FH_PAD + cpart * 32 + i * 8) = *(const uint4*)(qp + i * 8);
    }

    float m_old[2] = {-1e30f, -1e30f};
    float lsum[2]  = {0.f, 0.f};
    float oacc[8][4] = {};
    const int c0 = sp * 4;
    const int c1 = min(c0 + 4, qi + 1);

    for (int ch = c0; ch < c1; ch++) {
        const int kt = ch * 64;
        __syncthreads();
        {
            int r = tid >> 1, cpart = tid & 1;
            const __half* kp = base + (size_t)(kt + r) * 3 * EE + EE + cpart * 32;
            const __half* vp = base + (size_t)(kt + r) * 3 * EE + 2 * EE + cpart * 32;
#pragma unroll
            for (int i = 0; i < 4; i++) {
                *(uint4*)(Kh + r * FH_PAD + cpart * 32 + i * 8) = *(const uint4*)(kp + i * 8);
                uint4 vv = *(const uint4*)(vp + i * 8);
                const __half* hv = (const __half*)&vv;
                int d = cpart * 32 + i * 8;
#pragma unroll
                for (int j = 0; j < 8; j++)
                    Vt[(d + j) * FH_PAD + r] = hv[j];
            }
        }
        __syncthreads();

        // ---- S = Q @ K^T ----
        float sacc[8][4] = {};
#pragma unroll
        for (int j = 0; j < 4; j++) {
            const int kk = j * 16 + t * 2;
            uint32_t a[4];
            a[0] = *(const uint32_t*)&Qh[(wr + g)     * FH_PAD + kk];
            a[1] = *(const uint32_t*)&Qh[(wr + g + 8) * FH_PAD + kk];
            a[2] = *(const uint32_t*)&Qh[(wr + g)     * FH_PAD + kk + 8];
            a[3] = *(const uint32_t*)&Qh[(wr + g + 8) * FH_PAD + kk + 8];
#pragma unroll
            for (int nt = 0; nt < 8; nt++) {
                uint32_t bfr[2];
                bfr[0] = *(const uint32_t*)&Kh[(nt * 8 + g) * FH_PAD + kk];
                bfr[1] = *(const uint32_t*)&Kh[(nt * 8 + g) * FH_PAD + kk + 8];
                mma_f16(sacc[nt], a, bfr);
            }
        }

        // ---- online softmax; P packed to fp16 A-fragments in registers ----
        const bool diag = (ch == qi);
        uint32_t ap[4][4];
        float al[2];
#pragma unroll
        for (int rh = 0; rh < 2; rh++) {
            int row = q0 + wr + g + rh * 8;
            float pv[16];
            float lm = -1e30f;
#pragma unroll
            for (int nt = 0; nt < 8; nt++) {
#pragma unroll
                for (int jj = 0; jj < 2; jj++) {
                    float s = sacc[nt][rh * 2 + jj] * 0.125f;
                    if (diag && (kt + nt * 8 + t * 2 + jj > row)) s = -1e30f;
                    pv[nt * 2 + jj] = s;
                    lm = fmaxf(lm, s);
                }
            }
            lm = fmaxf(lm, __shfl_xor_sync(0xffffffffu, lm, 1));
            lm = fmaxf(lm, __shfl_xor_sync(0xffffffffu, lm, 2));
            float mnew = fmaxf(m_old[rh], lm);
            al[rh] = __expf(m_old[rh] - mnew);
            m_old[rh] = mnew;
            float ls = 0.f;
#pragma unroll
            for (int k = 0; k < 16; k++) {
                pv[k] = __expf(pv[k] - mnew);
                ls += pv[k];
            }
            ls += __shfl_xor_sync(0xffffffffu, ls, 1);
            ls += __shfl_xor_sync(0xffffffffu, ls, 2);
            lsum[rh] = lsum[rh] * al[rh] + ls;
#pragma unroll
            for (int j = 0; j < 4; j++) {
                ap[j][rh]     = pack_h2(pv[4 * j + 0], pv[4 * j + 1]);
                ap[j][rh + 2] = pack_h2(pv[4 * j + 2], pv[4 * j + 3]);
            }
        }

        // ---- O = O*alpha + P @ V ----
#pragma unroll
        for (int dt = 0; dt < 8; dt++) {
            oacc[dt][0] *= al[0]; oacc[dt][1] *= al[0];
            oacc[dt][2] *= al[1]; oacc[dt][3] *= al[1];
        }
#pragma unroll
        for (int j = 0; j < 4; j++) {
            const int kk = j * 16 + t * 2;
#pragma unroll
            for (int dt = 0; dt < 8; dt++) {
                uint32_t bfr[2];
                bfr[0] = *(const uint32_t*)&Vt[(dt * 8 + g) * FH_PAD + kk];
                bfr[1] = *(const uint32_t*)&Vt[(dt * 8 + g) * FH_PAD + kk + 8];
                mma_f16(oacc[dt], ap[j], bfr);
            }
        }
    }

    float* po = pO + ((size_t)(bh * NU + u) * 64) * 64;
    int r0 = wr + g;
#pragma unroll
    for (int dt = 0; dt < 8; dt++) {
        *(float2*)(po + (size_t)r0 * 64 + dt * 8 + t * 2)       = make_float2(oacc[dt][0], oacc[dt][1]);
        *(float2*)(po + (size_t)(r0 + 8) * 64 + dt * 8 + t * 2) = make_float2(oacc[dt][2], oacc[dt][3]);
    }
    if (t == 0) {
        pm[(size_t)(bh * NU + u) * 64 + r0]     = m_old[0];
        pm[(size_t)(bh * NU + u) * 64 + r0 + 8] = m_old[1];
        pl[(size_t)(bh * NU + u) * 64 + r0]     = lsum[0];
        pl[(size_t)(bh * NU + u) * 64 + r0 + 8] = lsum[1];
    }
}

// Combine split partials; half output (feeds o-proj GEMM A)
__global__ __launch_bounds__(256)
void fa_combine_k(const float* __restrict__ pO, const float* __restrict__ pm,
                  const float* __restrict__ pl, __half* __restrict__ out) {
    const int qi = blockIdx.x;
    const int bh = blockIdx.y;
    const int b = bh / HH, h = bh % HH;
    const int ns = c_ns[qi];
    const int u0 = c_u0[qi];
    const int tid = threadIdx.x;
    const int r4 = tid >> 6;
    const int d  = tid & 63;
    for (int p = 0; p < 16; p++) {
        int row = p * 4 + r4;
        float M = -1e30f;
        for (int s = 0; s < ns; s++)
            M = fmaxf(M, pm[(size_t)(bh * NU + u0 + s) * 64 + row]);
        float L = 0.f, O = 0.f;
        for (int s = 0; s < ns; s++) {
            size_t ub = (size_t)(bh * NU + u0 + s);
            float w = __expf(pm[ub * 64 + row] - M);
            L += w * pl[ub * 64 + row];
            O += w * pO[(ub * 64 + row) * 64 + d];
        }
        out[((size_t)(b * TT + qi * 64 + row)) * EE + h * DD + d] = __float2half_rn(O / L);
    }
}

// ---------------- Per-row NLL ----------------
__global__ void nll_k(const float* __restrict__ logits, const int* __restrict__ tgt,
                      float* __restrict__ nll) {
    int row = blockIdx.x;
    const float* lr = logits + (size_t)row * VV;
    int tid = threadIdx.x;
    __shared__ float sh[256];
    float m = -1e30f;
    for (int i = tid; i < VV; i += 256) m = fmaxf(m, lr[i]);
    sh[tid] = m; __syncthreads();
    for (int o = 128; o; o >>= 1) { if (tid < o) sh[tid] = fmaxf(sh[tid], sh[tid + o]); __syncthreads(); }
    m = sh[0]; __syncthreads();
    float s = 0.f;
    for (int i = tid; i < VV; i += 256) s += __expf(lr[i] - m);
    sh[tid] = s; __syncthreads();
    for (int o = 128; o; o >>= 1) { if (tid < o) sh[tid] += sh[tid + o]; __syncthreads(); }
    if (tid == 0) nll[row] = logf(sh[0]) + m - lr[tgt[row]];
}

__global__ void loss_reduce_k(const float* __restrict__ nll, float* __restrict__ dst, int count) {
    __shared__ float sh[256];
    float s = 0.f;
    for (int i = threadIdx.x; i < MM; i += 256) s += nll[i];
    sh[threadIdx.x] = s; __syncthreads();
    for (int o = 128; o; o >>= 1) { if (threadIdx.x < o) sh[threadIdx.x] += sh[threadIdx.x + o]; __syncthreads(); }
    if (threadIdx.x == 0) {
        float loss = sh[0] * (1.f / (float)MM);
        for (int i = 0; i < count; i++) dst[i] = loss;
    }
}

// ---------------- Launch ----------------
extern "C" void kernel_launch(void* const* d_in, const int* in_sizes, int n_in,
                              void* d_out, int out_size) {
    const int*   idx     = (const int*)  d_in[0];
    const int*   targets = (const int*)  d_in[1];
    const float* wte     = (const float*)d_in[2];
    const float* wpe     = (const float*)d_in[3];
    const float* ln1_g   = (const float*)d_in[4];
    const float* ln1_b   = (const float*)d_in[5];
    const float* qkv_w   = (const float*)d_in[6];
    const float* qkv_b   = (const float*)d_in[7];
    const float* o_w     = (const float*)d_in[8];
    const float* o_b     = (const float*)d_in[9];
    const float* ln2_g   = (const float*)d_in[10];
    const float* ln2_b   = (const float*)d_in[11];
    const float* up_w    = (const float*)d_in[12];
    const float* up_b    = (const float*)d_in[13];
    const float* down_w  = (const float*)d_in[14];
    const float* down_b  = (const float*)d_in[15];
    const float* lnf_g   = (const float*)d_in[16];
    const float* lnf_b   = (const float*)d_in[17];
    const float* lm_b    = (const float*)d_in[18];

    float *h, *nll, *logits_scratch, *pO, *pm, *pl;
    __half *xh, *qkvh, *attnh, *mlph, *qkvT, *oT, *upT, *downT, *wteH;
    cudaGetSymbolAddress((void**)&h,    g_h);
    cudaGetSymbolAddress((void**)&xh,   g_xh);
    cudaGetSymbolAddress((void**)&qkvh, g_qkvh);
    cudaGetSymbolAddress((void**)&attnh, g_attnh);
    cudaGetSymbolAddress((void**)&mlph, g_mlph);
    cudaGetSymbolAddress((void**)&nll,  g_nll);
    cudaGetSymbolAddress((void**)&logits_scratch, g_logits);
    cudaGetSymbolAddress((void**)&pO,   g_pO);
    cudaGetSymbolAddress((void**)&pm,   g_pm);
    cudaGetSymbolAddress((void**)&pl,   g_pl);
    cudaGetSymbolAddress((void**)&qkvT,  g_qkvT);
    cudaGetSymbolAddress((void**)&oT,    g_oT);
    cudaGetSymbolAddress((void**)&upT,   g_upT);
    cudaGetSymbolAddress((void**)&downT, g_downT);
    cudaGetSymbolAddress((void**)&wteH,  g_wteH);

    static bool attr_set = false;
    if (!attr_set) {
        cudaFuncSetAttribute(hgemm_k<0, false, false, true >, cudaFuncAttributeMaxDynamicSharedMemorySize, HSMEM);
        cudaFuncSetAttribute(hgemm_k<0, true,  false, false>, cudaFuncAttributeMaxDynamicSharedMemorySize, HSMEM);
        cudaFuncSetAttribute(hgemm_k<1, false, false, true >, cudaFuncAttributeMaxDynamicSharedMemorySize, HSMEM);
        cudaFuncSetAttribute(hgemm_k<0, false, true,  false>, cudaFuncAttributeMaxDynamicSharedMemorySize, HSMEM);
        attr_set = true;
    }

    float* logits = ((long long)out_size >= NBTV) ? (float*)d_out : logits_scratch;

    transh_k<<<dim3(3 * EE / 32, EE / 32, LL), dim3(32, 8)>>>(qkv_w, qkvT, EE, 3 * EE);
    transh_k<<<dim3(EE / 32, EE / 32, LL), dim3(32, 8)>>>(o_w, oT, EE, EE);
    transh_k<<<dim3(4 * EE / 32, EE / 32, LL), dim3(32, 8)>>>(up_w, upT, EE, 4 * EE);
    transh_k<<<dim3(EE / 32, 4 * EE / 32, LL), dim3(32, 8)>>>(down_w, downT, 4 * EE, EE);
    {
        int n = VV * EE / 4;
        halfcpy_k<<<(n + 255) / 256, 256>>>(wte, wteH, n);
    }

    embed_k<<<MM, 256>>>(idx, wte, wpe, h);

    for (int l = 0; l < LL; l++) {
        layernorm_k<<<MM, 256>>>(h, ln1_g + (size_t)l * EE, ln1_b + (size_t)l * EE, xh);
        hgemm_k<0, false, false, true><<<dim3(MM / 128, 3 * EE / 128), 256, HSMEM>>>(
            xh, qkvT + (size_t)l * 3 * EE * EE, qkv_b + (size_t)l * 3 * EE, nullptr,
            qkvh, MM, 3 * EE, EE);
        flash_attn_k<<<dim3(NU, BB * HH), 128>>>(qkvh, pO, pm, pl);
        fa_combine_k<<<dim3(TT / 64, BB * HH), 256>>>(pO, pm, pl, attnh);
        hgemm_k<0, true, false, false><<<dim3(MM / 128, EE / 128), 256, HSMEM>>>(
            attnh, oT + (size_t)l * EE * EE, o_b + (size_t)l * EE, h,
            h, MM, EE, EE);
        layernorm_k<<<MM, 256>>>(h, ln2_g + (size_t)l * EE, ln2_b + (size_t)l * EE, xh);
        hgemm_k<1, false, false, true><<<dim3(MM / 128, 4 * EE / 128), 256, HSMEM>>>(
            xh, upT + (size_t)l * 4 * EE * EE, up_b + (size_t)l * 4 * EE, nullptr,
            mlph, MM, 4 * EE, EE);
        hgemm_k<0, true, false, false><<<dim3(MM / 128, EE / 128), 256, HSMEM>>>(
            mlph, downT + (size_t)l * 4 * EE * EE, down_b + (size_t)l * EE, h,
            h, MM, EE, 4 * EE);
    }

    layernorm_k<<<MM, 256>>>(h, lnf_g, lnf_b, xh);
    hgemm_k<0, false, true, false><<<dim3(MM / 128, (VV + 127) / 128), 256, HSMEM>>>(
        xh, wteH, lm_b, nullptr, logits, MM, VV, EE);

    nll_k<<<MM, 256>>>(logits, targets, nll);

    long long extra = (long long)out_size - NBTV;
    if (extra > 0) {
        loss_reduce_k<<<1, 256>>>(nll, (float*)d_out + NBTV, (int)extra);
    } else if ((long long)out_size < NBTV) {
        loss_reduce_k<<<1, 256>>>(nll, (float*)d_out, out_size);
    }
}